// round 8
// baseline (speedup 1.0000x reference)
#include <cuda_runtime.h>
#include <cuda_bf16.h>
#include <mma.h>
#include <cstdint>
#include <stdint.h>
#include <math.h>

using namespace nvcuda;

#define TLEN    6000
#define NP      199
#define PLEN    60
#define PSTRIDE 30
#define NSP     30
#define NFREQ   16
#define NM      13
#define NS      9
#define NFEAT   22
#define TM      64
#define MAXROWS (1024*NP)

// 22-dim normalized feature rows (203776 x 22)
__device__ float g_F[(size_t)MAXROWS * NFEAT];

__device__ __forceinline__ float geluf(float v){
    return 0.5f * v * (1.0f + erff(v * 0.7071067811865476f));
}
__device__ __forceinline__ float freqf(int k){
    return (float)(((double)k * 200.0) / 30.0);
}

// ============================================================
// Kernel A: per-patch features + group layernorms -> g_F
// (unchanged from the passing 75us version)
// ============================================================
__global__ __launch_bounds__(256) void feat_kernel(
    const float* __restrict__ x,
    const float* __restrict__ gm, const float* __restrict__ bm,
    const float* __restrict__ gs, const float* __restrict__ bs)
{
    __shared__ float sx[TLEN];
    __shared__ float cosT[NFREQ * 16];
    __shared__ float sinT[NFREQ * 16];
    __shared__ float hannS[NSP];
    __shared__ float psdS[NFREQ * 200];

    const int tid = threadIdx.x;
    {
        const float4* xg = (const float4*)(x + (size_t)blockIdx.x * TLEN);
        float4* s4 = (float4*)sx;
        for (int i = tid; i < TLEN/4; i += 256) s4[i] = xg[i];
    }
    for (int i = tid; i < NFREQ*16; i += 256) {
        int k = i >> 4, t = i & 15;
        double sv, cv;
        sincospi(2.0 * (double)(k * t) / 30.0, &sv, &cv);
        cosT[i] = (float)cv;
        sinT[i] = (float)sv;
    }
    if (tid < NSP)
        hannS[tid] = (float)(0.5 * (1.0 - cospi(2.0 * (double)tid / 30.0)));
    __syncthreads();
    if (tid >= NP) return;

    const int off = tid * PSTRIDE;
    float* frow = &g_F[((size_t)blockIdx.x * NP + tid) * NFEAT];

    float v0 = sx[off];
    float mx = v0, mn = v0, sum = v0;
    float sumsq = v0 * v0;
    float amax = fabsf(v0); int aidx = 0;
    float prev = v0;
    float tsg = v0 + 1e-10f;
    int   sprev = (tsg > 0.0f) - (tsg < 0.0f);
    float dmax = -INFINITY, dmin = INFINITY, dabs = 0.0f;
    int zc = 0;
    #pragma unroll
    for (int t = 1; t < PLEN; t++) {
        float v = sx[off + t];
        mx = fmaxf(mx, v); mn = fminf(mn, v);
        sum += v; sumsq = fmaf(v, v, sumsq);
        float a = fabsf(v);
        if (a > amax) { amax = a; aidx = t; }
        float d = v - prev;
        dmax = fmaxf(dmax, d); dmin = fminf(dmin, d); dabs += fabsf(d);
        float tg = v + 1e-10f;
        int sg = (tg > 0.0f) - (tg < 0.0f);
        zc += (sg != sprev);
        sprev = sg; prev = v;
    }
    float mean = sum * (1.0f/60.0f);

    float m2 = 0.f, m3 = 0.f, m4 = 0.f;
    #pragma unroll
    for (int t = 0; t < PLEN; t++) {
        float c = sx[off + t] - mean;
        float c2 = c * c;
        m2 += c2; m3 = fmaf(c2, c, m3); m4 = fmaf(c2, c2, m4);
    }
    m2 *= (1.0f/60.0f); m3 *= (1.0f/60.0f); m4 *= (1.0f/60.0f);
    float stdv = sqrtf(m2);

    {
        float morph[NM];
        morph[0] = mx; morph[1] = mn; morph[2] = mx - mn; morph[3] = mean;
        morph[4] = stdv;
        morph[5] = (float)aidx * (1.0f/60.0f);
        morph[6] = dmax; morph[7] = dmin;
        morph[8] = dabs * (1.0f/59.0f);
        morph[9] = (float)zc * (1.0f/60.0f);
        morph[10] = sumsq;
        morph[11] = m4 / (m2 * m2) - 3.0f;
        morph[12] = m3 / (m2 * stdv);
        #pragma unroll
        for (int i = 0; i < NM; i++) if (!isfinite(morph[i])) morph[i] = 0.0f;

        float mu = 0.f;
        #pragma unroll
        for (int i = 0; i < NM; i++) mu += morph[i];
        mu *= (1.0f/13.0f);
        float var = 0.f;
        #pragma unroll
        for (int i = 0; i < NM; i++) { float d = morph[i]-mu; var = fmaf(d,d,var); }
        var *= (1.0f/13.0f);
        float scl = rsqrtf(var + 1e-5f);
        #pragma unroll
        for (int i = 0; i < NM; i++)
            frow[i] = fmaf((morph[i]-mu)*scl, gm[i], bm[i]);
    }

    float ye0[16], yo0[15], ye1[16], yo1[15], ye2[16], yo2[15];

    #define FOLD_SEG(YE, YO, SB) { \
        float s = 0.f; \
        _Pragma("unroll") \
        for (int t = 0; t < NSP; t++) s += sx[(SB) + t]; \
        s *= (1.0f/30.0f); \
        float s2 = 2.0f * s; \
        _Pragma("unroll") \
        for (int t = 1; t < 15; t++) { \
            float a = sx[(SB) + t]; \
            float b = sx[(SB) + 30 - t]; \
            float w = hannS[t]; \
            YE[t] = (a + b - s2) * w; \
            YO[t] = (a - b) * w; \
        } \
        YE[15] = sx[(SB) + 15] - s; \
    }

    FOLD_SEG(ye0, yo0, off)
    FOLD_SEG(ye1, yo1, off + 15)
    FOLD_SEG(ye2, yo2, off + 30)
    #undef FOLD_SEG

    for (int k = 0; k < NFREQ; k++) {
        const float* ck = &cosT[k * 16];
        const float* sk = &sinT[k * 16];
        float re0 = 0.f, im0 = 0.f, re1 = 0.f, im1 = 0.f, re2 = 0.f, im2 = 0.f;
        #pragma unroll
        for (int t = 1; t < 15; t++) {
            float c = ck[t], si = sk[t];
            re0 = fmaf(ye0[t], c, re0); im0 = fmaf(yo0[t], si, im0);
            re1 = fmaf(ye1[t], c, re1); im1 = fmaf(yo1[t], si, im1);
            re2 = fmaf(ye2[t], c, re2); im2 = fmaf(yo2[t], si, im2);
        }
        float c15 = ck[15];
        re0 = fmaf(ye0[15], c15, re0);
        re1 = fmaf(ye1[15], c15, re1);
        re2 = fmaf(ye2[15], c15, re2);
        float p = fmaf(re0,re0,im0*im0) + fmaf(re1,re1,im1*im1) + fmaf(re2,re2,im2*im2);
        float sc = (k == 0 || k == NFREQ-1) ? (1.0f/6750.0f) : (2.0f/6750.0f);
        psdS[k*200 + tid] = p * sc;
    }

    float psd[NFREQ];
    #pragma unroll
    for (int k = 0; k < NFREQ; k++) psd[k] = psdS[k*200 + tid];

    float total = 0.f;
    #pragma unroll
    for (int k = 0; k < NFREQ; k++) total += psd[k];
    total += 1e-12f;
    float inv = 1.0f / total;

    float b1v = psd[1];
    float b3v = psd[2] + psd[3] + psd[4];
    float b4v = 0.f;
    #pragma unroll
    for (int k = 5; k <= 14; k++) b4v += psd[k];

    float pmax = psd[0]; int pkk = 0;
    #pragma unroll
    for (int k = 1; k < NFREQ; k++)
        if (psd[k] > pmax) { pmax = psd[k]; pkk = k; }

    float thr = 0.95f * total;
    float csum = 0.f; int ek = 0; bool fnd = false;
    #pragma unroll
    for (int k = 0; k < NFREQ; k++) {
        csum += psd[k];
        if (!fnd && csum >= thr) { ek = k; fnd = true; }
    }
    float ent = 0.f;
    #pragma unroll
    for (int k = 0; k < NFREQ; k++) {
        float pn = psd[k] * inv;
        ent -= pn * log2f(pn + 1e-12f);
    }

    float spec[NS];
    spec[0] = 0.0f;
    spec[1] = b1v * inv;
    spec[2] = 0.0f;
    spec[3] = b3v * inv;
    spec[4] = b4v * inv;
    spec[5] = freqf(pkk);
    spec[6] = freqf(ek);
    spec[7] = ent;
    spec[8] = total;
    #pragma unroll
    for (int i = 0; i < NS; i++) if (!isfinite(spec[i])) spec[i] = 0.0f;

    {
        float mu = 0.f;
        #pragma unroll
        for (int i = 0; i < NS; i++) mu += spec[i];
        mu *= (1.0f/9.0f);
        float var = 0.f;
        #pragma unroll
        for (int i = 0; i < NS; i++) { float d = spec[i]-mu; var = fmaf(d,d,var); }
        var *= (1.0f/9.0f);
        float scl = rsqrtf(var + 1e-5f);
        #pragma unroll
        for (int i = 0; i < NS; i++)
            frow[NM + i] = fmaf((spec[i]-mu)*scl, gs[i], bs[i]);
    }
}

// ============================================================
// Kernel B: persistent MLP, GEMM2 on WMMA bf16 (split hi/lo x3)
// ============================================================
// smem byte layout:
//  B panels (persistent): Bhi 65536 | Blo 65536
//  A panels / D (union): Ahi 16640 | Alo 16640 ; D 64x264 f32 = 67584
//  W1 11264 | Fs 5632 | b1 512 | b2/go/bo 3x1024
#define OFF_BHI    0
#define OFF_BLO    65536
#define OFF_A      131072
#define A_STRIDE   1040      // elems per k-panel (16-row k x 64 rows + pad), 2080B (32B-aligned)
#define OFF_AHI    131072
#define OFF_ALO    147712    // 131072 + 8*1040*2
#define OFF_D      131072    // overlays A (synced)
#define D_LD       264       // f32 leading dim
#define OFF_W1     198656    // 131072 + 67584
#define OFF_FS     209920
#define OFF_B1     215552
#define OFF_B2     216064
#define OFF_GO     217088
#define OFF_BO     218112
#define SMEM_BYTES 219136

__global__ __launch_bounds__(512, 1) void mlp_kernel(
    const float* __restrict__ W1, const float* __restrict__ b1,
    const float* __restrict__ W2, const float* __restrict__ b2,
    const float* __restrict__ go, const float* __restrict__ bo,
    float* __restrict__ out, int nRows)
{
    extern __shared__ char smc[];
    __nv_bfloat16* Bhi = (__nv_bfloat16*)(smc + OFF_BHI);
    __nv_bfloat16* Blo = (__nv_bfloat16*)(smc + OFF_BLO);
    __nv_bfloat16* Ahi = (__nv_bfloat16*)(smc + OFF_AHI);
    __nv_bfloat16* Alo = (__nv_bfloat16*)(smc + OFF_ALO);
    float* Ds  = (float*)(smc + OFF_D);
    float* W1s = (float*)(smc + OFF_W1);
    float* Fs  = (float*)(smc + OFF_FS);
    float* b1s = (float*)(smc + OFF_B1);
    float* b2s = (float*)(smc + OFF_B2);
    float* gos = (float*)(smc + OFF_GO);
    float* bos = (float*)(smc + OFF_BO);

    const int tid  = threadIdx.x;
    const int wid  = tid >> 5;
    const int lane = tid & 31;

    // ---- one-time setup ----
    for (int i = tid; i < 22*128; i += 512) W1s[i] = W1[i];
    if (tid < 128) b1s[tid] = b1[tid];
    for (int i = tid; i < 256; i += 512) { b2s[i]=b2[i]; gos[i]=go[i]; bos[i]=bo[i]; }

    // W2 [k][n] -> B panels: [kb][n][k16]  (col-major 16x16 blocks, ldm=16)
    for (int i = tid; i < 128*256; i += 512) {
        int k = i >> 8, n = i & 255;
        float w = W2[i];
        __nv_bfloat16 hi = __float2bfloat16_rn(w);
        float rlo = w - __bfloat162float(hi);
        __nv_bfloat16 lo = __float2bfloat16_rn(rlo);
        int idx = (k >> 4) * 4096 + n * 16 + (k & 15);
        Bhi[idx] = hi;
        Blo[idx] = lo;
    }
    __syncthreads();

    const int c1 = lane * 4;              // GEMM1 cols (= GEMM2 k)
    const int kbw = lane >> 2;            // A panel for this lane's cols
    const int kin = (lane & 3) * 4;       // k offset inside panel
    float* Fw = Fs + wid * (4 * NFEAT);

    const int mb     = wid & 3;           // warp's m-block (16 rows)
    const int ngroup = wid >> 2;          // warp's n-group (4 n-blocks)
    const int nTiles = nRows / TM;        // 203776/64 = 3184 exact

    for (int tile = blockIdx.x; tile < nTiles; tile += gridDim.x) {
        const int rowBase = tile * TM;
        const int wRow = rowBase + wid * 4;

        __syncthreads();   // previous tile's D reads done before A overwrite

        // per-warp F staging (4 rows x 22)
        {
            const float* src = &g_F[(size_t)wRow * NFEAT];
            for (int i = lane; i < 4 * NFEAT; i += 32)
                Fw[i] = (wRow + i / NFEAT < nRows) ? src[i] : 0.0f;
        }
        __syncwarp();

        // GEMM1 + bias + GELU -> split bf16 into A panels
        {
            float acc[4][4];
            #pragma unroll
            for (int i = 0; i < 4; i++)
                #pragma unroll
                for (int j = 0; j < 4; j++) acc[i][j] = 0.0f;
            #pragma unroll
            for (int k = 0; k < NFEAT; k++) {
                float4 w = *(const float4*)&W1s[k*128 + c1];
                #pragma unroll
                for (int i = 0; i < 4; i++) {
                    float a = Fw[i*NFEAT + k];
                    acc[i][0] = fmaf(a, w.x, acc[i][0]);
                    acc[i][1] = fmaf(a, w.y, acc[i][1]);
                    acc[i][2] = fmaf(a, w.z, acc[i][2]);
                    acc[i][3] = fmaf(a, w.w, acc[i][3]);
                }
            }
            float bv[4] = { b1s[c1], b1s[c1+1], b1s[c1+2], b1s[c1+3] };
            #pragma unroll
            for (int i = 0; i < 4; i++) {
                unsigned long long hp = 0, lp = 0;
                #pragma unroll
                for (int j = 0; j < 4; j++) {
                    float h = geluf(acc[i][j] + bv[j]);
                    __nv_bfloat16 hb = __float2bfloat16_rn(h);
                    float rl = h - __bfloat162float(hb);
                    __nv_bfloat16 lb = __float2bfloat16_rn(rl);
                    hp |= (unsigned long long)__bfloat16_as_ushort(hb) << (16*j);
                    lp |= (unsigned long long)__bfloat16_as_ushort(lb) << (16*j);
                }
                int row = wid * 4 + i;   // tile-local row
                int idx = kbw * A_STRIDE + row * 16 + kin;
                *(unsigned long long*)&Ahi[idx] = hp;
                *(unsigned long long*)&Alo[idx] = lp;
            }
        }
        __syncthreads();

        // GEMM2 via WMMA: warp = m-block mb x n-blocks [ngroup*4, +4)
        wmma::fragment<wmma::accumulator, 16, 16, 16, float> dfr[4];
        #pragma unroll
        for (int i = 0; i < 4; i++) wmma::fill_fragment(dfr[i], 0.0f);

        #pragma unroll
        for (int kb = 0; kb < 8; kb++) {
            wmma::fragment<wmma::matrix_a, 16, 16, 16, __nv_bfloat16, wmma::row_major> ahi, alo;
            wmma::load_matrix_sync(ahi, Ahi + kb * A_STRIDE + mb * 256, 16);
            wmma::load_matrix_sync(alo, Alo + kb * A_STRIDE + mb * 256, 16);
            #pragma unroll
            for (int i = 0; i < 4; i++) {
                int nb = ngroup * 4 + i;
                wmma::fragment<wmma::matrix_b, 16, 16, 16, __nv_bfloat16, wmma::col_major> bhi, blo;
                wmma::load_matrix_sync(bhi, Bhi + kb * 4096 + nb * 256, 16);
                wmma::load_matrix_sync(blo, Blo + kb * 4096 + nb * 256, 16);
                wmma::mma_sync(dfr[i], ahi, bhi, dfr[i]);
                wmma::mma_sync(dfr[i], ahi, blo, dfr[i]);
                wmma::mma_sync(dfr[i], alo, bhi, dfr[i]);
            }
        }
        __syncthreads();   // all A reads done before D overlays A

        #pragma unroll
        for (int i = 0; i < 4; i++) {
            int nb = ngroup * 4 + i;
            wmma::store_matrix_sync(&Ds[(mb*16) * D_LD + nb * 16], dfr[i],
                                    D_LD, wmma::mem_row_major);
        }
        __syncthreads();

        // LN epilogue: 8 threads per row, 32 cols each
        {
            const int row = tid >> 3;        // 0..63
            const int seg = tid & 7;
            const int cb  = seg * 32;
            float v[32];
            #pragma unroll
            for (int c = 0; c < 32; c += 4) {
                float4 d4 = *(float4*)&Ds[row * D_LD + cb + c];
                v[c+0] = d4.x + b2s[cb+c+0];
                v[c+1] = d4.y + b2s[cb+c+1];
                v[c+2] = d4.z + b2s[cb+c+2];
                v[c+3] = d4.w + b2s[cb+c+3];
            }
            float s = 0.f, q = 0.f;
            #pragma unroll
            for (int c = 0; c < 32; c++) { s += v[c]; q = fmaf(v[c], v[c], q); }
            #pragma unroll
            for (int off = 4; off >= 1; off >>= 1) {
                s += __shfl_xor_sync(0xffffffffu, s, off);
                q += __shfl_xor_sync(0xffffffffu, q, off);
            }
            float mu = s * (1.0f/256.0f);
            float var = q * (1.0f/256.0f) - mu * mu;
            float rs = rsqrtf(var + 1e-5f);

            int grow = rowBase + row;
            if (grow < nRows) {
                float* op = out + (size_t)grow * 256 + cb;
                #pragma unroll
                for (int c = 0; c < 32; c += 4) {
                    float4 o;
                    o.x = fmaf((v[c+0]-mu)*rs, gos[cb+c+0], bos[cb+c+0]);
                    o.y = fmaf((v[c+1]-mu)*rs, gos[cb+c+1], bos[cb+c+1]);
                    o.z = fmaf((v[c+2]-mu)*rs, gos[cb+c+2], bos[cb+c+2]);
                    o.w = fmaf((v[c+3]-mu)*rs, gos[cb+c+3], bos[cb+c+3]);
                    *(float4*)(op + c) = o;
                }
            }
        }
    }
}

extern "C" void kernel_launch(void* const* d_in, const int* in_sizes, int n_in,
                              void* d_out, int out_size) {
    const float* x  = (const float*)d_in[0];
    const float* gm = (const float*)d_in[1];
    const float* bm = (const float*)d_in[2];
    const float* gs = (const float*)d_in[3];
    const float* bs = (const float*)d_in[4];
    const float* W1 = (const float*)d_in[5];
    const float* b1 = (const float*)d_in[6];
    const float* W2 = (const float*)d_in[7];
    const float* b2 = (const float*)d_in[8];
    const float* go = (const float*)d_in[9];
    const float* bo = (const float*)d_in[10];

    int B = in_sizes[0] / TLEN;
    int nRows = B * NP;

    cudaFuncSetAttribute(mlp_kernel, cudaFuncAttributeMaxDynamicSharedMemorySize,
                         SMEM_BYTES);

    feat_kernel<<<B, 256>>>(x, gm, bm, gs, bs);
    mlp_kernel<<<148, 512, SMEM_BYTES>>>(
        W1, b1, W2, b2, go, bo, (float*)d_out, nRows);
}

// round 9
// speedup vs baseline: 1.8298x; 1.8298x over previous
#include <cuda_runtime.h>
#include <cuda_bf16.h>
#include <cstdint>
#include <stdint.h>
#include <math.h>

#define TLEN    6000
#define NP      199
#define PLEN    60
#define PSTRIDE 30
#define NSP     30
#define NFREQ   16
#define NM      13
#define NS      9
#define NFEAT   22
#define TM      128
#define MAXROWS (1024*NP)

// 22-dim normalized feature rows (203776 x 22)
__device__ float g_F[(size_t)MAXROWS * NFEAT];

__device__ __forceinline__ float geluf(float v){
    return 0.5f * v * (1.0f + erff(v * 0.7071067811865476f));
}
__device__ __forceinline__ float freqf(int k){
    return (float)(((double)k * 200.0) / 30.0);
}

// mma.sync m16n8k16 bf16 -> f32, accumulate in place
__device__ __forceinline__ void mma16816(float* d, const uint32_t* a,
                                         const uint32_t* b){
    asm volatile(
        "mma.sync.aligned.m16n8k16.row.col.f32.bf16.bf16.f32 "
        "{%0,%1,%2,%3}, {%4,%5,%6,%7}, {%8,%9}, {%0,%1,%2,%3};"
        : "+f"(d[0]), "+f"(d[1]), "+f"(d[2]), "+f"(d[3])
        : "r"(a[0]), "r"(a[1]), "r"(a[2]), "r"(a[3]), "r"(b[0]), "r"(b[1]));
}

// ============================================================
// Kernel A: per-patch features + group layernorms -> g_F
// (unchanged 75us version)
// ============================================================
__global__ __launch_bounds__(256) void feat_kernel(
    const float* __restrict__ x,
    const float* __restrict__ gm, const float* __restrict__ bm,
    const float* __restrict__ gs, const float* __restrict__ bs)
{
    __shared__ float sx[TLEN];
    __shared__ float cosT[NFREQ * 16];
    __shared__ float sinT[NFREQ * 16];
    __shared__ float hannS[NSP];
    __shared__ float psdS[NFREQ * 200];

    const int tid = threadIdx.x;
    {
        const float4* xg = (const float4*)(x + (size_t)blockIdx.x * TLEN);
        float4* s4 = (float4*)sx;
        for (int i = tid; i < TLEN/4; i += 256) s4[i] = xg[i];
    }
    for (int i = tid; i < NFREQ*16; i += 256) {
        int k = i >> 4, t = i & 15;
        double sv, cv;
        sincospi(2.0 * (double)(k * t) / 30.0, &sv, &cv);
        cosT[i] = (float)cv;
        sinT[i] = (float)sv;
    }
    if (tid < NSP)
        hannS[tid] = (float)(0.5 * (1.0 - cospi(2.0 * (double)tid / 30.0)));
    __syncthreads();
    if (tid >= NP) return;

    const int off = tid * PSTRIDE;
    float* frow = &g_F[((size_t)blockIdx.x * NP + tid) * NFEAT];

    float v0 = sx[off];
    float mx = v0, mn = v0, sum = v0;
    float sumsq = v0 * v0;
    float amax = fabsf(v0); int aidx = 0;
    float prev = v0;
    float tsg = v0 + 1e-10f;
    int   sprev = (tsg > 0.0f) - (tsg < 0.0f);
    float dmax = -INFINITY, dmin = INFINITY, dabs = 0.0f;
    int zc = 0;
    #pragma unroll
    for (int t = 1; t < PLEN; t++) {
        float v = sx[off + t];
        mx = fmaxf(mx, v); mn = fminf(mn, v);
        sum += v; sumsq = fmaf(v, v, sumsq);
        float a = fabsf(v);
        if (a > amax) { amax = a; aidx = t; }
        float d = v - prev;
        dmax = fmaxf(dmax, d); dmin = fminf(dmin, d); dabs += fabsf(d);
        float tg = v + 1e-10f;
        int sg = (tg > 0.0f) - (tg < 0.0f);
        zc += (sg != sprev);
        sprev = sg; prev = v;
    }
    float mean = sum * (1.0f/60.0f);

    float m2 = 0.f, m3 = 0.f, m4 = 0.f;
    #pragma unroll
    for (int t = 0; t < PLEN; t++) {
        float c = sx[off + t] - mean;
        float c2 = c * c;
        m2 += c2; m3 = fmaf(c2, c, m3); m4 = fmaf(c2, c2, m4);
    }
    m2 *= (1.0f/60.0f); m3 *= (1.0f/60.0f); m4 *= (1.0f/60.0f);
    float stdv = sqrtf(m2);

    {
        float morph[NM];
        morph[0] = mx; morph[1] = mn; morph[2] = mx - mn; morph[3] = mean;
        morph[4] = stdv;
        morph[5] = (float)aidx * (1.0f/60.0f);
        morph[6] = dmax; morph[7] = dmin;
        morph[8] = dabs * (1.0f/59.0f);
        morph[9] = (float)zc * (1.0f/60.0f);
        morph[10] = sumsq;
        morph[11] = m4 / (m2 * m2) - 3.0f;
        morph[12] = m3 / (m2 * stdv);
        #pragma unroll
        for (int i = 0; i < NM; i++) if (!isfinite(morph[i])) morph[i] = 0.0f;

        float mu = 0.f;
        #pragma unroll
        for (int i = 0; i < NM; i++) mu += morph[i];
        mu *= (1.0f/13.0f);
        float var = 0.f;
        #pragma unroll
        for (int i = 0; i < NM; i++) { float d = morph[i]-mu; var = fmaf(d,d,var); }
        var *= (1.0f/13.0f);
        float scl = rsqrtf(var + 1e-5f);
        #pragma unroll
        for (int i = 0; i < NM; i++)
            frow[i] = fmaf((morph[i]-mu)*scl, gm[i], bm[i]);
    }

    float ye0[16], yo0[15], ye1[16], yo1[15], ye2[16], yo2[15];

    #define FOLD_SEG(YE, YO, SB) { \
        float s = 0.f; \
        _Pragma("unroll") \
        for (int t = 0; t < NSP; t++) s += sx[(SB) + t]; \
        s *= (1.0f/30.0f); \
        float s2 = 2.0f * s; \
        _Pragma("unroll") \
        for (int t = 1; t < 15; t++) { \
            float a = sx[(SB) + t]; \
            float b = sx[(SB) + 30 - t]; \
            float w = hannS[t]; \
            YE[t] = (a + b - s2) * w; \
            YO[t] = (a - b) * w; \
        } \
        YE[15] = sx[(SB) + 15] - s; \
    }

    FOLD_SEG(ye0, yo0, off)
    FOLD_SEG(ye1, yo1, off + 15)
    FOLD_SEG(ye2, yo2, off + 30)
    #undef FOLD_SEG

    for (int k = 0; k < NFREQ; k++) {
        const float* ck = &cosT[k * 16];
        const float* sk = &sinT[k * 16];
        float re0 = 0.f, im0 = 0.f, re1 = 0.f, im1 = 0.f, re2 = 0.f, im2 = 0.f;
        #pragma unroll
        for (int t = 1; t < 15; t++) {
            float c = ck[t], si = sk[t];
            re0 = fmaf(ye0[t], c, re0); im0 = fmaf(yo0[t], si, im0);
            re1 = fmaf(ye1[t], c, re1); im1 = fmaf(yo1[t], si, im1);
            re2 = fmaf(ye2[t], c, re2); im2 = fmaf(yo2[t], si, im2);
        }
        float c15 = ck[15];
        re0 = fmaf(ye0[15], c15, re0);
        re1 = fmaf(ye1[15], c15, re1);
        re2 = fmaf(ye2[15], c15, re2);
        float p = fmaf(re0,re0,im0*im0) + fmaf(re1,re1,im1*im1) + fmaf(re2,re2,im2*im2);
        float sc = (k == 0 || k == NFREQ-1) ? (1.0f/6750.0f) : (2.0f/6750.0f);
        psdS[k*200 + tid] = p * sc;
    }

    float psd[NFREQ];
    #pragma unroll
    for (int k = 0; k < NFREQ; k++) psd[k] = psdS[k*200 + tid];

    float total = 0.f;
    #pragma unroll
    for (int k = 0; k < NFREQ; k++) total += psd[k];
    total += 1e-12f;
    float inv = 1.0f / total;

    float b1v = psd[1];
    float b3v = psd[2] + psd[3] + psd[4];
    float b4v = 0.f;
    #pragma unroll
    for (int k = 5; k <= 14; k++) b4v += psd[k];

    float pmax = psd[0]; int pkk = 0;
    #pragma unroll
    for (int k = 1; k < NFREQ; k++)
        if (psd[k] > pmax) { pmax = psd[k]; pkk = k; }

    float thr = 0.95f * total;
    float csum = 0.f; int ek = 0; bool fnd = false;
    #pragma unroll
    for (int k = 0; k < NFREQ; k++) {
        csum += psd[k];
        if (!fnd && csum >= thr) { ek = k; fnd = true; }
    }
    float ent = 0.f;
    #pragma unroll
    for (int k = 0; k < NFREQ; k++) {
        float pn = psd[k] * inv;
        ent -= pn * log2f(pn + 1e-12f);
    }

    float spec[NS];
    spec[0] = 0.0f;
    spec[1] = b1v * inv;
    spec[2] = 0.0f;
    spec[3] = b3v * inv;
    spec[4] = b4v * inv;
    spec[5] = freqf(pkk);
    spec[6] = freqf(ek);
    spec[7] = ent;
    spec[8] = total;
    #pragma unroll
    for (int i = 0; i < NS; i++) if (!isfinite(spec[i])) spec[i] = 0.0f;

    {
        float mu = 0.f;
        #pragma unroll
        for (int i = 0; i < NS; i++) mu += spec[i];
        mu *= (1.0f/9.0f);
        float var = 0.f;
        #pragma unroll
        for (int i = 0; i < NS; i++) { float d = spec[i]-mu; var = fmaf(d,d,var); }
        var *= (1.0f/9.0f);
        float scl = rsqrtf(var + 1e-5f);
        #pragma unroll
        for (int i = 0; i < NS; i++)
            frow[NM + i] = fmaf((spec[i]-mu)*scl, gs[i], bs[i]);
    }
}

// ============================================================
// Kernel B: persistent MLP, GEMM2 via raw mma.sync (split-bf16 x3)
// TM=128, register-resident epilogue (no D smem round-trip)
// ============================================================
// smem layout (bytes):
#define OFF_BHI    0          // 256 x 256B = 65536
#define OFF_BLO    65536      // 65536
#define OFF_AHI    131072     // 128 x 256B = 32768
#define OFF_ALO    163840     // 32768
#define OFF_W1     196608     // 11264
#define OFF_FS     207872     // 11264
#define OFF_B1     219136     // 512
#define OFF_B2     219648     // 1024
#define OFF_GO     220672     // 1024
#define OFF_BO     221696     // 1024
#define OFF_PS     222720     // 2048
#define OFF_PQ     224768     // 2048
#define SMEM_BYTES 226816

// XOR swizzle at 16B granularity; 256B per row
__device__ __forceinline__ uint32_t offA(uint32_t row, uint32_t kbyte){
    return row * 256u + (kbyte ^ ((row & 7u) << 4));
}

__global__ __launch_bounds__(512, 1) void mlp_kernel(
    const float* __restrict__ W1, const float* __restrict__ b1,
    const float* __restrict__ W2, const float* __restrict__ b2,
    const float* __restrict__ go, const float* __restrict__ bo,
    float* __restrict__ out, int nRows)
{
    extern __shared__ char smc[];
    float* W1s = (float*)(smc + OFF_W1);
    float* Fs  = (float*)(smc + OFF_FS);
    float* b1s = (float*)(smc + OFF_B1);
    float* b2s = (float*)(smc + OFF_B2);
    float* gos = (float*)(smc + OFF_GO);
    float* bos = (float*)(smc + OFF_BO);
    float* partS = (float*)(smc + OFF_PS);   // [128][4]
    float* partQ = (float*)(smc + OFF_PQ);

    const int tid  = threadIdx.x;
    const int wid  = tid >> 5;
    const int lane = tid & 31;
    const int gid  = lane >> 2;   // 0..7
    const int tig  = lane & 3;    // 0..3

    // ---- one-time setup ----
    for (int i = tid; i < 22*128; i += 512) W1s[i] = W1[i];
    if (tid < 128) b1s[tid] = b1[tid];
    for (int i = tid; i < 256; i += 512) { b2s[i]=b2[i]; gos[i]=go[i]; bos[i]=bo[i]; }

    // W2 [k][n] -> B_T panels [n][kbyte] bf16, swizzled
    for (int i = tid; i < 128*256; i += 512) {
        int k = i >> 8, n = i & 255;
        float w = W2[i];
        __nv_bfloat16 hi = __float2bfloat16_rn(w);
        float rlo = w - __bfloat162float(hi);
        __nv_bfloat16 lo = __float2bfloat16_rn(rlo);
        uint32_t o = offA((uint32_t)n, (uint32_t)(2*k));
        *(__nv_bfloat16*)(smc + OFF_BHI + o) = hi;
        *(__nv_bfloat16*)(smc + OFF_BLO + o) = lo;
    }
    __syncthreads();

    const int c1 = lane * 4;              // GEMM1 cols (= GEMM2 k)
    float* Fw = Fs + wid * (8 * NFEAT);

    const int mbg = wid & 3;              // row group: 32 rows
    const int nh  = wid >> 2;             // col group: 64 cols
    const int nTiles = (nRows + TM - 1) / TM;

    for (int tile = blockIdx.x; tile < nTiles; tile += gridDim.x) {
        const int rowBase = tile * TM;
        const int wRow = rowBase + wid * 8;

        __syncthreads();   // prev tile's A-panel & partial reads complete

        // ---- per-warp F staging (8 rows x 22) ----
        {
            const float* src = &g_F[(size_t)wRow * NFEAT];
            for (int i = lane; i < 8 * NFEAT; i += 32)
                Fw[i] = (wRow + i / NFEAT < nRows) ? src[i] : 0.0f;
        }
        __syncwarp();

        // ---- GEMM1 + bias + GELU -> split bf16 A panels (swizzled) ----
        {
            float acc[8][4];
            #pragma unroll
            for (int i = 0; i < 8; i++)
                #pragma unroll
                for (int j = 0; j < 4; j++) acc[i][j] = 0.0f;
            #pragma unroll
            for (int k = 0; k < NFEAT; k++) {
                float4 w = *(const float4*)&W1s[k*128 + c1];
                #pragma unroll
                for (int i = 0; i < 8; i++) {
                    float a = Fw[i*NFEAT + k];
                    acc[i][0] = fmaf(a, w.x, acc[i][0]);
                    acc[i][1] = fmaf(a, w.y, acc[i][1]);
                    acc[i][2] = fmaf(a, w.z, acc[i][2]);
                    acc[i][3] = fmaf(a, w.w, acc[i][3]);
                }
            }
            float bv[4] = { b1s[c1], b1s[c1+1], b1s[c1+2], b1s[c1+3] };
            #pragma unroll
            for (int i = 0; i < 8; i++) {
                unsigned long long hp = 0, lp = 0;
                #pragma unroll
                for (int j = 0; j < 4; j++) {
                    float h = geluf(acc[i][j] + bv[j]);
                    __nv_bfloat16 hb = __float2bfloat16_rn(h);
                    float rl = h - __bfloat162float(hb);
                    __nv_bfloat16 lb = __float2bfloat16_rn(rl);
                    hp |= (unsigned long long)__bfloat16_as_ushort(hb) << (16*j);
                    lp |= (unsigned long long)__bfloat16_as_ushort(lb) << (16*j);
                }
                uint32_t row = (uint32_t)(wid * 8 + i);
                uint32_t o = offA(row, (uint32_t)(lane * 8));
                *(unsigned long long*)(smc + OFF_AHI + o) = hp;
                *(unsigned long long*)(smc + OFF_ALO + o) = lp;
            }
        }
        __syncthreads();

        // ---- GEMM2: warp = 32 rows (2 m-blocks) x 64 cols (8 n-blocks) ----
        float acc[2][8][4];
        #pragma unroll
        for (int m = 0; m < 2; m++)
            #pragma unroll
            for (int nb = 0; nb < 8; nb++)
                #pragma unroll
                for (int j = 0; j < 4; j++) acc[m][nb][j] = 0.0f;

        #pragma unroll
        for (int kb = 0; kb < 8; kb++) {
            const uint32_t kbyte = (uint32_t)(kb * 32 + tig * 4);
            uint32_t ah[2][4], al[2][4];
            #pragma unroll
            for (int m = 0; m < 2; m++) {
                uint32_t r = (uint32_t)(mbg * 32 + m * 16 + gid);
                ah[m][0] = *(const uint32_t*)(smc + OFF_AHI + offA(r,     kbyte));
                ah[m][1] = *(const uint32_t*)(smc + OFF_AHI + offA(r + 8, kbyte));
                ah[m][2] = *(const uint32_t*)(smc + OFF_AHI + offA(r,     kbyte + 16));
                ah[m][3] = *(const uint32_t*)(smc + OFF_AHI + offA(r + 8, kbyte + 16));
                al[m][0] = *(const uint32_t*)(smc + OFF_ALO + offA(r,     kbyte));
                al[m][1] = *(const uint32_t*)(smc + OFF_ALO + offA(r + 8, kbyte));
                al[m][2] = *(const uint32_t*)(smc + OFF_ALO + offA(r,     kbyte + 16));
                al[m][3] = *(const uint32_t*)(smc + OFF_ALO + offA(r + 8, kbyte + 16));
            }
            #pragma unroll
            for (int nb = 0; nb < 8; nb++) {
                uint32_t n = (uint32_t)(nh * 64 + nb * 8 + gid);
                uint32_t bh[2], bl[2];
                bh[0] = *(const uint32_t*)(smc + OFF_BHI + offA(n, kbyte));
                bh[1] = *(const uint32_t*)(smc + OFF_BHI + offA(n, kbyte + 16));
                bl[0] = *(const uint32_t*)(smc + OFF_BLO + offA(n, kbyte));
                bl[1] = *(const uint32_t*)(smc + OFF_BLO + offA(n, kbyte + 16));
                mma16816(acc[0][nb], ah[0], bh);
                mma16816(acc[0][nb], ah[0], bl);
                mma16816(acc[0][nb], al[0], bh);
                mma16816(acc[1][nb], ah[1], bh);
                mma16816(acc[1][nb], ah[1], bl);
                mma16816(acc[1][nb], al[1], bh);
            }
        }

        // ---- epilogue: +b2, per-row LN partials via quad shuffles ----
        #pragma unroll
        for (int nb = 0; nb < 8; nb++) {
            int col = nh * 64 + nb * 8 + tig * 2;
            float bx = b2s[col], by = b2s[col + 1];
            #pragma unroll
            for (int m = 0; m < 2; m++) {
                acc[m][nb][0] += bx; acc[m][nb][1] += by;
                acc[m][nb][2] += bx; acc[m][nb][3] += by;
            }
        }
        #pragma unroll
        for (int m = 0; m < 2; m++) {
            float s0 = 0.f, q0 = 0.f, s1 = 0.f, q1 = 0.f;
            #pragma unroll
            for (int nb = 0; nb < 8; nb++) {
                s0 += acc[m][nb][0] + acc[m][nb][1];
                q0 = fmaf(acc[m][nb][0], acc[m][nb][0], q0);
                q0 = fmaf(acc[m][nb][1], acc[m][nb][1], q0);
                s1 += acc[m][nb][2] + acc[m][nb][3];
                q1 = fmaf(acc[m][nb][2], acc[m][nb][2], q1);
                q1 = fmaf(acc[m][nb][3], acc[m][nb][3], q1);
            }
            #pragma unroll
            for (int o = 1; o <= 2; o <<= 1) {
                s0 += __shfl_xor_sync(0xffffffffu, s0, o);
                q0 += __shfl_xor_sync(0xffffffffu, q0, o);
                s1 += __shfl_xor_sync(0xffffffffu, s1, o);
                q1 += __shfl_xor_sync(0xffffffffu, q1, o);
            }
            if (tig == 0) {
                int r = mbg * 32 + m * 16 + gid;
                partS[r*4 + nh] = s0; partQ[r*4 + nh] = q0;
                partS[(r+8)*4 + nh] = s1; partQ[(r+8)*4 + nh] = q1;
            }
        }
        __syncthreads();

        // ---- normalize + store ----
        #pragma unroll
        for (int m = 0; m < 2; m++) {
            #pragma unroll
            for (int half = 0; half < 2; half++) {
                int r = mbg * 32 + m * 16 + gid + half * 8;
                float4 S4 = *(float4*)&partS[r*4];
                float4 Q4 = *(float4*)&partQ[r*4];
                float sum = (S4.x + S4.y) + (S4.z + S4.w);
                float sq  = (Q4.x + Q4.y) + (Q4.z + Q4.w);
                float mu = sum * (1.0f/256.0f);
                float var = sq * (1.0f/256.0f) - mu * mu;
                float rs = rsqrtf(var + 1e-5f);
                int grow = rowBase + r;
                if (grow < nRows) {
                    float* op = out + (size_t)grow * 256;
                    #pragma unroll
                    for (int nb = 0; nb < 8; nb++) {
                        int col = nh * 64 + nb * 8 + tig * 2;
                        float va = acc[m][nb][half*2+0];
                        float vb = acc[m][nb][half*2+1];
                        float2 o2;
                        o2.x = fmaf((va - mu) * rs, gos[col],   bos[col]);
                        o2.y = fmaf((vb - mu) * rs, gos[col+1], bos[col+1]);
                        *(float2*)(op + col) = o2;
                    }
                }
            }
        }
    }
}

extern "C" void kernel_launch(void* const* d_in, const int* in_sizes, int n_in,
                              void* d_out, int out_size) {
    const float* x  = (const float*)d_in[0];
    const float* gm = (const float*)d_in[1];
    const float* bm = (const float*)d_in[2];
    const float* gs = (const float*)d_in[3];
    const float* bs = (const float*)d_in[4];
    const float* W1 = (const float*)d_in[5];
    const float* b1 = (const float*)d_in[6];
    const float* W2 = (const float*)d_in[7];
    const float* b2 = (const float*)d_in[8];
    const float* go = (const float*)d_in[9];
    const float* bo = (const float*)d_in[10];

    int B = in_sizes[0] / TLEN;
    int nRows = B * NP;

    cudaFuncSetAttribute(mlp_kernel, cudaFuncAttributeMaxDynamicSharedMemorySize,
                         SMEM_BYTES);

    feat_kernel<<<B, 256>>>(x, gm, bm, gs, bs);
    mlp_kernel<<<148, 512, SMEM_BYTES>>>(
        W1, b1, W2, b2, go, bo, (float*)d_out, nRows);
}

// round 10
// speedup vs baseline: 1.8840x; 1.0297x over previous
#include <cuda_runtime.h>
#include <cuda_bf16.h>
#include <cstdint>
#include <stdint.h>
#include <math.h>

#define TLEN    6000
#define NP      199
#define PLEN    60
#define PSTRIDE 30
#define NSP     30
#define NFREQ   16
#define NM      13
#define NS      9
#define NFEAT   22
#define TM      128
#define MAXROWS (1024*NP)

// 22-dim normalized feature rows (203776 x 22)
__device__ float g_F[(size_t)MAXROWS * NFEAT];

__device__ __forceinline__ float geluf(float v){
    return 0.5f * v * (1.0f + erff(v * 0.7071067811865476f));
}
__device__ __forceinline__ float freqf(int k){
    return (float)(((double)k * 200.0) / 30.0);
}
__device__ __forceinline__ uint32_t smem_u32(const void* p){
    uint32_t a;
    asm("{ .reg .u64 t; cvta.to.shared.u64 t, %1; cvt.u32.u64 %0, t; }"
        : "=r"(a) : "l"(p));
    return a;
}

// mma.sync m16n8k16 bf16 -> f32, accumulate in place
__device__ __forceinline__ void mma16816(float* d, const uint32_t* a,
                                         const uint32_t* b){
    asm volatile(
        "mma.sync.aligned.m16n8k16.row.col.f32.bf16.bf16.f32 "
        "{%0,%1,%2,%3}, {%4,%5,%6,%7}, {%8,%9}, {%0,%1,%2,%3};"
        : "+f"(d[0]), "+f"(d[1]), "+f"(d[2]), "+f"(d[3])
        : "r"(a[0]), "r"(a[1]), "r"(a[2]), "r"(a[3]), "r"(b[0]), "r"(b[1]));
}
#define LDSM4(R, addr) \
    asm volatile("ldmatrix.sync.aligned.m8n8.x4.shared.b16 {%0,%1,%2,%3}, [%4];" \
        : "=r"((R)[0]), "=r"((R)[1]), "=r"((R)[2]), "=r"((R)[3]) : "r"(addr))

// ============================================================
// Kernel A: per-patch features + group layernorms -> g_F
// (unchanged 75us version)
// ============================================================
__global__ __launch_bounds__(256) void feat_kernel(
    const float* __restrict__ x,
    const float* __restrict__ gm, const float* __restrict__ bm,
    const float* __restrict__ gs, const float* __restrict__ bs)
{
    __shared__ float sx[TLEN];
    __shared__ float cosT[NFREQ * 16];
    __shared__ float sinT[NFREQ * 16];
    __shared__ float hannS[NSP];
    __shared__ float psdS[NFREQ * 200];

    const int tid = threadIdx.x;
    {
        const float4* xg = (const float4*)(x + (size_t)blockIdx.x * TLEN);
        float4* s4 = (float4*)sx;
        for (int i = tid; i < TLEN/4; i += 256) s4[i] = xg[i];
    }
    for (int i = tid; i < NFREQ*16; i += 256) {
        int k = i >> 4, t = i & 15;
        double sv, cv;
        sincospi(2.0 * (double)(k * t) / 30.0, &sv, &cv);
        cosT[i] = (float)cv;
        sinT[i] = (float)sv;
    }
    if (tid < NSP)
        hannS[tid] = (float)(0.5 * (1.0 - cospi(2.0 * (double)tid / 30.0)));
    __syncthreads();
    if (tid >= NP) return;

    const int off = tid * PSTRIDE;
    float* frow = &g_F[((size_t)blockIdx.x * NP + tid) * NFEAT];

    float v0 = sx[off];
    float mx = v0, mn = v0, sum = v0;
    float sumsq = v0 * v0;
    float amax = fabsf(v0); int aidx = 0;
    float prev = v0;
    float tsg = v0 + 1e-10f;
    int   sprev = (tsg > 0.0f) - (tsg < 0.0f);
    float dmax = -INFINITY, dmin = INFINITY, dabs = 0.0f;
    int zc = 0;
    #pragma unroll
    for (int t = 1; t < PLEN; t++) {
        float v = sx[off + t];
        mx = fmaxf(mx, v); mn = fminf(mn, v);
        sum += v; sumsq = fmaf(v, v, sumsq);
        float a = fabsf(v);
        if (a > amax) { amax = a; aidx = t; }
        float d = v - prev;
        dmax = fmaxf(dmax, d); dmin = fminf(dmin, d); dabs += fabsf(d);
        float tg = v + 1e-10f;
        int sg = (tg > 0.0f) - (tg < 0.0f);
        zc += (sg != sprev);
        sprev = sg; prev = v;
    }
    float mean = sum * (1.0f/60.0f);

    float m2 = 0.f, m3 = 0.f, m4 = 0.f;
    #pragma unroll
    for (int t = 0; t < PLEN; t++) {
        float c = sx[off + t] - mean;
        float c2 = c * c;
        m2 += c2; m3 = fmaf(c2, c, m3); m4 = fmaf(c2, c2, m4);
    }
    m2 *= (1.0f/60.0f); m3 *= (1.0f/60.0f); m4 *= (1.0f/60.0f);
    float stdv = sqrtf(m2);

    {
        float morph[NM];
        morph[0] = mx; morph[1] = mn; morph[2] = mx - mn; morph[3] = mean;
        morph[4] = stdv;
        morph[5] = (float)aidx * (1.0f/60.0f);
        morph[6] = dmax; morph[7] = dmin;
        morph[8] = dabs * (1.0f/59.0f);
        morph[9] = (float)zc * (1.0f/60.0f);
        morph[10] = sumsq;
        morph[11] = m4 / (m2 * m2) - 3.0f;
        morph[12] = m3 / (m2 * stdv);
        #pragma unroll
        for (int i = 0; i < NM; i++) if (!isfinite(morph[i])) morph[i] = 0.0f;

        float mu = 0.f;
        #pragma unroll
        for (int i = 0; i < NM; i++) mu += morph[i];
        mu *= (1.0f/13.0f);
        float var = 0.f;
        #pragma unroll
        for (int i = 0; i < NM; i++) { float d = morph[i]-mu; var = fmaf(d,d,var); }
        var *= (1.0f/13.0f);
        float scl = rsqrtf(var + 1e-5f);
        #pragma unroll
        for (int i = 0; i < NM; i++)
            frow[i] = fmaf((morph[i]-mu)*scl, gm[i], bm[i]);
    }

    float ye0[16], yo0[15], ye1[16], yo1[15], ye2[16], yo2[15];

    #define FOLD_SEG(YE, YO, SB) { \
        float s = 0.f; \
        _Pragma("unroll") \
        for (int t = 0; t < NSP; t++) s += sx[(SB) + t]; \
        s *= (1.0f/30.0f); \
        float s2 = 2.0f * s; \
        _Pragma("unroll") \
        for (int t = 1; t < 15; t++) { \
            float a = sx[(SB) + t]; \
            float b = sx[(SB) + 30 - t]; \
            float w = hannS[t]; \
            YE[t] = (a + b - s2) * w; \
            YO[t] = (a - b) * w; \
        } \
        YE[15] = sx[(SB) + 15] - s; \
    }

    FOLD_SEG(ye0, yo0, off)
    FOLD_SEG(ye1, yo1, off + 15)
    FOLD_SEG(ye2, yo2, off + 30)
    #undef FOLD_SEG

    for (int k = 0; k < NFREQ; k++) {
        const float* ck = &cosT[k * 16];
        const float* sk = &sinT[k * 16];
        float re0 = 0.f, im0 = 0.f, re1 = 0.f, im1 = 0.f, re2 = 0.f, im2 = 0.f;
        #pragma unroll
        for (int t = 1; t < 15; t++) {
            float c = ck[t], si = sk[t];
            re0 = fmaf(ye0[t], c, re0); im0 = fmaf(yo0[t], si, im0);
            re1 = fmaf(ye1[t], c, re1); im1 = fmaf(yo1[t], si, im1);
            re2 = fmaf(ye2[t], c, re2); im2 = fmaf(yo2[t], si, im2);
        }
        float c15 = ck[15];
        re0 = fmaf(ye0[15], c15, re0);
        re1 = fmaf(ye1[15], c15, re1);
        re2 = fmaf(ye2[15], c15, re2);
        float p = fmaf(re0,re0,im0*im0) + fmaf(re1,re1,im1*im1) + fmaf(re2,re2,im2*im2);
        float sc = (k == 0 || k == NFREQ-1) ? (1.0f/6750.0f) : (2.0f/6750.0f);
        psdS[k*200 + tid] = p * sc;
    }

    float psd[NFREQ];
    #pragma unroll
    for (int k = 0; k < NFREQ; k++) psd[k] = psdS[k*200 + tid];

    float total = 0.f;
    #pragma unroll
    for (int k = 0; k < NFREQ; k++) total += psd[k];
    total += 1e-12f;
    float inv = 1.0f / total;

    float b1v = psd[1];
    float b3v = psd[2] + psd[3] + psd[4];
    float b4v = 0.f;
    #pragma unroll
    for (int k = 5; k <= 14; k++) b4v += psd[k];

    float pmax = psd[0]; int pkk = 0;
    #pragma unroll
    for (int k = 1; k < NFREQ; k++)
        if (psd[k] > pmax) { pmax = psd[k]; pkk = k; }

    float thr = 0.95f * total;
    float csum = 0.f; int ek = 0; bool fnd = false;
    #pragma unroll
    for (int k = 0; k < NFREQ; k++) {
        csum += psd[k];
        if (!fnd && csum >= thr) { ek = k; fnd = true; }
    }
    float ent = 0.f;
    #pragma unroll
    for (int k = 0; k < NFREQ; k++) {
        float pn = psd[k] * inv;
        ent -= pn * log2f(pn + 1e-12f);
    }

    float spec[NS];
    spec[0] = 0.0f;
    spec[1] = b1v * inv;
    spec[2] = 0.0f;
    spec[3] = b3v * inv;
    spec[4] = b4v * inv;
    spec[5] = freqf(pkk);
    spec[6] = freqf(ek);
    spec[7] = ent;
    spec[8] = total;
    #pragma unroll
    for (int i = 0; i < NS; i++) if (!isfinite(spec[i])) spec[i] = 0.0f;

    {
        float mu = 0.f;
        #pragma unroll
        for (int i = 0; i < NS; i++) mu += spec[i];
        mu *= (1.0f/9.0f);
        float var = 0.f;
        #pragma unroll
        for (int i = 0; i < NS; i++) { float d = spec[i]-mu; var = fmaf(d,d,var); }
        var *= (1.0f/9.0f);
        float scl = rsqrtf(var + 1e-5f);
        #pragma unroll
        for (int i = 0; i < NS; i++)
            frow[NM + i] = fmaf((spec[i]-mu)*scl, gs[i], bs[i]);
    }
}

// ============================================================
// Kernel B: persistent MLP, GEMM2 via mma.sync + ldmatrix
// (split-bf16 x3, register-resident LN epilogue)
// ============================================================
#define OFF_BHI    0          // 256 x 256B = 65536
#define OFF_BLO    65536      // 65536
#define OFF_AHI    131072     // 128 x 256B = 32768
#define OFF_ALO    163840     // 32768
#define OFF_W1     196608     // 11264
#define OFF_FS     207872     // 11264
#define OFF_B1     219136     // 512
#define OFF_B2     219648     // 1024
#define OFF_GO     220672     // 1024
#define OFF_BO     221696     // 1024
#define OFF_PS     222720     // 2048
#define OFF_PQ     224768     // 2048
#define SMEM_BYTES 226816

// XOR swizzle at 16B granularity; 256B per row
__device__ __forceinline__ uint32_t offA(uint32_t row, uint32_t kbyte){
    return row * 256u + (kbyte ^ ((row & 7u) << 4));
}

__global__ __launch_bounds__(512, 1) void mlp_kernel(
    const float* __restrict__ W1, const float* __restrict__ b1,
    const float* __restrict__ W2, const float* __restrict__ b2,
    const float* __restrict__ go, const float* __restrict__ bo,
    float* __restrict__ out, int nRows)
{
    extern __shared__ char smc[];
    const uint32_t sm32 = smem_u32(smc);
    float* W1s = (float*)(smc + OFF_W1);
    float* Fs  = (float*)(smc + OFF_FS);
    float* b1s = (float*)(smc + OFF_B1);
    float* b2s = (float*)(smc + OFF_B2);
    float* gos = (float*)(smc + OFF_GO);
    float* bos = (float*)(smc + OFF_BO);
    float* partS = (float*)(smc + OFF_PS);   // [128][4]
    float* partQ = (float*)(smc + OFF_PQ);

    const int tid  = threadIdx.x;
    const int wid  = tid >> 5;
    const int lane = tid & 31;
    const int gid  = lane >> 2;   // 0..7
    const int tig  = lane & 3;    // 0..3

    // ---- one-time setup ----
    for (int i = tid; i < 22*128; i += 512) W1s[i] = W1[i];
    if (tid < 128) b1s[tid] = b1[tid];
    for (int i = tid; i < 256; i += 512) { b2s[i]=b2[i]; gos[i]=go[i]; bos[i]=bo[i]; }

    // W2 [k][n] -> B_T panels [n][kbyte] bf16, swizzled
    for (int i = tid; i < 128*256; i += 512) {
        int k = i >> 8, n = i & 255;
        float w = W2[i];
        __nv_bfloat16 hi = __float2bfloat16_rn(w);
        float rlo = w - __bfloat162float(hi);
        __nv_bfloat16 lo = __float2bfloat16_rn(rlo);
        uint32_t o = offA((uint32_t)n, (uint32_t)(2*k));
        *(__nv_bfloat16*)(smc + OFF_BHI + o) = hi;
        *(__nv_bfloat16*)(smc + OFF_BLO + o) = lo;
    }
    __syncthreads();

    const int c1 = lane * 4;              // GEMM1 cols (= GEMM2 k)
    float* Fw = Fs + wid * (8 * NFEAT);

    const int mbg = wid & 3;              // row group: 32 rows
    const int nh  = wid >> 2;             // col group: 64 cols
    const int nTiles = (nRows + TM - 1) / TM;

    // ---- ldmatrix per-lane address invariants ----
    const uint32_t swz   = (uint32_t)(lane & 7) << 4;
    const uint32_t chA   = (uint32_t)((lane >> 4) & 1) * 16;   // A: g>>1 -> k-chunk
    const uint32_t rA    = (uint32_t)(mbg * 32 + (lane & 7) + ((lane >> 3) & 1) * 8);
    const uint32_t aB0   = sm32 + OFF_AHI + rA * 256;          // m-block 0
    const uint32_t aB1   = aB0 + 4096;                         // m-block 1 (+16 rows)
    const uint32_t chB   = (uint32_t)((lane >> 3) & 1) * 16;   // B: g&1 -> k-chunk
    const uint32_t bCst  = sm32 + OFF_BHI
                         + (uint32_t)(nh * 64 + (lane & 7)) * 256
                         + (uint32_t)((lane >> 4) & 1) * 2048; // g>>1 -> nb within pair

    for (int tile = blockIdx.x; tile < nTiles; tile += gridDim.x) {
        const int rowBase = tile * TM;
        const int wRow = rowBase + wid * 8;

        __syncthreads();   // prev tile's A-panel & partial reads complete

        // ---- per-warp F staging (8 rows x 22) ----
        {
            const float* src = &g_F[(size_t)wRow * NFEAT];
            for (int i = lane; i < 8 * NFEAT; i += 32)
                Fw[i] = (wRow + i / NFEAT < nRows) ? src[i] : 0.0f;
        }
        __syncwarp();

        // ---- GEMM1 + bias + GELU -> split bf16 A panels (swizzled) ----
        {
            float acc1[8][4];
            #pragma unroll
            for (int i = 0; i < 8; i++)
                #pragma unroll
                for (int j = 0; j < 4; j++) acc1[i][j] = 0.0f;
            #pragma unroll
            for (int k = 0; k < NFEAT; k++) {
                float4 w = *(const float4*)&W1s[k*128 + c1];
                #pragma unroll
                for (int i = 0; i < 8; i++) {
                    float a = Fw[i*NFEAT + k];
                    acc1[i][0] = fmaf(a, w.x, acc1[i][0]);
                    acc1[i][1] = fmaf(a, w.y, acc1[i][1]);
                    acc1[i][2] = fmaf(a, w.z, acc1[i][2]);
                    acc1[i][3] = fmaf(a, w.w, acc1[i][3]);
                }
            }
            float bv[4] = { b1s[c1], b1s[c1+1], b1s[c1+2], b1s[c1+3] };
            #pragma unroll
            for (int i = 0; i < 8; i++) {
                unsigned long long hp = 0, lp = 0;
                #pragma unroll
                for (int j = 0; j < 4; j++) {
                    float h = geluf(acc1[i][j] + bv[j]);
                    __nv_bfloat16 hb = __float2bfloat16_rn(h);
                    float rl = h - __bfloat162float(hb);
                    __nv_bfloat16 lb = __float2bfloat16_rn(rl);
                    hp |= (unsigned long long)__bfloat16_as_ushort(hb) << (16*j);
                    lp |= (unsigned long long)__bfloat16_as_ushort(lb) << (16*j);
                }
                uint32_t row = (uint32_t)(wid * 8 + i);
                uint32_t o = offA(row, (uint32_t)(lane * 8));
                *(unsigned long long*)(smc + OFF_AHI + o) = hp;
                *(unsigned long long*)(smc + OFF_ALO + o) = lp;
            }
        }
        __syncthreads();

        // ---- GEMM2: warp = 32 rows (2 m-blocks) x 64 cols (8 n-blocks) ----
        float acc[2][8][4];
        #pragma unroll
        for (int m = 0; m < 2; m++)
            #pragma unroll
            for (int nb = 0; nb < 8; nb++)
                #pragma unroll
                for (int j = 0; j < 4; j++) acc[m][nb][j] = 0.0f;

        #pragma unroll
        for (int kb = 0; kb < 8; kb++) {
            const uint32_t kxA = ((uint32_t)(kb * 32) + chA) ^ swz;
            const uint32_t kxB = ((uint32_t)(kb * 32) + chB) ^ swz;

            uint32_t ah0[4], ah1[4], al0[4], al1[4];
            LDSM4(ah0, aB0 + kxA);
            LDSM4(ah1, aB1 + kxA);
            LDSM4(al0, aB0 + 32768u + kxA);
            LDSM4(al1, aB1 + 32768u + kxA);

            #pragma unroll
            for (int p = 0; p < 4; p++) {
                uint32_t bh[4], bl[4];
                uint32_t ba = bCst + (uint32_t)(p * 4096) + kxB;
                LDSM4(bh, ba);
                LDSM4(bl, ba + 65536u);
                // nb = 2p : frag {bh[0],bh[1]} ; nb = 2p+1 : frag {bh[2],bh[3]}
                mma16816(acc[0][2*p],   ah0, bh);
                mma16816(acc[0][2*p],   ah0, bl);
                mma16816(acc[0][2*p],   al0, bh);
                mma16816(acc[1][2*p],   ah1, bh);
                mma16816(acc[1][2*p],   ah1, bl);
                mma16816(acc[1][2*p],   al1, bh);
                mma16816(acc[0][2*p+1], ah0, bh + 2);
                mma16816(acc[0][2*p+1], ah0, bl + 2);
                mma16816(acc[0][2*p+1], al0, bh + 2);
                mma16816(acc[1][2*p+1], ah1, bh + 2);
                mma16816(acc[1][2*p+1], ah1, bl + 2);
                mma16816(acc[1][2*p+1], al1, bh + 2);
            }
        }

        // ---- epilogue: +b2, per-row LN partials via quad shuffles ----
        #pragma unroll
        for (int nb = 0; nb < 8; nb++) {
            int col = nh * 64 + nb * 8 + tig * 2;
            float bx = b2s[col], by = b2s[col + 1];
            #pragma unroll
            for (int m = 0; m < 2; m++) {
                acc[m][nb][0] += bx; acc[m][nb][1] += by;
                acc[m][nb][2] += bx; acc[m][nb][3] += by;
            }
        }
        #pragma unroll
        for (int m = 0; m < 2; m++) {
            float s0 = 0.f, q0 = 0.f, s1 = 0.f, q1 = 0.f;
            #pragma unroll
            for (int nb = 0; nb < 8; nb++) {
                s0 += acc[m][nb][0] + acc[m][nb][1];
                q0 = fmaf(acc[m][nb][0], acc[m][nb][0], q0);
                q0 = fmaf(acc[m][nb][1], acc[m][nb][1], q0);
                s1 += acc[m][nb][2] + acc[m][nb][3];
                q1 = fmaf(acc[m][nb][2], acc[m][nb][2], q1);
                q1 = fmaf(acc[m][nb][3], acc[m][nb][3], q1);
            }
            #pragma unroll
            for (int o = 1; o <= 2; o <<= 1) {
                s0 += __shfl_xor_sync(0xffffffffu, s0, o);
                q0 += __shfl_xor_sync(0xffffffffu, q0, o);
                s1 += __shfl_xor_sync(0xffffffffu, s1, o);
                q1 += __shfl_xor_sync(0xffffffffu, q1, o);
            }
            if (tig == 0) {
                int r = mbg * 32 + m * 16 + gid;
                partS[r*4 + nh] = s0; partQ[r*4 + nh] = q0;
                partS[(r+8)*4 + nh] = s1; partQ[(r+8)*4 + nh] = q1;
            }
        }
        __syncthreads();

        // ---- normalize + store ----
        #pragma unroll
        for (int m = 0; m < 2; m++) {
            #pragma unroll
            for (int half = 0; half < 2; half++) {
                int r = mbg * 32 + m * 16 + gid + half * 8;
                float4 S4 = *(float4*)&partS[r*4];
                float4 Q4 = *(float4*)&partQ[r*4];
                float sum = (S4.x + S4.y) + (S4.z + S4.w);
                float sq  = (Q4.x + Q4.y) + (Q4.z + Q4.w);
                float mu = sum * (1.0f/256.0f);
                float var = sq * (1.0f/256.0f) - mu * mu;
                float rs = rsqrtf(var + 1e-5f);
                int grow = rowBase + r;
                if (grow < nRows) {
                    float* op = out + (size_t)grow * 256;
                    #pragma unroll
                    for (int nb = 0; nb < 8; nb++) {
                        int col = nh * 64 + nb * 8 + tig * 2;
                        float va = acc[m][nb][half*2+0];
                        float vb = acc[m][nb][half*2+1];
                        float2 o2;
                        o2.x = fmaf((va - mu) * rs, gos[col],   bos[col]);
                        o2.y = fmaf((vb - mu) * rs, gos[col+1], bos[col+1]);
                        *(float2*)(op + col) = o2;
                    }
                }
            }
        }
    }
}

extern "C" void kernel_launch(void* const* d_in, const int* in_sizes, int n_in,
                              void* d_out, int out_size) {
    const float* x  = (const float*)d_in[0];
    const float* gm = (const float*)d_in[1];
    const float* bm = (const float*)d_in[2];
    const float* gs = (const float*)d_in[3];
    const float* bs = (const float*)d_in[4];
    const float* W1 = (const float*)d_in[5];
    const float* b1 = (const float*)d_in[6];
    const float* W2 = (const float*)d_in[7];
    const float* b2 = (const float*)d_in[8];
    const float* go = (const float*)d_in[9];
    const float* bo = (const float*)d_in[10];

    int B = in_sizes[0] / TLEN;
    int nRows = B * NP;

    cudaFuncSetAttribute(mlp_kernel, cudaFuncAttributeMaxDynamicSharedMemorySize,
                         SMEM_BYTES);

    feat_kernel<<<B, 256>>>(x, gm, bm, gs, bs);
    mlp_kernel<<<148, 512, SMEM_BYTES>>>(
        W1, b1, W2, b2, go, bo, (float*)d_out, nRows);
}

// round 11
// speedup vs baseline: 1.9273x; 1.0230x over previous
#include <cuda_runtime.h>
#include <cuda_bf16.h>
#include <cstdint>
#include <stdint.h>
#include <math.h>

#define TLEN    6000
#define NP      199
#define PLEN    60
#define PSTRIDE 30
#define NSP     30
#define NFREQ   16
#define NM      13
#define NS      9
#define NFEAT   22
#define GTM     64            // rows per group tile
#define MAXROWS (1024*NP)

// 22-dim normalized feature rows (203776 x 22)
__device__ float g_F[(size_t)MAXROWS * NFEAT];

__device__ __forceinline__ float geluf(float v){
    return 0.5f * v * (1.0f + erff(v * 0.7071067811865476f));
}
__device__ __forceinline__ float freqf(int k){
    return (float)(((double)k * 200.0) / 30.0);
}
__device__ __forceinline__ uint32_t smem_u32(const void* p){
    uint32_t a;
    asm("{ .reg .u64 t; cvta.to.shared.u64 t, %1; cvt.u32.u64 %0, t; }"
        : "=r"(a) : "l"(p));
    return a;
}

// mma.sync m16n8k16 bf16 -> f32, accumulate in place
__device__ __forceinline__ void mma16816(float* d, const uint32_t* a,
                                         const uint32_t* b){
    asm volatile(
        "mma.sync.aligned.m16n8k16.row.col.f32.bf16.bf16.f32 "
        "{%0,%1,%2,%3}, {%4,%5,%6,%7}, {%8,%9}, {%0,%1,%2,%3};"
        : "+f"(d[0]), "+f"(d[1]), "+f"(d[2]), "+f"(d[3])
        : "r"(a[0]), "r"(a[1]), "r"(a[2]), "r"(a[3]), "r"(b[0]), "r"(b[1]));
}
#define LDSM4(R, addr) \
    asm volatile("ldmatrix.sync.aligned.m8n8.x4.shared.b16 {%0,%1,%2,%3}, [%4];" \
        : "=r"((R)[0]), "=r"((R)[1]), "=r"((R)[2]), "=r"((R)[3]) : "r"(addr))
#define BARG(id) \
    asm volatile("bar.sync %0, 256;" :: "r"(id) : "memory")

// ============================================================
// Kernel A: per-patch features + group layernorms -> g_F
// (unchanged 75us version)
// ============================================================
__global__ __launch_bounds__(256) void feat_kernel(
    const float* __restrict__ x,
    const float* __restrict__ gm, const float* __restrict__ bm,
    const float* __restrict__ gs, const float* __restrict__ bs)
{
    __shared__ float sx[TLEN];
    __shared__ float cosT[NFREQ * 16];
    __shared__ float sinT[NFREQ * 16];
    __shared__ float hannS[NSP];
    __shared__ float psdS[NFREQ * 200];

    const int tid = threadIdx.x;
    {
        const float4* xg = (const float4*)(x + (size_t)blockIdx.x * TLEN);
        float4* s4 = (float4*)sx;
        for (int i = tid; i < TLEN/4; i += 256) s4[i] = xg[i];
    }
    for (int i = tid; i < NFREQ*16; i += 256) {
        int k = i >> 4, t = i & 15;
        double sv, cv;
        sincospi(2.0 * (double)(k * t) / 30.0, &sv, &cv);
        cosT[i] = (float)cv;
        sinT[i] = (float)sv;
    }
    if (tid < NSP)
        hannS[tid] = (float)(0.5 * (1.0 - cospi(2.0 * (double)tid / 30.0)));
    __syncthreads();
    if (tid >= NP) return;

    const int off = tid * PSTRIDE;
    float* frow = &g_F[((size_t)blockIdx.x * NP + tid) * NFEAT];

    float v0 = sx[off];
    float mx = v0, mn = v0, sum = v0;
    float sumsq = v0 * v0;
    float amax = fabsf(v0); int aidx = 0;
    float prev = v0;
    float tsg = v0 + 1e-10f;
    int   sprev = (tsg > 0.0f) - (tsg < 0.0f);
    float dmax = -INFINITY, dmin = INFINITY, dabs = 0.0f;
    int zc = 0;
    #pragma unroll
    for (int t = 1; t < PLEN; t++) {
        float v = sx[off + t];
        mx = fmaxf(mx, v); mn = fminf(mn, v);
        sum += v; sumsq = fmaf(v, v, sumsq);
        float a = fabsf(v);
        if (a > amax) { amax = a; aidx = t; }
        float d = v - prev;
        dmax = fmaxf(dmax, d); dmin = fminf(dmin, d); dabs += fabsf(d);
        float tg = v + 1e-10f;
        int sg = (tg > 0.0f) - (tg < 0.0f);
        zc += (sg != sprev);
        sprev = sg; prev = v;
    }
    float mean = sum * (1.0f/60.0f);

    float m2 = 0.f, m3 = 0.f, m4 = 0.f;
    #pragma unroll
    for (int t = 0; t < PLEN; t++) {
        float c = sx[off + t] - mean;
        float c2 = c * c;
        m2 += c2; m3 = fmaf(c2, c, m3); m4 = fmaf(c2, c2, m4);
    }
    m2 *= (1.0f/60.0f); m3 *= (1.0f/60.0f); m4 *= (1.0f/60.0f);
    float stdv = sqrtf(m2);

    {
        float morph[NM];
        morph[0] = mx; morph[1] = mn; morph[2] = mx - mn; morph[3] = mean;
        morph[4] = stdv;
        morph[5] = (float)aidx * (1.0f/60.0f);
        morph[6] = dmax; morph[7] = dmin;
        morph[8] = dabs * (1.0f/59.0f);
        morph[9] = (float)zc * (1.0f/60.0f);
        morph[10] = sumsq;
        morph[11] = m4 / (m2 * m2) - 3.0f;
        morph[12] = m3 / (m2 * stdv);
        #pragma unroll
        for (int i = 0; i < NM; i++) if (!isfinite(morph[i])) morph[i] = 0.0f;

        float mu = 0.f;
        #pragma unroll
        for (int i = 0; i < NM; i++) mu += morph[i];
        mu *= (1.0f/13.0f);
        float var = 0.f;
        #pragma unroll
        for (int i = 0; i < NM; i++) { float d = morph[i]-mu; var = fmaf(d,d,var); }
        var *= (1.0f/13.0f);
        float scl = rsqrtf(var + 1e-5f);
        #pragma unroll
        for (int i = 0; i < NM; i++)
            frow[i] = fmaf((morph[i]-mu)*scl, gm[i], bm[i]);
    }

    float ye0[16], yo0[15], ye1[16], yo1[15], ye2[16], yo2[15];

    #define FOLD_SEG(YE, YO, SB) { \
        float s = 0.f; \
        _Pragma("unroll") \
        for (int t = 0; t < NSP; t++) s += sx[(SB) + t]; \
        s *= (1.0f/30.0f); \
        float s2 = 2.0f * s; \
        _Pragma("unroll") \
        for (int t = 1; t < 15; t++) { \
            float a = sx[(SB) + t]; \
            float b = sx[(SB) + 30 - t]; \
            float w = hannS[t]; \
            YE[t] = (a + b - s2) * w; \
            YO[t] = (a - b) * w; \
        } \
        YE[15] = sx[(SB) + 15] - s; \
    }

    FOLD_SEG(ye0, yo0, off)
    FOLD_SEG(ye1, yo1, off + 15)
    FOLD_SEG(ye2, yo2, off + 30)
    #undef FOLD_SEG

    for (int k = 0; k < NFREQ; k++) {
        const float* ck = &cosT[k * 16];
        const float* sk = &sinT[k * 16];
        float re0 = 0.f, im0 = 0.f, re1 = 0.f, im1 = 0.f, re2 = 0.f, im2 = 0.f;
        #pragma unroll
        for (int t = 1; t < 15; t++) {
            float c = ck[t], si = sk[t];
            re0 = fmaf(ye0[t], c, re0); im0 = fmaf(yo0[t], si, im0);
            re1 = fmaf(ye1[t], c, re1); im1 = fmaf(yo1[t], si, im1);
            re2 = fmaf(ye2[t], c, re2); im2 = fmaf(yo2[t], si, im2);
        }
        float c15 = ck[15];
        re0 = fmaf(ye0[15], c15, re0);
        re1 = fmaf(ye1[15], c15, re1);
        re2 = fmaf(ye2[15], c15, re2);
        float p = fmaf(re0,re0,im0*im0) + fmaf(re1,re1,im1*im1) + fmaf(re2,re2,im2*im2);
        float sc = (k == 0 || k == NFREQ-1) ? (1.0f/6750.0f) : (2.0f/6750.0f);
        psdS[k*200 + tid] = p * sc;
    }

    float psd[NFREQ];
    #pragma unroll
    for (int k = 0; k < NFREQ; k++) psd[k] = psdS[k*200 + tid];

    float total = 0.f;
    #pragma unroll
    for (int k = 0; k < NFREQ; k++) total += psd[k];
    total += 1e-12f;
    float inv = 1.0f / total;

    float b1v = psd[1];
    float b3v = psd[2] + psd[3] + psd[4];
    float b4v = 0.f;
    #pragma unroll
    for (int k = 5; k <= 14; k++) b4v += psd[k];

    float pmax = psd[0]; int pkk = 0;
    #pragma unroll
    for (int k = 1; k < NFREQ; k++)
        if (psd[k] > pmax) { pmax = psd[k]; pkk = k; }

    float thr = 0.95f * total;
    float csum = 0.f; int ek = 0; bool fnd = false;
    #pragma unroll
    for (int k = 0; k < NFREQ; k++) {
        csum += psd[k];
        if (!fnd && csum >= thr) { ek = k; fnd = true; }
    }
    float ent = 0.f;
    #pragma unroll
    for (int k = 0; k < NFREQ; k++) {
        float pn = psd[k] * inv;
        ent -= pn * log2f(pn + 1e-12f);
    }

    float spec[NS];
    spec[0] = 0.0f;
    spec[1] = b1v * inv;
    spec[2] = 0.0f;
    spec[3] = b3v * inv;
    spec[4] = b4v * inv;
    spec[5] = freqf(pkk);
    spec[6] = freqf(ek);
    spec[7] = ent;
    spec[8] = total;
    #pragma unroll
    for (int i = 0; i < NS; i++) if (!isfinite(spec[i])) spec[i] = 0.0f;

    {
        float mu = 0.f;
        #pragma unroll
        for (int i = 0; i < NS; i++) mu += spec[i];
        mu *= (1.0f/9.0f);
        float var = 0.f;
        #pragma unroll
        for (int i = 0; i < NS; i++) { float d = spec[i]-mu; var = fmaf(d,d,var); }
        var *= (1.0f/9.0f);
        float scl = rsqrtf(var + 1e-5f);
        #pragma unroll
        for (int i = 0; i < NS; i++)
            frow[NM + i] = fmaf((spec[i]-mu)*scl, gs[i], bs[i]);
    }
}

// ============================================================
// Kernel B: persistent MLP, 2 staggered warp-groups x 64-row tiles
// GEMM2 via mma.sync + ldmatrix (split-bf16 x3), register LN epilogue
// ============================================================
#define OFF_BHI    0          // 256 x 256B = 65536
#define OFF_BLO    65536      // 65536
#define OFF_AG     131072     // 2 groups x (Ahi 16384 + Alo 16384) = 65536
#define OFF_W1     196608     // 11264
#define OFF_FS     207872     // 11264
#define OFF_B1     219136     // 512
#define OFF_B2     219648     // 1024
#define OFF_GO     220672     // 1024
#define OFF_BO     221696     // 1024
#define OFF_PS     222720     // 2 x 64 x 4 floats = 2048
#define OFF_PQ     224768     // 2048
#define SMEM_BYTES 226816

// XOR swizzle at 16B granularity; 256B per row
__device__ __forceinline__ uint32_t offA(uint32_t row, uint32_t kbyte){
    return row * 256u + (kbyte ^ ((row & 7u) << 4));
}

__global__ __launch_bounds__(512, 1) void mlp_kernel(
    const float* __restrict__ W1, const float* __restrict__ b1,
    const float* __restrict__ W2, const float* __restrict__ b2,
    const float* __restrict__ go, const float* __restrict__ bo,
    float* __restrict__ out, int nRows)
{
    extern __shared__ char smc[];
    const uint32_t sm32 = smem_u32(smc);
    float* W1s = (float*)(smc + OFF_W1);
    float* Fs  = (float*)(smc + OFF_FS);
    float* b1s = (float*)(smc + OFF_B1);
    float* b2s = (float*)(smc + OFF_B2);
    float* gos = (float*)(smc + OFF_GO);
    float* bos = (float*)(smc + OFF_BO);

    const int tid  = threadIdx.x;
    const int wid  = tid >> 5;
    const int lane = tid & 31;
    const int gid  = lane >> 2;   // 0..7
    const int tig  = lane & 3;    // 0..3

    const int g    = wid >> 3;    // warp group 0/1
    const int wg   = wid & 7;     // warp within group
    const int barid = 1 + g;

    // ---- one-time setup ----
    for (int i = tid; i < 22*128; i += 512) W1s[i] = W1[i];
    if (tid < 128) b1s[tid] = b1[tid];
    for (int i = tid; i < 256; i += 512) { b2s[i]=b2[i]; gos[i]=go[i]; bos[i]=bo[i]; }

    // W2 [k][n] -> B_T panels [n][kbyte] bf16, swizzled
    for (int i = tid; i < 128*256; i += 512) {
        int k = i >> 8, n = i & 255;
        float w = W2[i];
        __nv_bfloat16 hi = __float2bfloat16_rn(w);
        float rlo = w - __bfloat162float(hi);
        __nv_bfloat16 lo = __float2bfloat16_rn(rlo);
        uint32_t o = offA((uint32_t)n, (uint32_t)(2*k));
        *(__nv_bfloat16*)(smc + OFF_BHI + o) = hi;
        *(__nv_bfloat16*)(smc + OFF_BLO + o) = lo;
    }
    __syncthreads();

    const int c1 = lane * 4;              // GEMM1 cols (= GEMM2 k)
    float* Fw = Fs + wid * (8 * NFEAT);
    float* partS = (float*)(smc + OFF_PS) + g * 256;  // [64][4]
    float* partQ = (float*)(smc + OFF_PQ) + g * 256;

    const int mbg2 = wg & 1;              // 32-row half within 64-row tile
    const int nh4  = wg >> 1;             // 64-col quarter (0..3)
    const int nTiles = (nRows + GTM - 1) / GTM;

    // group A panel bases
    const uint32_t AG   = sm32 + OFF_AG + (uint32_t)g * 32768u;  // hi
    const char*    AGc  = smc  + OFF_AG + g * 32768;

    // ---- ldmatrix per-lane address invariants ----
    const uint32_t swz   = (uint32_t)(lane & 7) << 4;
    const uint32_t chA   = (uint32_t)((lane >> 4) & 1) * 16;
    const uint32_t rA    = (uint32_t)(mbg2 * 32 + (lane & 7) + ((lane >> 3) & 1) * 8);
    const uint32_t aB0   = AG + rA * 256;          // m-block 0
    const uint32_t aB1   = aB0 + 4096;             // m-block 1 (+16 rows)
    const uint32_t chB   = (uint32_t)((lane >> 3) & 1) * 16;
    const uint32_t bCst  = sm32 + OFF_BHI
                         + (uint32_t)(nh4 * 64 + (lane & 7)) * 256
                         + (uint32_t)((lane >> 4) & 1) * 2048;

    for (int tile = blockIdx.x * 2 + g; tile < nTiles; tile += 296) {
        const int rowBase = tile * GTM;
        const int wRow = rowBase + wg * 8;

        BARG(barid);   // prev iter's A reads + partial reads complete

        // ---- per-warp F staging (8 rows x 22) ----
        {
            const float* src = &g_F[(size_t)wRow * NFEAT];
            for (int i = lane; i < 8 * NFEAT; i += 32)
                Fw[i] = (wRow + i / NFEAT < nRows) ? src[i] : 0.0f;
        }
        __syncwarp();

        // ---- GEMM1 + bias + GELU -> split bf16 group A panels ----
        {
            float acc1[8][4];
            #pragma unroll
            for (int i = 0; i < 8; i++)
                #pragma unroll
                for (int j = 0; j < 4; j++) acc1[i][j] = 0.0f;
            #pragma unroll
            for (int k = 0; k < NFEAT; k++) {
                float4 w = *(const float4*)&W1s[k*128 + c1];
                #pragma unroll
                for (int i = 0; i < 8; i++) {
                    float a = Fw[i*NFEAT + k];
                    acc1[i][0] = fmaf(a, w.x, acc1[i][0]);
                    acc1[i][1] = fmaf(a, w.y, acc1[i][1]);
                    acc1[i][2] = fmaf(a, w.z, acc1[i][2]);
                    acc1[i][3] = fmaf(a, w.w, acc1[i][3]);
                }
            }
            float bv[4] = { b1s[c1], b1s[c1+1], b1s[c1+2], b1s[c1+3] };
            #pragma unroll
            for (int i = 0; i < 8; i++) {
                unsigned long long hp = 0, lp = 0;
                #pragma unroll
                for (int j = 0; j < 4; j++) {
                    float h = geluf(acc1[i][j] + bv[j]);
                    __nv_bfloat16 hb = __float2bfloat16_rn(h);
                    float rl = h - __bfloat162float(hb);
                    __nv_bfloat16 lb = __float2bfloat16_rn(rl);
                    hp |= (unsigned long long)__bfloat16_as_ushort(hb) << (16*j);
                    lp |= (unsigned long long)__bfloat16_as_ushort(lb) << (16*j);
                }
                uint32_t row = (uint32_t)(wg * 8 + i);
                uint32_t o = offA(row, (uint32_t)(lane * 8));
                *(unsigned long long*)(AGc + o) = hp;
                *(unsigned long long*)(AGc + 16384 + o) = lp;
            }
        }
        BARG(barid);

        // ---- GEMM2: warp = 32 rows (2 m-blocks) x 64 cols (8 n-blocks) ----
        float acc[2][8][4];
        #pragma unroll
        for (int m = 0; m < 2; m++)
            #pragma unroll
            for (int nb = 0; nb < 8; nb++)
                #pragma unroll
                for (int j = 0; j < 4; j++) acc[m][nb][j] = 0.0f;

        #pragma unroll
        for (int kb = 0; kb < 8; kb++) {
            const uint32_t kxA = ((uint32_t)(kb * 32) + chA) ^ swz;
            const uint32_t kxB = ((uint32_t)(kb * 32) + chB) ^ swz;

            uint32_t ah0[4], ah1[4], al0[4], al1[4];
            LDSM4(ah0, aB0 + kxA);
            LDSM4(ah1, aB1 + kxA);
            LDSM4(al0, aB0 + 16384u + kxA);
            LDSM4(al1, aB1 + 16384u + kxA);

            #pragma unroll
            for (int p = 0; p < 4; p++) {
                uint32_t bh[4], bl[4];
                uint32_t ba = bCst + (uint32_t)(p * 4096) + kxB;
                LDSM4(bh, ba);
                LDSM4(bl, ba + 65536u);
                mma16816(acc[0][2*p],   ah0, bh);
                mma16816(acc[0][2*p],   ah0, bl);
                mma16816(acc[0][2*p],   al0, bh);
                mma16816(acc[1][2*p],   ah1, bh);
                mma16816(acc[1][2*p],   ah1, bl);
                mma16816(acc[1][2*p],   al1, bh);
                mma16816(acc[0][2*p+1], ah0, bh + 2);
                mma16816(acc[0][2*p+1], ah0, bl + 2);
                mma16816(acc[0][2*p+1], al0, bh + 2);
                mma16816(acc[1][2*p+1], ah1, bh + 2);
                mma16816(acc[1][2*p+1], ah1, bl + 2);
                mma16816(acc[1][2*p+1], al1, bh + 2);
            }
        }

        // ---- epilogue: +b2, per-row LN partials via quad shuffles ----
        #pragma unroll
        for (int nb = 0; nb < 8; nb++) {
            int col = nh4 * 64 + nb * 8 + tig * 2;
            float bx = b2s[col], by = b2s[col + 1];
            #pragma unroll
            for (int m = 0; m < 2; m++) {
                acc[m][nb][0] += bx; acc[m][nb][1] += by;
                acc[m][nb][2] += bx; acc[m][nb][3] += by;
            }
        }
        #pragma unroll
        for (int m = 0; m < 2; m++) {
            float s0 = 0.f, q0 = 0.f, s1 = 0.f, q1 = 0.f;
            #pragma unroll
            for (int nb = 0; nb < 8; nb++) {
                s0 += acc[m][nb][0] + acc[m][nb][1];
                q0 = fmaf(acc[m][nb][0], acc[m][nb][0], q0);
                q0 = fmaf(acc[m][nb][1], acc[m][nb][1], q0);
                s1 += acc[m][nb][2] + acc[m][nb][3];
                q1 = fmaf(acc[m][nb][2], acc[m][nb][2], q1);
                q1 = fmaf(acc[m][nb][3], acc[m][nb][3], q1);
            }
            #pragma unroll
            for (int o = 1; o <= 2; o <<= 1) {
                s0 += __shfl_xor_sync(0xffffffffu, s0, o);
                q0 += __shfl_xor_sync(0xffffffffu, q0, o);
                s1 += __shfl_xor_sync(0xffffffffu, s1, o);
                q1 += __shfl_xor_sync(0xffffffffu, q1, o);
            }
            if (tig == 0) {
                int r = mbg2 * 32 + m * 16 + gid;
                partS[r*4 + nh4] = s0; partQ[r*4 + nh4] = q0;
                partS[(r+8)*4 + nh4] = s1; partQ[(r+8)*4 + nh4] = q1;
            }
        }
        BARG(barid);

        // ---- normalize + store ----
        #pragma unroll
        for (int m = 0; m < 2; m++) {
            #pragma unroll
            for (int half = 0; half < 2; half++) {
                int r = mbg2 * 32 + m * 16 + gid + half * 8;
                float4 S4 = *(float4*)&partS[r*4];
                float4 Q4 = *(float4*)&partQ[r*4];
                float sum = (S4.x + S4.y) + (S4.z + S4.w);
                float sq  = (Q4.x + Q4.y) + (Q4.z + Q4.w);
                float mu = sum * (1.0f/256.0f);
                float var = sq * (1.0f/256.0f) - mu * mu;
                float rs = rsqrtf(var + 1e-5f);
                int grow = rowBase + r;
                if (grow < nRows) {
                    float* op = out + (size_t)grow * 256;
                    #pragma unroll
                    for (int nb = 0; nb < 8; nb++) {
                        int col = nh4 * 64 + nb * 8 + tig * 2;
                        float va = acc[m][nb][half*2+0];
                        float vb = acc[m][nb][half*2+1];
                        float2 o2;
                        o2.x = fmaf((va - mu) * rs, gos[col],   bos[col]);
                        o2.y = fmaf((vb - mu) * rs, gos[col+1], bos[col+1]);
                        *(float2*)(op + col) = o2;
                    }
                }
            }
        }
    }
}

extern "C" void kernel_launch(void* const* d_in, const int* in_sizes, int n_in,
                              void* d_out, int out_size) {
    const float* x  = (const float*)d_in[0];
    const float* gm = (const float*)d_in[1];
    const float* bm = (const float*)d_in[2];
    const float* gs = (const float*)d_in[3];
    const float* bs = (const float*)d_in[4];
    const float* W1 = (const float*)d_in[5];
    const float* b1 = (const float*)d_in[6];
    const float* W2 = (const float*)d_in[7];
    const float* b2 = (const float*)d_in[8];
    const float* go = (const float*)d_in[9];
    const float* bo = (const float*)d_in[10];

    int B = in_sizes[0] / TLEN;
    int nRows = B * NP;

    cudaFuncSetAttribute(mlp_kernel, cudaFuncAttributeMaxDynamicSharedMemorySize,
                         SMEM_BYTES);

    feat_kernel<<<B, 256>>>(x, gm, bm, gs, bs);
    mlp_kernel<<<148, 512, SMEM_BYTES>>>(
        W1, b1, W2, b2, go, bo, (float*)d_out, nRows);
}

// round 12
// speedup vs baseline: 2.0303x; 1.0534x over previous
#include <cuda_runtime.h>
#include <cuda_bf16.h>
#include <cstdint>
#include <stdint.h>
#include <math.h>

#define TLEN    6000
#define NP      199
#define PLEN    60
#define PSTRIDE 30
#define NSP     30
#define NFREQ   16
#define NM      13
#define NS      9
#define NFEAT   22
#define GTM     32            // rows per group tile
#define NTHREADS 768
#define MAXROWS (1024*NP)

// 22-dim normalized feature rows (203776 x 22)
__device__ float g_F[(size_t)MAXROWS * NFEAT];

__device__ __forceinline__ float geluf(float v){
    return 0.5f * v * (1.0f + erff(v * 0.7071067811865476f));
}
__device__ __forceinline__ float freqf(int k){
    return (float)(((double)k * 200.0) / 30.0);
}
__device__ __forceinline__ uint32_t smem_u32(const void* p){
    uint32_t a;
    asm("{ .reg .u64 t; cvta.to.shared.u64 t, %1; cvt.u32.u64 %0, t; }"
        : "=r"(a) : "l"(p));
    return a;
}

// mma.sync m16n8k16 bf16 -> f32, accumulate in place
__device__ __forceinline__ void mma16816(float* d, const uint32_t* a,
                                         const uint32_t* b){
    asm volatile(
        "mma.sync.aligned.m16n8k16.row.col.f32.bf16.bf16.f32 "
        "{%0,%1,%2,%3}, {%4,%5,%6,%7}, {%8,%9}, {%0,%1,%2,%3};"
        : "+f"(d[0]), "+f"(d[1]), "+f"(d[2]), "+f"(d[3])
        : "r"(a[0]), "r"(a[1]), "r"(a[2]), "r"(a[3]), "r"(b[0]), "r"(b[1]));
}
#define LDSM4(R, addr) \
    asm volatile("ldmatrix.sync.aligned.m8n8.x4.shared.b16 {%0,%1,%2,%3}, [%4];" \
        : "=r"((R)[0]), "=r"((R)[1]), "=r"((R)[2]), "=r"((R)[3]) : "r"(addr))
#define BARG(id) \
    asm volatile("bar.sync %0, 256;" :: "r"(id) : "memory")

// ============================================================
// Kernel A: per-patch features + group layernorms -> g_F
// (unchanged 75us version)
// ============================================================
__global__ __launch_bounds__(256) void feat_kernel(
    const float* __restrict__ x,
    const float* __restrict__ gm, const float* __restrict__ bm,
    const float* __restrict__ gs, const float* __restrict__ bs)
{
    __shared__ float sx[TLEN];
    __shared__ float cosT[NFREQ * 16];
    __shared__ float sinT[NFREQ * 16];
    __shared__ float hannS[NSP];
    __shared__ float psdS[NFREQ * 200];

    const int tid = threadIdx.x;
    {
        const float4* xg = (const float4*)(x + (size_t)blockIdx.x * TLEN);
        float4* s4 = (float4*)sx;
        for (int i = tid; i < TLEN/4; i += 256) s4[i] = xg[i];
    }
    for (int i = tid; i < NFREQ*16; i += 256) {
        int k = i >> 4, t = i & 15;
        double sv, cv;
        sincospi(2.0 * (double)(k * t) / 30.0, &sv, &cv);
        cosT[i] = (float)cv;
        sinT[i] = (float)sv;
    }
    if (tid < NSP)
        hannS[tid] = (float)(0.5 * (1.0 - cospi(2.0 * (double)tid / 30.0)));
    __syncthreads();
    if (tid >= NP) return;

    const int off = tid * PSTRIDE;
    float* frow = &g_F[((size_t)blockIdx.x * NP + tid) * NFEAT];

    float v0 = sx[off];
    float mx = v0, mn = v0, sum = v0;
    float sumsq = v0 * v0;
    float amax = fabsf(v0); int aidx = 0;
    float prev = v0;
    float tsg = v0 + 1e-10f;
    int   sprev = (tsg > 0.0f) - (tsg < 0.0f);
    float dmax = -INFINITY, dmin = INFINITY, dabs = 0.0f;
    int zc = 0;
    #pragma unroll
    for (int t = 1; t < PLEN; t++) {
        float v = sx[off + t];
        mx = fmaxf(mx, v); mn = fminf(mn, v);
        sum += v; sumsq = fmaf(v, v, sumsq);
        float a = fabsf(v);
        if (a > amax) { amax = a; aidx = t; }
        float d = v - prev;
        dmax = fmaxf(dmax, d); dmin = fminf(dmin, d); dabs += fabsf(d);
        float tg = v + 1e-10f;
        int sg = (tg > 0.0f) - (tg < 0.0f);
        zc += (sg != sprev);
        sprev = sg; prev = v;
    }
    float mean = sum * (1.0f/60.0f);

    float m2 = 0.f, m3 = 0.f, m4 = 0.f;
    #pragma unroll
    for (int t = 0; t < PLEN; t++) {
        float c = sx[off + t] - mean;
        float c2 = c * c;
        m2 += c2; m3 = fmaf(c2, c, m3); m4 = fmaf(c2, c2, m4);
    }
    m2 *= (1.0f/60.0f); m3 *= (1.0f/60.0f); m4 *= (1.0f/60.0f);
    float stdv = sqrtf(m2);

    {
        float morph[NM];
        morph[0] = mx; morph[1] = mn; morph[2] = mx - mn; morph[3] = mean;
        morph[4] = stdv;
        morph[5] = (float)aidx * (1.0f/60.0f);
        morph[6] = dmax; morph[7] = dmin;
        morph[8] = dabs * (1.0f/59.0f);
        morph[9] = (float)zc * (1.0f/60.0f);
        morph[10] = sumsq;
        morph[11] = m4 / (m2 * m2) - 3.0f;
        morph[12] = m3 / (m2 * stdv);
        #pragma unroll
        for (int i = 0; i < NM; i++) if (!isfinite(morph[i])) morph[i] = 0.0f;

        float mu = 0.f;
        #pragma unroll
        for (int i = 0; i < NM; i++) mu += morph[i];
        mu *= (1.0f/13.0f);
        float var = 0.f;
        #pragma unroll
        for (int i = 0; i < NM; i++) { float d = morph[i]-mu; var = fmaf(d,d,var); }
        var *= (1.0f/13.0f);
        float scl = rsqrtf(var + 1e-5f);
        #pragma unroll
        for (int i = 0; i < NM; i++)
            frow[i] = fmaf((morph[i]-mu)*scl, gm[i], bm[i]);
    }

    float ye0[16], yo0[15], ye1[16], yo1[15], ye2[16], yo2[15];

    #define FOLD_SEG(YE, YO, SB) { \
        float s = 0.f; \
        _Pragma("unroll") \
        for (int t = 0; t < NSP; t++) s += sx[(SB) + t]; \
        s *= (1.0f/30.0f); \
        float s2 = 2.0f * s; \
        _Pragma("unroll") \
        for (int t = 1; t < 15; t++) { \
            float a = sx[(SB) + t]; \
            float b = sx[(SB) + 30 - t]; \
            float w = hannS[t]; \
            YE[t] = (a + b - s2) * w; \
            YO[t] = (a - b) * w; \
        } \
        YE[15] = sx[(SB) + 15] - s; \
    }

    FOLD_SEG(ye0, yo0, off)
    FOLD_SEG(ye1, yo1, off + 15)
    FOLD_SEG(ye2, yo2, off + 30)
    #undef FOLD_SEG

    for (int k = 0; k < NFREQ; k++) {
        const float* ck = &cosT[k * 16];
        const float* sk = &sinT[k * 16];
        float re0 = 0.f, im0 = 0.f, re1 = 0.f, im1 = 0.f, re2 = 0.f, im2 = 0.f;
        #pragma unroll
        for (int t = 1; t < 15; t++) {
            float c = ck[t], si = sk[t];
            re0 = fmaf(ye0[t], c, re0); im0 = fmaf(yo0[t], si, im0);
            re1 = fmaf(ye1[t], c, re1); im1 = fmaf(yo1[t], si, im1);
            re2 = fmaf(ye2[t], c, re2); im2 = fmaf(yo2[t], si, im2);
        }
        float c15 = ck[15];
        re0 = fmaf(ye0[15], c15, re0);
        re1 = fmaf(ye1[15], c15, re1);
        re2 = fmaf(ye2[15], c15, re2);
        float p = fmaf(re0,re0,im0*im0) + fmaf(re1,re1,im1*im1) + fmaf(re2,re2,im2*im2);
        float sc = (k == 0 || k == NFREQ-1) ? (1.0f/6750.0f) : (2.0f/6750.0f);
        psdS[k*200 + tid] = p * sc;
    }

    float psd[NFREQ];
    #pragma unroll
    for (int k = 0; k < NFREQ; k++) psd[k] = psdS[k*200 + tid];

    float total = 0.f;
    #pragma unroll
    for (int k = 0; k < NFREQ; k++) total += psd[k];
    total += 1e-12f;
    float inv = 1.0f / total;

    float b1v = psd[1];
    float b3v = psd[2] + psd[3] + psd[4];
    float b4v = 0.f;
    #pragma unroll
    for (int k = 5; k <= 14; k++) b4v += psd[k];

    float pmax = psd[0]; int pkk = 0;
    #pragma unroll
    for (int k = 1; k < NFREQ; k++)
        if (psd[k] > pmax) { pmax = psd[k]; pkk = k; }

    float thr = 0.95f * total;
    float csum = 0.f; int ek = 0; bool fnd = false;
    #pragma unroll
    for (int k = 0; k < NFREQ; k++) {
        csum += psd[k];
        if (!fnd && csum >= thr) { ek = k; fnd = true; }
    }
    float ent = 0.f;
    #pragma unroll
    for (int k = 0; k < NFREQ; k++) {
        float pn = psd[k] * inv;
        ent -= pn * log2f(pn + 1e-12f);
    }

    float spec[NS];
    spec[0] = 0.0f;
    spec[1] = b1v * inv;
    spec[2] = 0.0f;
    spec[3] = b3v * inv;
    spec[4] = b4v * inv;
    spec[5] = freqf(pkk);
    spec[6] = freqf(ek);
    spec[7] = ent;
    spec[8] = total;
    #pragma unroll
    for (int i = 0; i < NS; i++) if (!isfinite(spec[i])) spec[i] = 0.0f;

    {
        float mu = 0.f;
        #pragma unroll
        for (int i = 0; i < NS; i++) mu += spec[i];
        mu *= (1.0f/9.0f);
        float var = 0.f;
        #pragma unroll
        for (int i = 0; i < NS; i++) { float d = spec[i]-mu; var = fmaf(d,d,var); }
        var *= (1.0f/9.0f);
        float scl = rsqrtf(var + 1e-5f);
        #pragma unroll
        for (int i = 0; i < NS; i++)
            frow[NM + i] = fmaf((spec[i]-mu)*scl, gs[i], bs[i]);
    }
}

// ============================================================
// Kernel B: persistent MLP, 3 staggered warp-groups x 32-row tiles
// 768 threads (occ 37.5%), warp tile 16x64
// GEMM2 via mma.sync + ldmatrix (split-bf16 x3), register LN epilogue
// ============================================================
#define OFF_BHI    0          // 65536
#define OFF_BLO    65536      // 65536
#define OFF_AG     131072     // 3 groups x (Ahi 8192 + Alo 8192) = 49152
#define OFF_W1     180224     // 11264
#define OFF_FS     191488     // 24 warps x 4 rows x 22 floats = 8448
#define OFF_B1     199936     // 512
#define OFF_B2     200448     // 1024
#define OFF_GO     201472     // 1024
#define OFF_BO     202496     // 1024
#define OFF_PS     203520     // 3 x 32 x 4 floats = 1536
#define OFF_PQ     205056     // 1536
#define SMEM_BYTES 206592

// XOR swizzle at 16B granularity; 256B per row
__device__ __forceinline__ uint32_t offA(uint32_t row, uint32_t kbyte){
    return row * 256u + (kbyte ^ ((row & 7u) << 4));
}

__global__ __launch_bounds__(NTHREADS, 1) void mlp_kernel(
    const float* __restrict__ W1, const float* __restrict__ b1,
    const float* __restrict__ W2, const float* __restrict__ b2,
    const float* __restrict__ go, const float* __restrict__ bo,
    float* __restrict__ out, int nRows)
{
    extern __shared__ char smc[];
    const uint32_t sm32 = smem_u32(smc);
    float* W1s = (float*)(smc + OFF_W1);
    float* Fs  = (float*)(smc + OFF_FS);
    float* b1s = (float*)(smc + OFF_B1);
    float* b2s = (float*)(smc + OFF_B2);
    float* gos = (float*)(smc + OFF_GO);
    float* bos = (float*)(smc + OFF_BO);

    const int tid  = threadIdx.x;
    const int wid  = tid >> 5;
    const int lane = tid & 31;
    const int gid  = lane >> 2;   // 0..7
    const int tig  = lane & 3;    // 0..3

    const int g    = wid >> 3;    // warp group 0/1/2
    const int wg   = wid & 7;     // warp within group
    const int barid = 1 + g;

    // ---- one-time setup ----
    for (int i = tid; i < 22*128; i += NTHREADS) W1s[i] = W1[i];
    if (tid < 128) b1s[tid] = b1[tid];
    for (int i = tid; i < 256; i += NTHREADS) { b2s[i]=b2[i]; gos[i]=go[i]; bos[i]=bo[i]; }

    // W2 [k][n] -> B_T panels [n][kbyte] bf16, swizzled
    for (int i = tid; i < 128*256; i += NTHREADS) {
        int k = i >> 8, n = i & 255;
        float w = W2[i];
        __nv_bfloat16 hi = __float2bfloat16_rn(w);
        float rlo = w - __bfloat162float(hi);
        __nv_bfloat16 lo = __float2bfloat16_rn(rlo);
        uint32_t o = offA((uint32_t)n, (uint32_t)(2*k));
        *(__nv_bfloat16*)(smc + OFF_BHI + o) = hi;
        *(__nv_bfloat16*)(smc + OFF_BLO + o) = lo;
    }
    __syncthreads();

    const int c1 = lane * 4;              // GEMM1 cols (= GEMM2 k)
    float* Fw = Fs + wid * (4 * NFEAT);
    float* partS = (float*)(smc + OFF_PS) + g * 128;  // [32][4]
    float* partQ = (float*)(smc + OFF_PQ) + g * 128;

    const int mw = wg & 1;                // 16-row half within 32-row tile
    const int nw = wg >> 1;               // 64-col quarter (0..3)
    const int nTiles = (nRows + GTM - 1) / GTM;   // 6368

    // group A panel bases (hi at +0, lo at +8192)
    const char* AGc = smc + OFF_AG + g * 16384;
    const uint32_t AG = sm32 + OFF_AG + (uint32_t)g * 16384u;

    // ---- ldmatrix per-lane address invariants ----
    const uint32_t swz  = (uint32_t)(lane & 7) << 4;
    const uint32_t chA  = (uint32_t)((lane >> 4) & 1) * 16;
    const uint32_t rA   = (uint32_t)(mw * 16 + (lane & 7) + ((lane >> 3) & 1) * 8);
    const uint32_t aB0  = AG + rA * 256;
    const uint32_t chB  = (uint32_t)((lane >> 3) & 1) * 16;
    const uint32_t bCst = sm32 + OFF_BHI
                        + (uint32_t)(nw * 64 + (lane & 7)) * 256
                        + (uint32_t)((lane >> 4) & 1) * 2048;

    for (int tile = blockIdx.x * 3 + g; tile < nTiles; tile += 444) {
        const int rowBase = tile * GTM;
        const int wRow = rowBase + wg * 4;

        BARG(barid);   // prev iter's A reads + partial reads complete

        // ---- per-warp F staging (4 rows x 22) ----
        {
            const float* src = &g_F[(size_t)wRow * NFEAT];
            for (int i = lane; i < 4 * NFEAT; i += 32)
                Fw[i] = (wRow + i / NFEAT < nRows) ? src[i] : 0.0f;
        }
        __syncwarp();

        // ---- GEMM1 + bias + GELU -> split bf16 group A panel ----
        {
            float acc1[4][4];
            #pragma unroll
            for (int i = 0; i < 4; i++)
                #pragma unroll
                for (int j = 0; j < 4; j++) acc1[i][j] = 0.0f;
            #pragma unroll
            for (int k = 0; k < NFEAT; k++) {
                float4 w = *(const float4*)&W1s[k*128 + c1];
                #pragma unroll
                for (int i = 0; i < 4; i++) {
                    float a = Fw[i*NFEAT + k];
                    acc1[i][0] = fmaf(a, w.x, acc1[i][0]);
                    acc1[i][1] = fmaf(a, w.y, acc1[i][1]);
                    acc1[i][2] = fmaf(a, w.z, acc1[i][2]);
                    acc1[i][3] = fmaf(a, w.w, acc1[i][3]);
                }
            }
            float bv[4] = { b1s[c1], b1s[c1+1], b1s[c1+2], b1s[c1+3] };
            #pragma unroll
            for (int i = 0; i < 4; i++) {
                unsigned long long hp = 0, lp = 0;
                #pragma unroll
                for (int j = 0; j < 4; j++) {
                    float h = geluf(acc1[i][j] + bv[j]);
                    __nv_bfloat16 hb = __float2bfloat16_rn(h);
                    float rl = h - __bfloat162float(hb);
                    __nv_bfloat16 lb = __float2bfloat16_rn(rl);
                    hp |= (unsigned long long)__bfloat16_as_ushort(hb) << (16*j);
                    lp |= (unsigned long long)__bfloat16_as_ushort(lb) << (16*j);
                }
                uint32_t row = (uint32_t)(wg * 4 + i);
                uint32_t o = offA(row, (uint32_t)(lane * 8));
                *(unsigned long long*)(AGc + o) = hp;
                *(unsigned long long*)(AGc + 8192 + o) = lp;
            }
        }
        BARG(barid);

        // ---- GEMM2: warp = 16 rows (1 m-block) x 64 cols (8 n-blocks) ----
        float acc[8][4];
        #pragma unroll
        for (int nb = 0; nb < 8; nb++)
            #pragma unroll
            for (int j = 0; j < 4; j++) acc[nb][j] = 0.0f;

        #pragma unroll
        for (int kb = 0; kb < 8; kb++) {
            const uint32_t kxA = ((uint32_t)(kb * 32) + chA) ^ swz;
            const uint32_t kxB = ((uint32_t)(kb * 32) + chB) ^ swz;

            uint32_t ah[4], al[4];
            LDSM4(ah, aB0 + kxA);
            LDSM4(al, aB0 + 8192u + kxA);

            #pragma unroll
            for (int p = 0; p < 4; p++) {
                uint32_t bh[4], bl[4];
                uint32_t ba = bCst + (uint32_t)(p * 4096) + kxB;
                LDSM4(bh, ba);
                LDSM4(bl, ba + 65536u);
                mma16816(acc[2*p],   ah, bh);
                mma16816(acc[2*p],   ah, bl);
                mma16816(acc[2*p],   al, bh);
                mma16816(acc[2*p+1], ah, bh + 2);
                mma16816(acc[2*p+1], ah, bl + 2);
                mma16816(acc[2*p+1], al, bh + 2);
            }
        }

        // ---- epilogue: +b2, per-row LN partials via quad shuffles ----
        #pragma unroll
        for (int nb = 0; nb < 8; nb++) {
            int col = nw * 64 + nb * 8 + tig * 2;
            float bx = b2s[col], by = b2s[col + 1];
            acc[nb][0] += bx; acc[nb][1] += by;
            acc[nb][2] += bx; acc[nb][3] += by;
        }
        {
            float s0 = 0.f, q0 = 0.f, s1 = 0.f, q1 = 0.f;
            #pragma unroll
            for (int nb = 0; nb < 8; nb++) {
                s0 += acc[nb][0] + acc[nb][1];
                q0 = fmaf(acc[nb][0], acc[nb][0], q0);
                q0 = fmaf(acc[nb][1], acc[nb][1], q0);
                s1 += acc[nb][2] + acc[nb][3];
                q1 = fmaf(acc[nb][2], acc[nb][2], q1);
                q1 = fmaf(acc[nb][3], acc[nb][3], q1);
            }
            #pragma unroll
            for (int o = 1; o <= 2; o <<= 1) {
                s0 += __shfl_xor_sync(0xffffffffu, s0, o);
                q0 += __shfl_xor_sync(0xffffffffu, q0, o);
                s1 += __shfl_xor_sync(0xffffffffu, s1, o);
                q1 += __shfl_xor_sync(0xffffffffu, q1, o);
            }
            if (tig == 0) {
                int r = mw * 16 + gid;
                partS[r*4 + nw] = s0; partQ[r*4 + nw] = q0;
                partS[(r+8)*4 + nw] = s1; partQ[(r+8)*4 + nw] = q1;
            }
        }
        BARG(barid);

        // ---- normalize + store ----
        #pragma unroll
        for (int half = 0; half < 2; half++) {
            int r = mw * 16 + gid + half * 8;
            float4 S4 = *(float4*)&partS[r*4];
            float4 Q4 = *(float4*)&partQ[r*4];
            float sum = (S4.x + S4.y) + (S4.z + S4.w);
            float sq  = (Q4.x + Q4.y) + (Q4.z + Q4.w);
            float mu = sum * (1.0f/256.0f);
            float var = sq * (1.0f/256.0f) - mu * mu;
            float rs = rsqrtf(var + 1e-5f);
            int grow = rowBase + r;
            if (grow < nRows) {
                float* op = out + (size_t)grow * 256;
                #pragma unroll
                for (int nb = 0; nb < 8; nb++) {
                    int col = nw * 64 + nb * 8 + tig * 2;
                    float va = acc[nb][half*2+0];
                    float vb = acc[nb][half*2+1];
                    float2 o2;
                    o2.x = fmaf((va - mu) * rs, gos[col],   bos[col]);
                    o2.y = fmaf((vb - mu) * rs, gos[col+1], bos[col+1]);
                    *(float2*)(op + col) = o2;
                }
            }
        }
    }
}

extern "C" void kernel_launch(void* const* d_in, const int* in_sizes, int n_in,
                              void* d_out, int out_size) {
    const float* x  = (const float*)d_in[0];
    const float* gm = (const float*)d_in[1];
    const float* bm = (const float*)d_in[2];
    const float* gs = (const float*)d_in[3];
    const float* bs = (const float*)d_in[4];
    const float* W1 = (const float*)d_in[5];
    const float* b1 = (const float*)d_in[6];
    const float* W2 = (const float*)d_in[7];
    const float* b2 = (const float*)d_in[8];
    const float* go = (const float*)d_in[9];
    const float* bo = (const float*)d_in[10];

    int B = in_sizes[0] / TLEN;
    int nRows = B * NP;

    cudaFuncSetAttribute(mlp_kernel, cudaFuncAttributeMaxDynamicSharedMemorySize,
                         SMEM_BYTES);

    feat_kernel<<<B, 256>>>(x, gm, bm, gs, bs);
    mlp_kernel<<<148, NTHREADS, SMEM_BYTES>>>(
        W1, b1, W2, b2, go, bo, (float*)d_out, nRows);
}

// round 13
// speedup vs baseline: 2.2500x; 1.1082x over previous
#include <cuda_runtime.h>
#include <cuda_fp16.h>
#include <cstdint>
#include <stdint.h>
#include <math.h>

#define TLEN    6000
#define NP      199
#define PLEN    60
#define PSTRIDE 30
#define NSP     30
#define NFREQ   16
#define NM      13
#define NS      9
#define NFEAT   22
#define GTM     32            // rows per group tile
#define NTHREADS 768
#define MAXROWS (1024*NP)

// 22-dim normalized feature rows (203776 x 22)
__device__ float g_F[(size_t)MAXROWS * NFEAT];

__device__ __forceinline__ float geluf(float v){
    return 0.5f * v * (1.0f + erff(v * 0.7071067811865476f));
}
__device__ __forceinline__ float freqf(int k){
    return (float)(((double)k * 200.0) / 30.0);
}
__device__ __forceinline__ uint32_t smem_u32(const void* p){
    uint32_t a;
    asm("{ .reg .u64 t; cvta.to.shared.u64 t, %1; cvt.u32.u64 %0, t; }"
        : "=r"(a) : "l"(p));
    return a;
}

// mma.sync m16n8k16 fp16 -> f32, accumulate in place
__device__ __forceinline__ void mma16816(float* d, const uint32_t* a,
                                         const uint32_t* b){
    asm volatile(
        "mma.sync.aligned.m16n8k16.row.col.f32.f16.f16.f32 "
        "{%0,%1,%2,%3}, {%4,%5,%6,%7}, {%8,%9}, {%0,%1,%2,%3};"
        : "+f"(d[0]), "+f"(d[1]), "+f"(d[2]), "+f"(d[3])
        : "r"(a[0]), "r"(a[1]), "r"(a[2]), "r"(a[3]), "r"(b[0]), "r"(b[1]));
}
#define LDSM4(R, addr) \
    asm volatile("ldmatrix.sync.aligned.m8n8.x4.shared.b16 {%0,%1,%2,%3}, [%4];" \
        : "=r"((R)[0]), "=r"((R)[1]), "=r"((R)[2]), "=r"((R)[3]) : "r"(addr))
#define BARG(id) \
    asm volatile("bar.sync %0, 256;" :: "r"(id) : "memory")

// ============================================================
// Kernel A: per-patch features + group layernorms -> g_F
// (unchanged 75us version)
// ============================================================
__global__ __launch_bounds__(256) void feat_kernel(
    const float* __restrict__ x,
    const float* __restrict__ gm, const float* __restrict__ bm,
    const float* __restrict__ gs, const float* __restrict__ bs)
{
    __shared__ float sx[TLEN];
    __shared__ float cosT[NFREQ * 16];
    __shared__ float sinT[NFREQ * 16];
    __shared__ float hannS[NSP];
    __shared__ float psdS[NFREQ * 200];

    const int tid = threadIdx.x;
    {
        const float4* xg = (const float4*)(x + (size_t)blockIdx.x * TLEN);
        float4* s4 = (float4*)sx;
        for (int i = tid; i < TLEN/4; i += 256) s4[i] = xg[i];
    }
    for (int i = tid; i < NFREQ*16; i += 256) {
        int k = i >> 4, t = i & 15;
        double sv, cv;
        sincospi(2.0 * (double)(k * t) / 30.0, &sv, &cv);
        cosT[i] = (float)cv;
        sinT[i] = (float)sv;
    }
    if (tid < NSP)
        hannS[tid] = (float)(0.5 * (1.0 - cospi(2.0 * (double)tid / 30.0)));
    __syncthreads();
    if (tid >= NP) return;

    const int off = tid * PSTRIDE;
    float* frow = &g_F[((size_t)blockIdx.x * NP + tid) * NFEAT];

    float v0 = sx[off];
    float mx = v0, mn = v0, sum = v0;
    float sumsq = v0 * v0;
    float amax = fabsf(v0); int aidx = 0;
    float prev = v0;
    float tsg = v0 + 1e-10f;
    int   sprev = (tsg > 0.0f) - (tsg < 0.0f);
    float dmax = -INFINITY, dmin = INFINITY, dabs = 0.0f;
    int zc = 0;
    #pragma unroll
    for (int t = 1; t < PLEN; t++) {
        float v = sx[off + t];
        mx = fmaxf(mx, v); mn = fminf(mn, v);
        sum += v; sumsq = fmaf(v, v, sumsq);
        float a = fabsf(v);
        if (a > amax) { amax = a; aidx = t; }
        float d = v - prev;
        dmax = fmaxf(dmax, d); dmin = fminf(dmin, d); dabs += fabsf(d);
        float tg = v + 1e-10f;
        int sg = (tg > 0.0f) - (tg < 0.0f);
        zc += (sg != sprev);
        sprev = sg; prev = v;
    }
    float mean = sum * (1.0f/60.0f);

    float m2 = 0.f, m3 = 0.f, m4 = 0.f;
    #pragma unroll
    for (int t = 0; t < PLEN; t++) {
        float c = sx[off + t] - mean;
        float c2 = c * c;
        m2 += c2; m3 = fmaf(c2, c, m3); m4 = fmaf(c2, c2, m4);
    }
    m2 *= (1.0f/60.0f); m3 *= (1.0f/60.0f); m4 *= (1.0f/60.0f);
    float stdv = sqrtf(m2);

    {
        float morph[NM];
        morph[0] = mx; morph[1] = mn; morph[2] = mx - mn; morph[3] = mean;
        morph[4] = stdv;
        morph[5] = (float)aidx * (1.0f/60.0f);
        morph[6] = dmax; morph[7] = dmin;
        morph[8] = dabs * (1.0f/59.0f);
        morph[9] = (float)zc * (1.0f/60.0f);
        morph[10] = sumsq;
        morph[11] = m4 / (m2 * m2) - 3.0f;
        morph[12] = m3 / (m2 * stdv);
        #pragma unroll
        for (int i = 0; i < NM; i++) if (!isfinite(morph[i])) morph[i] = 0.0f;

        float mu = 0.f;
        #pragma unroll
        for (int i = 0; i < NM; i++) mu += morph[i];
        mu *= (1.0f/13.0f);
        float var = 0.f;
        #pragma unroll
        for (int i = 0; i < NM; i++) { float d = morph[i]-mu; var = fmaf(d,d,var); }
        var *= (1.0f/13.0f);
        float scl = rsqrtf(var + 1e-5f);
        #pragma unroll
        for (int i = 0; i < NM; i++)
            frow[i] = fmaf((morph[i]-mu)*scl, gm[i], bm[i]);
    }

    float ye0[16], yo0[15], ye1[16], yo1[15], ye2[16], yo2[15];

    #define FOLD_SEG(YE, YO, SB) { \
        float s = 0.f; \
        _Pragma("unroll") \
        for (int t = 0; t < NSP; t++) s += sx[(SB) + t]; \
        s *= (1.0f/30.0f); \
        float s2 = 2.0f * s; \
        _Pragma("unroll") \
        for (int t = 1; t < 15; t++) { \
            float a = sx[(SB) + t]; \
            float b = sx[(SB) + 30 - t]; \
            float w = hannS[t]; \
            YE[t] = (a + b - s2) * w; \
            YO[t] = (a - b) * w; \
        } \
        YE[15] = sx[(SB) + 15] - s; \
    }

    FOLD_SEG(ye0, yo0, off)
    FOLD_SEG(ye1, yo1, off + 15)
    FOLD_SEG(ye2, yo2, off + 30)
    #undef FOLD_SEG

    for (int k = 0; k < NFREQ; k++) {
        const float* ck = &cosT[k * 16];
        const float* sk = &sinT[k * 16];
        float re0 = 0.f, im0 = 0.f, re1 = 0.f, im1 = 0.f, re2 = 0.f, im2 = 0.f;
        #pragma unroll
        for (int t = 1; t < 15; t++) {
            float c = ck[t], si = sk[t];
            re0 = fmaf(ye0[t], c, re0); im0 = fmaf(yo0[t], si, im0);
            re1 = fmaf(ye1[t], c, re1); im1 = fmaf(yo1[t], si, im1);
            re2 = fmaf(ye2[t], c, re2); im2 = fmaf(yo2[t], si, im2);
        }
        float c15 = ck[15];
        re0 = fmaf(ye0[15], c15, re0);
        re1 = fmaf(ye1[15], c15, re1);
        re2 = fmaf(ye2[15], c15, re2);
        float p = fmaf(re0,re0,im0*im0) + fmaf(re1,re1,im1*im1) + fmaf(re2,re2,im2*im2);
        float sc = (k == 0 || k == NFREQ-1) ? (1.0f/6750.0f) : (2.0f/6750.0f);
        psdS[k*200 + tid] = p * sc;
    }

    float psd[NFREQ];
    #pragma unroll
    for (int k = 0; k < NFREQ; k++) psd[k] = psdS[k*200 + tid];

    float total = 0.f;
    #pragma unroll
    for (int k = 0; k < NFREQ; k++) total += psd[k];
    total += 1e-12f;
    float inv = 1.0f / total;

    float b1v = psd[1];
    float b3v = psd[2] + psd[3] + psd[4];
    float b4v = 0.f;
    #pragma unroll
    for (int k = 5; k <= 14; k++) b4v += psd[k];

    float pmax = psd[0]; int pkk = 0;
    #pragma unroll
    for (int k = 1; k < NFREQ; k++)
        if (psd[k] > pmax) { pmax = psd[k]; pkk = k; }

    float thr = 0.95f * total;
    float csum = 0.f; int ek = 0; bool fnd = false;
    #pragma unroll
    for (int k = 0; k < NFREQ; k++) {
        csum += psd[k];
        if (!fnd && csum >= thr) { ek = k; fnd = true; }
    }
    float ent = 0.f;
    #pragma unroll
    for (int k = 0; k < NFREQ; k++) {
        float pn = psd[k] * inv;
        ent -= pn * log2f(pn + 1e-12f);
    }

    float spec[NS];
    spec[0] = 0.0f;
    spec[1] = b1v * inv;
    spec[2] = 0.0f;
    spec[3] = b3v * inv;
    spec[4] = b4v * inv;
    spec[5] = freqf(pkk);
    spec[6] = freqf(ek);
    spec[7] = ent;
    spec[8] = total;
    #pragma unroll
    for (int i = 0; i < NS; i++) if (!isfinite(spec[i])) spec[i] = 0.0f;

    {
        float mu = 0.f;
        #pragma unroll
        for (int i = 0; i < NS; i++) mu += spec[i];
        mu *= (1.0f/9.0f);
        float var = 0.f;
        #pragma unroll
        for (int i = 0; i < NS; i++) { float d = spec[i]-mu; var = fmaf(d,d,var); }
        var *= (1.0f/9.0f);
        float scl = rsqrtf(var + 1e-5f);
        #pragma unroll
        for (int i = 0; i < NS; i++)
            frow[NM + i] = fmaf((spec[i]-mu)*scl, gs[i], bs[i]);
    }
}

// ============================================================
// Kernel B: persistent MLP, 3 staggered warp-groups x 32-row tiles
// fp16 split-A x2 MMA (B single fp16 panel), register LN epilogue
// ============================================================
#define OFF_B      0          // 65536
#define OFF_AG     65536      // 3 groups x (Ahi 8192 + Alo 8192) = 49152
#define OFF_W1     114688     // 11264
#define OFF_FS     125952     // 8448
#define OFF_B1     134400     // 512
#define OFF_B2     134912     // 1024
#define OFF_GO     135936     // 1024
#define OFF_BO     136960     // 1024
#define OFF_PS     137984     // 1536
#define OFF_PQ     139520     // 1536
#define SMEM_BYTES 141056

// XOR swizzle at 16B granularity; 256B per row
__device__ __forceinline__ uint32_t offA(uint32_t row, uint32_t kbyte){
    return row * 256u + (kbyte ^ ((row & 7u) << 4));
}

__global__ __launch_bounds__(NTHREADS, 1) void mlp_kernel(
    const float* __restrict__ W1, const float* __restrict__ b1,
    const float* __restrict__ W2, const float* __restrict__ b2,
    const float* __restrict__ go, const float* __restrict__ bo,
    float* __restrict__ out, int nRows)
{
    extern __shared__ char smc[];
    const uint32_t sm32 = smem_u32(smc);
    float* W1s = (float*)(smc + OFF_W1);
    float* Fs  = (float*)(smc + OFF_FS);
    float* b1s = (float*)(smc + OFF_B1);
    float* b2s = (float*)(smc + OFF_B2);
    float* gos = (float*)(smc + OFF_GO);
    float* bos = (float*)(smc + OFF_BO);

    const int tid  = threadIdx.x;
    const int wid  = tid >> 5;
    const int lane = tid & 31;
    const int gid  = lane >> 2;   // 0..7
    const int tig  = lane & 3;    // 0..3

    const int g    = wid >> 3;    // warp group 0/1/2
    const int wg   = wid & 7;     // warp within group
    const int barid = 1 + g;

    // ---- one-time setup ----
    for (int i = tid; i < 22*128; i += NTHREADS) W1s[i] = W1[i];
    if (tid < 128) b1s[tid] = b1[tid];
    for (int i = tid; i < 256; i += NTHREADS) { b2s[i]=b2[i]; gos[i]=go[i]; bos[i]=bo[i]; }

    // W2 [k][n] -> B_T panel [n][kbyte] fp16, swizzled
    for (int i = tid; i < 128*256; i += NTHREADS) {
        int k = i >> 8, n = i & 255;
        uint32_t o = offA((uint32_t)n, (uint32_t)(2*k));
        *(__half*)(smc + OFF_B + o) = __float2half_rn(W2[i]);
    }
    __syncthreads();

    const int c1 = lane * 4;              // GEMM1 cols (= GEMM2 k)
    float* Fw = Fs + wid * (4 * NFEAT);
    float* partS = (float*)(smc + OFF_PS) + g * 128;  // [32][4]
    float* partQ = (float*)(smc + OFF_PQ) + g * 128;

    const int mw = wg & 1;                // 16-row half within 32-row tile
    const int nw = wg >> 1;               // 64-col quarter (0..3)
    const int nTiles = (nRows + GTM - 1) / GTM;   // 6368

    // group A panel bases (hi at +0, lo at +8192)
    const char* AGc = smc + OFF_AG + g * 16384;
    const uint32_t AG = sm32 + OFF_AG + (uint32_t)g * 16384u;

    // ---- ldmatrix per-lane address invariants ----
    const uint32_t swz  = (uint32_t)(lane & 7) << 4;
    const uint32_t chA  = (uint32_t)((lane >> 4) & 1) * 16;
    const uint32_t rA   = (uint32_t)(mw * 16 + (lane & 7) + ((lane >> 3) & 1) * 8);
    const uint32_t aB0  = AG + rA * 256;
    const uint32_t chB  = (uint32_t)((lane >> 3) & 1) * 16;
    const uint32_t bCst = sm32 + OFF_B
                        + (uint32_t)(nw * 64 + (lane & 7)) * 256
                        + (uint32_t)((lane >> 4) & 1) * 2048;

    for (int tile = blockIdx.x * 3 + g; tile < nTiles; tile += 444) {
        const int rowBase = tile * GTM;
        const int wRow = rowBase + wg * 4;

        BARG(barid);   // prev iter's A reads + partial reads complete

        // ---- per-warp F staging (4 rows x 22) ----
        {
            const float* src = &g_F[(size_t)wRow * NFEAT];
            for (int i = lane; i < 4 * NFEAT; i += 32)
                Fw[i] = (wRow + i / NFEAT < nRows) ? src[i] : 0.0f;
        }
        __syncwarp();

        // ---- GEMM1 + bias + GELU -> fp16 hi/lo group A panel ----
        {
            float acc1[4][4];
            #pragma unroll
            for (int i = 0; i < 4; i++)
                #pragma unroll
                for (int j = 0; j < 4; j++) acc1[i][j] = 0.0f;
            #pragma unroll
            for (int k = 0; k < NFEAT; k++) {
                float4 w = *(const float4*)&W1s[k*128 + c1];
                #pragma unroll
                for (int i = 0; i < 4; i++) {
                    float a = Fw[i*NFEAT + k];
                    acc1[i][0] = fmaf(a, w.x, acc1[i][0]);
                    acc1[i][1] = fmaf(a, w.y, acc1[i][1]);
                    acc1[i][2] = fmaf(a, w.z, acc1[i][2]);
                    acc1[i][3] = fmaf(a, w.w, acc1[i][3]);
                }
            }
            float bv[4] = { b1s[c1], b1s[c1+1], b1s[c1+2], b1s[c1+3] };
            #pragma unroll
            for (int i = 0; i < 4; i++) {
                unsigned long long hp = 0, lp = 0;
                #pragma unroll
                for (int j = 0; j < 4; j++) {
                    float h = geluf(acc1[i][j] + bv[j]);
                    __half hb = __float2half_rn(h);
                    float rl = h - __half2float(hb);
                    __half lb = __float2half_rn(rl);
                    hp |= (unsigned long long)__half_as_ushort(hb) << (16*j);
                    lp |= (unsigned long long)__half_as_ushort(lb) << (16*j);
                }
                uint32_t row = (uint32_t)(wg * 4 + i);
                uint32_t o = offA(row, (uint32_t)(lane * 8));
                *(unsigned long long*)(AGc + o) = hp;
                *(unsigned long long*)(AGc + 8192 + o) = lp;
            }
        }
        BARG(barid);

        // ---- GEMM2: warp = 16 rows x 64 cols; D = hi_A*B + lo_A*B ----
        float acc[8][4];
        #pragma unroll
        for (int nb = 0; nb < 8; nb++)
            #pragma unroll
            for (int j = 0; j < 4; j++) acc[nb][j] = 0.0f;

        #pragma unroll
        for (int kb = 0; kb < 8; kb++) {
            const uint32_t kxA = ((uint32_t)(kb * 32) + chA) ^ swz;
            const uint32_t kxB = ((uint32_t)(kb * 32) + chB) ^ swz;

            uint32_t ah[4], al[4];
            LDSM4(ah, aB0 + kxA);
            LDSM4(al, aB0 + 8192u + kxA);

            #pragma unroll
            for (int p = 0; p < 4; p++) {
                uint32_t bh[4];
                LDSM4(bh, bCst + (uint32_t)(p * 4096) + kxB);
                mma16816(acc[2*p],   ah, bh);
                mma16816(acc[2*p],   al, bh);
                mma16816(acc[2*p+1], ah, bh + 2);
                mma16816(acc[2*p+1], al, bh + 2);
            }
        }

        // ---- epilogue: +b2, per-row LN partials via quad shuffles ----
        #pragma unroll
        for (int nb = 0; nb < 8; nb++) {
            int col = nw * 64 + nb * 8 + tig * 2;
            float bx = b2s[col], by = b2s[col + 1];
            acc[nb][0] += bx; acc[nb][1] += by;
            acc[nb][2] += bx; acc[nb][3] += by;
        }
        {
            float s0 = 0.f, q0 = 0.f, s1 = 0.f, q1 = 0.f;
            #pragma unroll
            for (int nb = 0; nb < 8; nb++) {
                s0 += acc[nb][0] + acc[nb][1];
                q0 = fmaf(acc[nb][0], acc[nb][0], q0);
                q0 = fmaf(acc[nb][1], acc[nb][1], q0);
                s1 += acc[nb][2] + acc[nb][3];
                q1 = fmaf(acc[nb][2], acc[nb][2], q1);
                q1 = fmaf(acc[nb][3], acc[nb][3], q1);
            }
            #pragma unroll
            for (int o = 1; o <= 2; o <<= 1) {
                s0 += __shfl_xor_sync(0xffffffffu, s0, o);
                q0 += __shfl_xor_sync(0xffffffffu, q0, o);
                s1 += __shfl_xor_sync(0xffffffffu, s1, o);
                q1 += __shfl_xor_sync(0xffffffffu, q1, o);
            }
            if (tig == 0) {
                int r = mw * 16 + gid;
                partS[r*4 + nw] = s0; partQ[r*4 + nw] = q0;
                partS[(r+8)*4 + nw] = s1; partQ[(r+8)*4 + nw] = q1;
            }
        }
        BARG(barid);

        // ---- normalize + store ----
        #pragma unroll
        for (int half = 0; half < 2; half++) {
            int r = mw * 16 + gid + half * 8;
            float4 S4 = *(float4*)&partS[r*4];
            float4 Q4 = *(float4*)&partQ[r*4];
            float sum = (S4.x + S4.y) + (S4.z + S4.w);
            float sq  = (Q4.x + Q4.y) + (Q4.z + Q4.w);
            float mu = sum * (1.0f/256.0f);
            float var = sq * (1.0f/256.0f) - mu * mu;
            float rs = rsqrtf(var + 1e-5f);
            int grow = rowBase + r;
            if (grow < nRows) {
                float* op = out + (size_t)grow * 256;
                #pragma unroll
                for (int nb = 0; nb < 8; nb++) {
                    int col = nw * 64 + nb * 8 + tig * 2;
                    float va = acc[nb][half*2+0];
                    float vb = acc[nb][half*2+1];
                    float2 o2;
                    o2.x = fmaf((va - mu) * rs, gos[col],   bos[col]);
                    o2.y = fmaf((vb - mu) * rs, gos[col+1], bos[col+1]);
                    *(float2*)(op + col) = o2;
                }
            }
        }
    }
}

extern "C" void kernel_launch(void* const* d_in, const int* in_sizes, int n_in,
                              void* d_out, int out_size) {
    const float* x  = (const float*)d_in[0];
    const float* gm = (const float*)d_in[1];
    const float* bm = (const float*)d_in[2];
    const float* gs = (const float*)d_in[3];
    const float* bs = (const float*)d_in[4];
    const float* W1 = (const float*)d_in[5];
    const float* b1 = (const float*)d_in[6];
    const float* W2 = (const float*)d_in[7];
    const float* b2 = (const float*)d_in[8];
    const float* go = (const float*)d_in[9];
    const float* bo = (const float*)d_in[10];

    int B = in_sizes[0] / TLEN;
    int nRows = B * NP;

    cudaFuncSetAttribute(mlp_kernel, cudaFuncAttributeMaxDynamicSharedMemorySize,
                         SMEM_BYTES);

    feat_kernel<<<B, 256>>>(x, gm, bm, gs, bs);
    mlp_kernel<<<148, NTHREADS, SMEM_BYTES>>>(
        W1, b1, W2, b2, go, bo, (float*)d_out, nRows);
}

// round 14
// speedup vs baseline: 2.3536x; 1.0460x over previous
#include <cuda_runtime.h>
#include <cuda_fp16.h>
#include <cstdint>
#include <stdint.h>
#include <math.h>

#define TLEN    6000
#define NP      199
#define PLEN    60
#define PSTRIDE 30
#define NSP     30
#define NFREQ   16
#define NM      13
#define NS      9
#define NFEAT   22
#define GTM     32            // rows per group tile
#define NTHREADS 768
#define MAXROWS (1024*NP)

// 22-dim normalized feature rows (203776 x 22)
__device__ float g_F[(size_t)MAXROWS * NFEAT];

__device__ __forceinline__ float geluf(float v){
    return 0.5f * v * (1.0f + erff(v * 0.7071067811865476f));
}
__device__ __forceinline__ float freqf(int k){
    return (float)(((double)k * 200.0) / 30.0);
}
__device__ __forceinline__ uint32_t smem_u32(const void* p){
    uint32_t a;
    asm("{ .reg .u64 t; cvta.to.shared.u64 t, %1; cvt.u32.u64 %0, t; }"
        : "=r"(a) : "l"(p));
    return a;
}

// mma.sync m16n8k16 fp16 -> f32, accumulate in place
__device__ __forceinline__ void mma16816(float* d, const uint32_t* a,
                                         const uint32_t* b){
    asm volatile(
        "mma.sync.aligned.m16n8k16.row.col.f32.f16.f16.f32 "
        "{%0,%1,%2,%3}, {%4,%5,%6,%7}, {%8,%9}, {%0,%1,%2,%3};"
        : "+f"(d[0]), "+f"(d[1]), "+f"(d[2]), "+f"(d[3])
        : "r"(a[0]), "r"(a[1]), "r"(a[2]), "r"(a[3]), "r"(b[0]), "r"(b[1]));
}
#define LDSM4(R, addr) \
    asm volatile("ldmatrix.sync.aligned.m8n8.x4.shared.b16 {%0,%1,%2,%3}, [%4];" \
        : "=r"((R)[0]), "=r"((R)[1]), "=r"((R)[2]), "=r"((R)[3]) : "r"(addr))
#define BARG(id) \
    asm volatile("bar.sync %0, 256;" :: "r"(id) : "memory")

// ============================================================
// Kernel A: per-patch features + group layernorms -> g_F
// (unchanged 75us version)
// ============================================================
__global__ __launch_bounds__(256) void feat_kernel(
    const float* __restrict__ x,
    const float* __restrict__ gm, const float* __restrict__ bm,
    const float* __restrict__ gs, const float* __restrict__ bs)
{
    __shared__ float sx[TLEN];
    __shared__ float cosT[NFREQ * 16];
    __shared__ float sinT[NFREQ * 16];
    __shared__ float hannS[NSP];
    __shared__ float psdS[NFREQ * 200];

    const int tid = threadIdx.x;
    {
        const float4* xg = (const float4*)(x + (size_t)blockIdx.x * TLEN);
        float4* s4 = (float4*)sx;
        for (int i = tid; i < TLEN/4; i += 256) s4[i] = xg[i];
    }
    for (int i = tid; i < NFREQ*16; i += 256) {
        int k = i >> 4, t = i & 15;
        double sv, cv;
        sincospi(2.0 * (double)(k * t) / 30.0, &sv, &cv);
        cosT[i] = (float)cv;
        sinT[i] = (float)sv;
    }
    if (tid < NSP)
        hannS[tid] = (float)(0.5 * (1.0 - cospi(2.0 * (double)tid / 30.0)));
    __syncthreads();
    if (tid >= NP) return;

    const int off = tid * PSTRIDE;
    float* frow = &g_F[((size_t)blockIdx.x * NP + tid) * NFEAT];

    float v0 = sx[off];
    float mx = v0, mn = v0, sum = v0;
    float sumsq = v0 * v0;
    float amax = fabsf(v0); int aidx = 0;
    float prev = v0;
    float tsg = v0 + 1e-10f;
    int   sprev = (tsg > 0.0f) - (tsg < 0.0f);
    float dmax = -INFINITY, dmin = INFINITY, dabs = 0.0f;
    int zc = 0;
    #pragma unroll
    for (int t = 1; t < PLEN; t++) {
        float v = sx[off + t];
        mx = fmaxf(mx, v); mn = fminf(mn, v);
        sum += v; sumsq = fmaf(v, v, sumsq);
        float a = fabsf(v);
        if (a > amax) { amax = a; aidx = t; }
        float d = v - prev;
        dmax = fmaxf(dmax, d); dmin = fminf(dmin, d); dabs += fabsf(d);
        float tg = v + 1e-10f;
        int sg = (tg > 0.0f) - (tg < 0.0f);
        zc += (sg != sprev);
        sprev = sg; prev = v;
    }
    float mean = sum * (1.0f/60.0f);

    float m2 = 0.f, m3 = 0.f, m4 = 0.f;
    #pragma unroll
    for (int t = 0; t < PLEN; t++) {
        float c = sx[off + t] - mean;
        float c2 = c * c;
        m2 += c2; m3 = fmaf(c2, c, m3); m4 = fmaf(c2, c2, m4);
    }
    m2 *= (1.0f/60.0f); m3 *= (1.0f/60.0f); m4 *= (1.0f/60.0f);
    float stdv = sqrtf(m2);

    {
        float morph[NM];
        morph[0] = mx; morph[1] = mn; morph[2] = mx - mn; morph[3] = mean;
        morph[4] = stdv;
        morph[5] = (float)aidx * (1.0f/60.0f);
        morph[6] = dmax; morph[7] = dmin;
        morph[8] = dabs * (1.0f/59.0f);
        morph[9] = (float)zc * (1.0f/60.0f);
        morph[10] = sumsq;
        morph[11] = m4 / (m2 * m2) - 3.0f;
        morph[12] = m3 / (m2 * stdv);
        #pragma unroll
        for (int i = 0; i < NM; i++) if (!isfinite(morph[i])) morph[i] = 0.0f;

        float mu = 0.f;
        #pragma unroll
        for (int i = 0; i < NM; i++) mu += morph[i];
        mu *= (1.0f/13.0f);
        float var = 0.f;
        #pragma unroll
        for (int i = 0; i < NM; i++) { float d = morph[i]-mu; var = fmaf(d,d,var); }
        var *= (1.0f/13.0f);
        float scl = rsqrtf(var + 1e-5f);
        #pragma unroll
        for (int i = 0; i < NM; i++)
            frow[i] = fmaf((morph[i]-mu)*scl, gm[i], bm[i]);
    }

    float ye0[16], yo0[15], ye1[16], yo1[15], ye2[16], yo2[15];

    #define FOLD_SEG(YE, YO, SB) { \
        float s = 0.f; \
        _Pragma("unroll") \
        for (int t = 0; t < NSP; t++) s += sx[(SB) + t]; \
        s *= (1.0f/30.0f); \
        float s2 = 2.0f * s; \
        _Pragma("unroll") \
        for (int t = 1; t < 15; t++) { \
            float a = sx[(SB) + t]; \
            float b = sx[(SB) + 30 - t]; \
            float w = hannS[t]; \
            YE[t] = (a + b - s2) * w; \
            YO[t] = (a - b) * w; \
        } \
        YE[15] = sx[(SB) + 15] - s; \
    }

    FOLD_SEG(ye0, yo0, off)
    FOLD_SEG(ye1, yo1, off + 15)
    FOLD_SEG(ye2, yo2, off + 30)
    #undef FOLD_SEG

    for (int k = 0; k < NFREQ; k++) {
        const float* ck = &cosT[k * 16];
        const float* sk = &sinT[k * 16];
        float re0 = 0.f, im0 = 0.f, re1 = 0.f, im1 = 0.f, re2 = 0.f, im2 = 0.f;
        #pragma unroll
        for (int t = 1; t < 15; t++) {
            float c = ck[t], si = sk[t];
            re0 = fmaf(ye0[t], c, re0); im0 = fmaf(yo0[t], si, im0);
            re1 = fmaf(ye1[t], c, re1); im1 = fmaf(yo1[t], si, im1);
            re2 = fmaf(ye2[t], c, re2); im2 = fmaf(yo2[t], si, im2);
        }
        float c15 = ck[15];
        re0 = fmaf(ye0[15], c15, re0);
        re1 = fmaf(ye1[15], c15, re1);
        re2 = fmaf(ye2[15], c15, re2);
        float p = fmaf(re0,re0,im0*im0) + fmaf(re1,re1,im1*im1) + fmaf(re2,re2,im2*im2);
        float sc = (k == 0 || k == NFREQ-1) ? (1.0f/6750.0f) : (2.0f/6750.0f);
        psdS[k*200 + tid] = p * sc;
    }

    float psd[NFREQ];
    #pragma unroll
    for (int k = 0; k < NFREQ; k++) psd[k] = psdS[k*200 + tid];

    float total = 0.f;
    #pragma unroll
    for (int k = 0; k < NFREQ; k++) total += psd[k];
    total += 1e-12f;
    float inv = 1.0f / total;

    float b1v = psd[1];
    float b3v = psd[2] + psd[3] + psd[4];
    float b4v = 0.f;
    #pragma unroll
    for (int k = 5; k <= 14; k++) b4v += psd[k];

    float pmax = psd[0]; int pkk = 0;
    #pragma unroll
    for (int k = 1; k < NFREQ; k++)
        if (psd[k] > pmax) { pmax = psd[k]; pkk = k; }

    float thr = 0.95f * total;
    float csum = 0.f; int ek = 0; bool fnd = false;
    #pragma unroll
    for (int k = 0; k < NFREQ; k++) {
        csum += psd[k];
        if (!fnd && csum >= thr) { ek = k; fnd = true; }
    }
    float ent = 0.f;
    #pragma unroll
    for (int k = 0; k < NFREQ; k++) {
        float pn = psd[k] * inv;
        ent -= pn * log2f(pn + 1e-12f);
    }

    float spec[NS];
    spec[0] = 0.0f;
    spec[1] = b1v * inv;
    spec[2] = 0.0f;
    spec[3] = b3v * inv;
    spec[4] = b4v * inv;
    spec[5] = freqf(pkk);
    spec[6] = freqf(ek);
    spec[7] = ent;
    spec[8] = total;
    #pragma unroll
    for (int i = 0; i < NS; i++) if (!isfinite(spec[i])) spec[i] = 0.0f;

    {
        float mu = 0.f;
        #pragma unroll
        for (int i = 0; i < NS; i++) mu += spec[i];
        mu *= (1.0f/9.0f);
        float var = 0.f;
        #pragma unroll
        for (int i = 0; i < NS; i++) { float d = spec[i]-mu; var = fmaf(d,d,var); }
        var *= (1.0f/9.0f);
        float scl = rsqrtf(var + 1e-5f);
        #pragma unroll
        for (int i = 0; i < NS; i++)
            frow[NM + i] = fmaf((spec[i]-mu)*scl, gs[i], bs[i]);
    }
}

// ============================================================
// Kernel B: persistent MLP, 3 staggered warp-groups x 32-row tiles
// pure fp16 MMA (1 product), double-buffered A, 2 barriers/tile
// ============================================================
#define OFF_B      0          // 65536
#define OFF_AG     65536      // 3 groups x 2 bufs x 8192 = 49152
#define OFF_W1     114688     // 11264
#define OFF_FS     125952     // 8448
#define OFF_B1     134400     // 512
#define OFF_B2     134912     // 1024
#define OFF_GO     135936     // 1024
#define OFF_BO     136960     // 1024
#define OFF_PS     137984     // 1536
#define OFF_PQ     139520     // 1536
#define SMEM_BYTES 141056

// XOR swizzle at 16B granularity; 256B per row
__device__ __forceinline__ uint32_t offA(uint32_t row, uint32_t kbyte){
    return row * 256u + (kbyte ^ ((row & 7u) << 4));
}

__global__ __launch_bounds__(NTHREADS, 1) void mlp_kernel(
    const float* __restrict__ W1, const float* __restrict__ b1,
    const float* __restrict__ W2, const float* __restrict__ b2,
    const float* __restrict__ go, const float* __restrict__ bo,
    float* __restrict__ out, int nRows)
{
    extern __shared__ char smc[];
    const uint32_t sm32 = smem_u32(smc);
    float* W1s = (float*)(smc + OFF_W1);
    float* Fs  = (float*)(smc + OFF_FS);
    float* b1s = (float*)(smc + OFF_B1);
    float* b2s = (float*)(smc + OFF_B2);
    float* gos = (float*)(smc + OFF_GO);
    float* bos = (float*)(smc + OFF_BO);

    const int tid  = threadIdx.x;
    const int wid  = tid >> 5;
    const int lane = tid & 31;
    const int gid  = lane >> 2;   // 0..7
    const int tig  = lane & 3;    // 0..3

    const int g    = wid >> 3;    // warp group 0/1/2
    const int wg   = wid & 7;     // warp within group
    const int barid = 1 + g;

    // ---- one-time setup ----
    for (int i = tid; i < 22*128; i += NTHREADS) W1s[i] = W1[i];
    if (tid < 128) b1s[tid] = b1[tid];
    for (int i = tid; i < 256; i += NTHREADS) { b2s[i]=b2[i]; gos[i]=go[i]; bos[i]=bo[i]; }

    // W2 [k][n] -> B_T panel [n][kbyte] fp16, swizzled
    for (int i = tid; i < 128*256; i += NTHREADS) {
        int k = i >> 8, n = i & 255;
        uint32_t o = offA((uint32_t)n, (uint32_t)(2*k));
        *(__half*)(smc + OFF_B + o) = __float2half_rn(W2[i]);
    }
    __syncthreads();

    const int c1 = lane * 4;              // GEMM1 cols (= GEMM2 k)
    float* Fw = Fs + wid * (4 * NFEAT);
    float* partS = (float*)(smc + OFF_PS) + g * 128;  // [32][4]
    float* partQ = (float*)(smc + OFF_PQ) + g * 128;

    const int mw = wg & 1;                // 16-row half within 32-row tile
    const int nw = wg >> 1;               // 64-col quarter (0..3)
    const int nTiles = (nRows + GTM - 1) / GTM;   // 6368

    // group A panel base (2 buffers x 8192)
    const char* AGc = smc + OFF_AG + g * 16384;
    const uint32_t AG = sm32 + OFF_AG + (uint32_t)g * 16384u;

    // ---- ldmatrix per-lane address invariants ----
    const uint32_t swz  = (uint32_t)(lane & 7) << 4;
    const uint32_t chA  = (uint32_t)((lane >> 4) & 1) * 16;
    const uint32_t rA   = (uint32_t)(mw * 16 + (lane & 7) + ((lane >> 3) & 1) * 8);
    const uint32_t aOff = rA * 256;
    const uint32_t chB  = (uint32_t)((lane >> 3) & 1) * 16;
    const uint32_t bCst = sm32 + OFF_B
                        + (uint32_t)(nw * 64 + (lane & 7)) * 256
                        + (uint32_t)((lane >> 4) & 1) * 2048;

    int buf = 0;
    for (int tile = blockIdx.x * 3 + g; tile < nTiles; tile += 444) {
        const int rowBase = tile * GTM;
        const int wRow = rowBase + wg * 4;

        // ---- per-warp F staging (4 rows x 22) ----
        {
            const float* src = &g_F[(size_t)wRow * NFEAT];
            for (int i = lane; i < 4 * NFEAT; i += 32)
                Fw[i] = (wRow + i / NFEAT < nRows) ? src[i] : 0.0f;
        }
        __syncwarp();

        // ---- GEMM1 + bias + GELU -> fp16 group A panel[buf] ----
        {
            float acc1[4][4];
            #pragma unroll
            for (int i = 0; i < 4; i++)
                #pragma unroll
                for (int j = 0; j < 4; j++) acc1[i][j] = 0.0f;
            #pragma unroll
            for (int k = 0; k < NFEAT; k++) {
                float4 w = *(const float4*)&W1s[k*128 + c1];
                #pragma unroll
                for (int i = 0; i < 4; i++) {
                    float a = Fw[i*NFEAT + k];
                    acc1[i][0] = fmaf(a, w.x, acc1[i][0]);
                    acc1[i][1] = fmaf(a, w.y, acc1[i][1]);
                    acc1[i][2] = fmaf(a, w.z, acc1[i][2]);
                    acc1[i][3] = fmaf(a, w.w, acc1[i][3]);
                }
            }
            float bv[4] = { b1s[c1], b1s[c1+1], b1s[c1+2], b1s[c1+3] };
            const char* Ab = AGc + buf * 8192;
            #pragma unroll
            for (int i = 0; i < 4; i++) {
                unsigned long long hp = 0;
                #pragma unroll
                for (int j = 0; j < 4; j++) {
                    float h = geluf(acc1[i][j] + bv[j]);
                    hp |= (unsigned long long)__half_as_ushort(__float2half_rn(h)) << (16*j);
                }
                uint32_t row = (uint32_t)(wg * 4 + i);
                uint32_t o = offA(row, (uint32_t)(lane * 8));
                *(unsigned long long*)(Ab + o) = hp;
            }
        }
        BARG(barid);   // A[buf] visible to the whole group

        // ---- GEMM2: warp = 16 rows x 64 cols; single fp16 product ----
        float acc[8][4];
        #pragma unroll
        for (int nb = 0; nb < 8; nb++)
            #pragma unroll
            for (int j = 0; j < 4; j++) acc[nb][j] = 0.0f;

        const uint32_t aBase = AG + (uint32_t)(buf << 13) + aOff;
        #pragma unroll
        for (int kb = 0; kb < 8; kb++) {
            const uint32_t kxA = ((uint32_t)(kb * 32) + chA) ^ swz;
            const uint32_t kxB = ((uint32_t)(kb * 32) + chB) ^ swz;

            uint32_t ah[4];
            LDSM4(ah, aBase + kxA);

            #pragma unroll
            for (int p = 0; p < 4; p++) {
                uint32_t bh[4];
                LDSM4(bh, bCst + (uint32_t)(p * 4096) + kxB);
                mma16816(acc[2*p],   ah, bh);
                mma16816(acc[2*p+1], ah, bh + 2);
            }
        }

        // ---- epilogue: +b2, per-row LN partials via quad shuffles ----
        #pragma unroll
        for (int nb = 0; nb < 8; nb++) {
            int col = nw * 64 + nb * 8 + tig * 2;
            float bx = b2s[col], by = b2s[col + 1];
            acc[nb][0] += bx; acc[nb][1] += by;
            acc[nb][2] += bx; acc[nb][3] += by;
        }
        {
            float s0 = 0.f, q0 = 0.f, s1 = 0.f, q1 = 0.f;
            #pragma unroll
            for (int nb = 0; nb < 8; nb++) {
                s0 += acc[nb][0] + acc[nb][1];
                q0 = fmaf(acc[nb][0], acc[nb][0], q0);
                q0 = fmaf(acc[nb][1], acc[nb][1], q0);
                s1 += acc[nb][2] + acc[nb][3];
                q1 = fmaf(acc[nb][2], acc[nb][2], q1);
                q1 = fmaf(acc[nb][3], acc[nb][3], q1);
            }
            #pragma unroll
            for (int o = 1; o <= 2; o <<= 1) {
                s0 += __shfl_xor_sync(0xffffffffu, s0, o);
                q0 += __shfl_xor_sync(0xffffffffu, q0, o);
                s1 += __shfl_xor_sync(0xffffffffu, s1, o);
                q1 += __shfl_xor_sync(0xffffffffu, q1, o);
            }
            if (tig == 0) {
                int r = mw * 16 + gid;
                partS[r*4 + nw] = s0; partQ[r*4 + nw] = q0;
                partS[(r+8)*4 + nw] = s1; partQ[(r+8)*4 + nw] = q1;
            }
        }
        BARG(barid);

        // ---- normalize + store ----
        #pragma unroll
        for (int half = 0; half < 2; half++) {
            int r = mw * 16 + gid + half * 8;
            float4 S4 = *(float4*)&partS[r*4];
            float4 Q4 = *(float4*)&partQ[r*4];
            float sum = (S4.x + S4.y) + (S4.z + S4.w);
            float sq  = (Q4.x + Q4.y) + (Q4.z + Q4.w);
            float mu = sum * (1.0f/256.0f);
            float var = sq * (1.0f/256.0f) - mu * mu;
            float rs = rsqrtf(var + 1e-5f);
            int grow = rowBase + r;
            if (grow < nRows) {
                float* op = out + (size_t)grow * 256;
                #pragma unroll
                for (int nb = 0; nb < 8; nb++) {
                    int col = nw * 64 + nb * 8 + tig * 2;
                    float va = acc[nb][half*2+0];
                    float vb = acc[nb][half*2+1];
                    float2 o2;
                    o2.x = fmaf((va - mu) * rs, gos[col],   bos[col]);
                    o2.y = fmaf((vb - mu) * rs, gos[col+1], bos[col+1]);
                    *(float2*)(op + col) = o2;
                }
            }
        }
        buf ^= 1;
    }
}

extern "C" void kernel_launch(void* const* d_in, const int* in_sizes, int n_in,
                              void* d_out, int out_size) {
    const float* x  = (const float*)d_in[0];
    const float* gm = (const float*)d_in[1];
    const float* bm = (const float*)d_in[2];
    const float* gs = (const float*)d_in[3];
    const float* bs = (const float*)d_in[4];
    const float* W1 = (const float*)d_in[5];
    const float* b1 = (const float*)d_in[6];
    const float* W2 = (const float*)d_in[7];
    const float* b2 = (const float*)d_in[8];
    const float* go = (const float*)d_in[9];
    const float* bo = (const float*)d_in[10];

    int B = in_sizes[0] / TLEN;
    int nRows = B * NP;

    cudaFuncSetAttribute(mlp_kernel, cudaFuncAttributeMaxDynamicSharedMemorySize,
                         SMEM_BYTES);

    feat_kernel<<<B, 256>>>(x, gm, bm, gs, bs);
    mlp_kernel<<<148, NTHREADS, SMEM_BYTES>>>(
        W1, b1, W2, b2, go, bo, (float*)d_out, nRows);
}

// round 15
// speedup vs baseline: 2.5657x; 1.0901x over previous
#include <cuda_runtime.h>
#include <cuda_fp16.h>
#include <cstdint>
#include <stdint.h>
#include <math.h>

#define TLEN    6000
#define NP      199
#define PLEN    60
#define PSTRIDE 30
#define NSP     30
#define NFREQ   16
#define NM      13
#define NS      9
#define NFEAT   22
#define GTM     32            // rows per group tile
#define NTHREADS 768
#define MAXROWS (1024*NP)

// fp16 feature rows, padded to 32 (22 real + 10 zeros)
__device__ __half g_F2[(size_t)MAXROWS * 32];

__device__ __forceinline__ float geluf(float v){
    return 0.5f * v * (1.0f + erff(v * 0.7071067811865476f));
}
__device__ __forceinline__ float freqf(int k){
    return (float)(((double)k * 200.0) / 30.0);
}
__device__ __forceinline__ uint32_t smem_u32(const void* p){
    uint32_t a;
    asm("{ .reg .u64 t; cvta.to.shared.u64 t, %1; cvt.u32.u64 %0, t; }"
        : "=r"(a) : "l"(p));
    return a;
}

// mma.sync m16n8k16 fp16 -> f32, accumulate in place
__device__ __forceinline__ void mma16816(float* d, const uint32_t* a,
                                         const uint32_t* b){
    asm volatile(
        "mma.sync.aligned.m16n8k16.row.col.f32.f16.f16.f32 "
        "{%0,%1,%2,%3}, {%4,%5,%6,%7}, {%8,%9}, {%0,%1,%2,%3};"
        : "+f"(d[0]), "+f"(d[1]), "+f"(d[2]), "+f"(d[3])
        : "r"(a[0]), "r"(a[1]), "r"(a[2]), "r"(a[3]), "r"(b[0]), "r"(b[1]));
}
#define LDSM4(R, addr) \
    asm volatile("ldmatrix.sync.aligned.m8n8.x4.shared.b16 {%0,%1,%2,%3}, [%4];" \
        : "=r"((R)[0]), "=r"((R)[1]), "=r"((R)[2]), "=r"((R)[3]) : "r"(addr))
#define BARG(id) \
    asm volatile("bar.sync %0, 256;" :: "r"(id) : "memory")

// ============================================================
// Kernel A: per-patch features + group layernorms -> g_F2 (fp16)
// ============================================================
__global__ __launch_bounds__(256) void feat_kernel(
    const float* __restrict__ x,
    const float* __restrict__ gm, const float* __restrict__ bm,
    const float* __restrict__ gs, const float* __restrict__ bs)
{
    __shared__ float sx[TLEN];
    __shared__ float cosT[NFREQ * 16];
    __shared__ float sinT[NFREQ * 16];
    __shared__ float hannS[NSP];
    __shared__ float psdS[NFREQ * 200];

    const int tid = threadIdx.x;
    {
        const float4* xg = (const float4*)(x + (size_t)blockIdx.x * TLEN);
        float4* s4 = (float4*)sx;
        for (int i = tid; i < TLEN/4; i += 256) s4[i] = xg[i];
    }
    for (int i = tid; i < NFREQ*16; i += 256) {
        int k = i >> 4, t = i & 15;
        double sv, cv;
        sincospi(2.0 * (double)(k * t) / 30.0, &sv, &cv);
        cosT[i] = (float)cv;
        sinT[i] = (float)sv;
    }
    if (tid < NSP)
        hannS[tid] = (float)(0.5 * (1.0 - cospi(2.0 * (double)tid / 30.0)));
    __syncthreads();
    if (tid >= NP) return;

    const int off = tid * PSTRIDE;
    __half* frow = &g_F2[((size_t)blockIdx.x * NP + tid) * 32];

    float v0 = sx[off];
    float mx = v0, mn = v0, sum = v0;
    float sumsq = v0 * v0;
    float amax = fabsf(v0); int aidx = 0;
    float prev = v0;
    float tsg = v0 + 1e-10f;
    int   sprev = (tsg > 0.0f) - (tsg < 0.0f);
    float dmax = -INFINITY, dmin = INFINITY, dabs = 0.0f;
    int zc = 0;
    #pragma unroll
    for (int t = 1; t < PLEN; t++) {
        float v = sx[off + t];
        mx = fmaxf(mx, v); mn = fminf(mn, v);
        sum += v; sumsq = fmaf(v, v, sumsq);
        float a = fabsf(v);
        if (a > amax) { amax = a; aidx = t; }
        float d = v - prev;
        dmax = fmaxf(dmax, d); dmin = fminf(dmin, d); dabs += fabsf(d);
        float tg = v + 1e-10f;
        int sg = (tg > 0.0f) - (tg < 0.0f);
        zc += (sg != sprev);
        sprev = sg; prev = v;
    }
    float mean = sum * (1.0f/60.0f);

    float m2 = 0.f, m3 = 0.f, m4 = 0.f;
    #pragma unroll
    for (int t = 0; t < PLEN; t++) {
        float c = sx[off + t] - mean;
        float c2 = c * c;
        m2 += c2; m3 = fmaf(c2, c, m3); m4 = fmaf(c2, c2, m4);
    }
    m2 *= (1.0f/60.0f); m3 *= (1.0f/60.0f); m4 *= (1.0f/60.0f);
    float stdv = sqrtf(m2);

    {
        float morph[NM];
        morph[0] = mx; morph[1] = mn; morph[2] = mx - mn; morph[3] = mean;
        morph[4] = stdv;
        morph[5] = (float)aidx * (1.0f/60.0f);
        morph[6] = dmax; morph[7] = dmin;
        morph[8] = dabs * (1.0f/59.0f);
        morph[9] = (float)zc * (1.0f/60.0f);
        morph[10] = sumsq;
        morph[11] = m4 / (m2 * m2) - 3.0f;
        morph[12] = m3 / (m2 * stdv);
        #pragma unroll
        for (int i = 0; i < NM; i++) if (!isfinite(morph[i])) morph[i] = 0.0f;

        float mu = 0.f;
        #pragma unroll
        for (int i = 0; i < NM; i++) mu += morph[i];
        mu *= (1.0f/13.0f);
        float var = 0.f;
        #pragma unroll
        for (int i = 0; i < NM; i++) { float d = morph[i]-mu; var = fmaf(d,d,var); }
        var *= (1.0f/13.0f);
        float scl = rsqrtf(var + 1e-5f);
        #pragma unroll
        for (int i = 0; i < NM; i++)
            frow[i] = __float2half_rn(fmaf((morph[i]-mu)*scl, gm[i], bm[i]));
    }

    float ye0[16], yo0[15], ye1[16], yo1[15], ye2[16], yo2[15];

    #define FOLD_SEG(YE, YO, SB) { \
        float s = 0.f; \
        _Pragma("unroll") \
        for (int t = 0; t < NSP; t++) s += sx[(SB) + t]; \
        s *= (1.0f/30.0f); \
        float s2 = 2.0f * s; \
        _Pragma("unroll") \
        for (int t = 1; t < 15; t++) { \
            float a = sx[(SB) + t]; \
            float b = sx[(SB) + 30 - t]; \
            float w = hannS[t]; \
            YE[t] = (a + b - s2) * w; \
            YO[t] = (a - b) * w; \
        } \
        YE[15] = sx[(SB) + 15] - s; \
    }

    FOLD_SEG(ye0, yo0, off)
    FOLD_SEG(ye1, yo1, off + 15)
    FOLD_SEG(ye2, yo2, off + 30)
    #undef FOLD_SEG

    for (int k = 0; k < NFREQ; k++) {
        const float* ck = &cosT[k * 16];
        const float* sk = &sinT[k * 16];
        float re0 = 0.f, im0 = 0.f, re1 = 0.f, im1 = 0.f, re2 = 0.f, im2 = 0.f;
        #pragma unroll
        for (int t = 1; t < 15; t++) {
            float c = ck[t], si = sk[t];
            re0 = fmaf(ye0[t], c, re0); im0 = fmaf(yo0[t], si, im0);
            re1 = fmaf(ye1[t], c, re1); im1 = fmaf(yo1[t], si, im1);
            re2 = fmaf(ye2[t], c, re2); im2 = fmaf(yo2[t], si, im2);
        }
        float c15 = ck[15];
        re0 = fmaf(ye0[15], c15, re0);
        re1 = fmaf(ye1[15], c15, re1);
        re2 = fmaf(ye2[15], c15, re2);
        float p = fmaf(re0,re0,im0*im0) + fmaf(re1,re1,im1*im1) + fmaf(re2,re2,im2*im2);
        float sc = (k == 0 || k == NFREQ-1) ? (1.0f/6750.0f) : (2.0f/6750.0f);
        psdS[k*200 + tid] = p * sc;
    }

    float psd[NFREQ];
    #pragma unroll
    for (int k = 0; k < NFREQ; k++) psd[k] = psdS[k*200 + tid];

    float total = 0.f;
    #pragma unroll
    for (int k = 0; k < NFREQ; k++) total += psd[k];
    total += 1e-12f;
    float inv = 1.0f / total;

    float b1v = psd[1];
    float b3v = psd[2] + psd[3] + psd[4];
    float b4v = 0.f;
    #pragma unroll
    for (int k = 5; k <= 14; k++) b4v += psd[k];

    float pmax = psd[0]; int pkk = 0;
    #pragma unroll
    for (int k = 1; k < NFREQ; k++)
        if (psd[k] > pmax) { pmax = psd[k]; pkk = k; }

    float thr = 0.95f * total;
    float csum = 0.f; int ek = 0; bool fnd = false;
    #pragma unroll
    for (int k = 0; k < NFREQ; k++) {
        csum += psd[k];
        if (!fnd && csum >= thr) { ek = k; fnd = true; }
    }
    float ent = 0.f;
    #pragma unroll
    for (int k = 0; k < NFREQ; k++) {
        float pn = psd[k] * inv;
        ent -= pn * log2f(pn + 1e-12f);
    }

    float spec[NS];
    spec[0] = 0.0f;
    spec[1] = b1v * inv;
    spec[2] = 0.0f;
    spec[3] = b3v * inv;
    spec[4] = b4v * inv;
    spec[5] = freqf(pkk);
    spec[6] = freqf(ek);
    spec[7] = ent;
    spec[8] = total;
    #pragma unroll
    for (int i = 0; i < NS; i++) if (!isfinite(spec[i])) spec[i] = 0.0f;

    {
        float mu = 0.f;
        #pragma unroll
        for (int i = 0; i < NS; i++) mu += spec[i];
        mu *= (1.0f/9.0f);
        float var = 0.f;
        #pragma unroll
        for (int i = 0; i < NS; i++) { float d = spec[i]-mu; var = fmaf(d,d,var); }
        var *= (1.0f/9.0f);
        float scl = rsqrtf(var + 1e-5f);
        #pragma unroll
        for (int i = 0; i < NS; i++)
            frow[NM + i] = __float2half_rn(fmaf((spec[i]-mu)*scl, gs[i], bs[i]));
    }
    #pragma unroll
    for (int i = NFEAT; i < 32; i++) frow[i] = __ushort_as_half((unsigned short)0);
}

// ============================================================
// Kernel B: persistent MLP, both GEMMs on tensor cores (fp16)
// 3 staggered warp-groups x 32-row tiles, 2 barriers/tile
// ============================================================
#define OFF_B      0          // W2 panel 65536
#define OFF_W1P    65536      // W1 fp16 panel 128x128B = 16384
#define OFF_AG     81920      // 3 groups x 2 bufs x 8192 = 49152
#define OFF_B1     131072     // 512
#define OFF_B2     131584     // 1024
#define OFF_GO     132608     // 1024
#define OFF_BO     133632     // 1024
#define OFF_PS     134656     // 1536
#define OFF_PQ     136192     // 1536
#define SMEM_BYTES 137728

// XOR swizzle at 16B granularity; 256B rows (A / W2 panels)
__device__ __forceinline__ uint32_t offA(uint32_t row, uint32_t kbyte){
    return row * 256u + (kbyte ^ ((row & 7u) << 4));
}
// 128B rows (W1 panel)
__device__ __forceinline__ uint32_t offW(uint32_t row, uint32_t kbyte){
    return row * 128u + (kbyte ^ ((row & 7u) << 4));
}

__global__ __launch_bounds__(NTHREADS, 1) void mlp_kernel(
    const float* __restrict__ W1, const float* __restrict__ b1,
    const float* __restrict__ W2, const float* __restrict__ b2,
    const float* __restrict__ go, const float* __restrict__ bo,
    float* __restrict__ out, int nRows)
{
    extern __shared__ char smc[];
    const uint32_t sm32 = smem_u32(smc);
    float* b1s = (float*)(smc + OFF_B1);
    float* b2s = (float*)(smc + OFF_B2);
    float* gos = (float*)(smc + OFF_GO);
    float* bos = (float*)(smc + OFF_BO);

    const int tid  = threadIdx.x;
    const int wid  = tid >> 5;
    const int lane = tid & 31;
    const int gid  = lane >> 2;   // 0..7
    const int tig  = lane & 3;    // 0..3

    const int g    = wid >> 3;    // warp group 0/1/2
    const int wg   = wid & 7;     // warp within group
    const int barid = 1 + g;

    // ---- one-time setup ----
    if (tid < 128) b1s[tid] = b1[tid];
    for (int i = tid; i < 256; i += NTHREADS) { b2s[i]=b2[i]; gos[i]=go[i]; bos[i]=bo[i]; }

    // W2 [k][n] -> B_T panel [n][kbyte] fp16, swizzled (256B rows)
    for (int i = tid; i < 128*256; i += NTHREADS) {
        int k = i >> 8, n = i & 255;
        uint32_t o = offA((uint32_t)n, (uint32_t)(2*k));
        *(__half*)(smc + OFF_B + o) = __float2half_rn(W2[i]);
    }
    // W1 [k][n] -> panel [n][kbyte] fp16, K padded to 32 (128B rows)
    for (int i = tid; i < 128*32; i += NTHREADS) {
        int n = i >> 5, k = i & 31;
        float v = (k < NFEAT) ? W1[k*128 + n] : 0.0f;
        uint32_t o = offW((uint32_t)n, (uint32_t)(2*k));
        *(__half*)(smc + OFF_W1P + o) = __float2half_rn(v);
    }
    __syncthreads();

    float* partS = (float*)(smc + OFF_PS) + g * 128;  // [32][4]
    float* partQ = (float*)(smc + OFF_PQ) + g * 128;

    const int mw = wg & 1;                // 16-row half within 32-row tile
    const int nw = wg >> 1;               // 64-col quarter of 256 (GEMM2)
    const int nw1 = wg >> 1;              // 32-col quarter of 128 (GEMM1)
    const int nTiles = (nRows + GTM - 1) / GTM;   // 6368

    // group A panel base (2 buffers x 8192)
    const char* AGc = smc + OFF_AG + g * 16384;
    const uint32_t AG = sm32 + OFF_AG + (uint32_t)g * 16384u;

    // ---- ldmatrix / address invariants ----
    const uint32_t swz  = (uint32_t)(lane & 7) << 4;
    const uint32_t chA  = (uint32_t)((lane >> 4) & 1) * 16;
    const uint32_t rA   = (uint32_t)(mw * 16 + (lane & 7) + ((lane >> 3) & 1) * 8);
    const uint32_t aOff = rA * 256;
    const uint32_t chB  = (uint32_t)((lane >> 3) & 1) * 16;
    const uint32_t bCst = sm32 + OFF_B
                        + (uint32_t)(nw * 64 + (lane & 7)) * 256
                        + (uint32_t)((lane >> 4) & 1) * 2048;
    // W1 frags: col-major B pattern over 128B rows
    const uint32_t nW1  = (uint32_t)(nw1 * 32 + (lane & 7) + ((lane >> 4) & 1) * 8);
    const uint32_t w1Base = sm32 + OFF_W1P + nW1 * 128u;
    const uint32_t swW  = (nW1 & 7u) << 4;

    int buf = 0;
    for (int tile = blockIdx.x * 3 + g; tile < nTiles; tile += 444) {
        const int rowBase = tile * GTM;

        // ---- GEMM1 on MMA: warp = 16 rows x 32 cols, K=32 ----
        {
            float acc1[4][4];
            #pragma unroll
            for (int nb = 0; nb < 4; nb++)
                #pragma unroll
                for (int j = 0; j < 4; j++) acc1[nb][j] = 0.0f;

            const __half* f0 = g_F2 + (size_t)(rowBase + mw*16 + gid) * 32 + tig * 2;
            #pragma unroll
            for (int kb = 0; kb < 2; kb++) {
                uint32_t af[4];
                af[0] = *(const uint32_t*)(f0 + kb*16);
                af[1] = *(const uint32_t*)(f0 + kb*16 + 256);
                af[2] = *(const uint32_t*)(f0 + kb*16 + 8);
                af[3] = *(const uint32_t*)(f0 + kb*16 + 264);
                uint32_t kxW = ((uint32_t)(kb * 32) + chB) ^ swW;
                uint32_t wf0[4], wf1[4];
                LDSM4(wf0, w1Base + kxW);
                LDSM4(wf1, w1Base + 2048u + kxW);
                mma16816(acc1[0], af, wf0);
                mma16816(acc1[1], af, wf0 + 2);
                mma16816(acc1[2], af, wf1);
                mma16816(acc1[3], af, wf1 + 2);
            }
            // bias + GELU + pack fp16 -> A panel[buf]
            const char* Ab = AGc + buf * 8192;
            const uint32_t r0 = (uint32_t)(mw * 16 + gid);
            #pragma unroll
            for (int nb = 0; nb < 4; nb++) {
                int col = nw1 * 32 + nb * 8 + tig * 2;
                float bx = b1s[col], by = b1s[col + 1];
                float h0 = geluf(acc1[nb][0] + bx);
                float h1 = geluf(acc1[nb][1] + by);
                float h2 = geluf(acc1[nb][2] + bx);
                float h3 = geluf(acc1[nb][3] + by);
                uint32_t p01 = (uint32_t)__half_as_ushort(__float2half_rn(h0))
                             | ((uint32_t)__half_as_ushort(__float2half_rn(h1)) << 16);
                uint32_t p23 = (uint32_t)__half_as_ushort(__float2half_rn(h2))
                             | ((uint32_t)__half_as_ushort(__float2half_rn(h3)) << 16);
                uint32_t cb = (uint32_t)(nw1 * 64 + nb * 16);
                *(uint32_t*)(Ab + offA(r0,     cb) + tig * 4) = p01;
                *(uint32_t*)(Ab + offA(r0 + 8, cb) + tig * 4) = p23;
            }
        }
        BARG(barid);   // A[buf] visible to the whole group

        // ---- GEMM2: warp = 16 rows x 64 cols; single fp16 product ----
        float acc[8][4];
        #pragma unroll
        for (int nb = 0; nb < 8; nb++)
            #pragma unroll
            for (int j = 0; j < 4; j++) acc[nb][j] = 0.0f;

        const uint32_t aBase = AG + (uint32_t)(buf << 13) + aOff;
        #pragma unroll
        for (int kb = 0; kb < 8; kb++) {
            const uint32_t kxA = ((uint32_t)(kb * 32) + chA) ^ swz;
            const uint32_t kxB = ((uint32_t)(kb * 32) + chB) ^ swz;

            uint32_t ah[4];
            LDSM4(ah, aBase + kxA);

            #pragma unroll
            for (int p = 0; p < 4; p++) {
                uint32_t bh[4];
                LDSM4(bh, bCst + (uint32_t)(p * 4096) + kxB);
                mma16816(acc[2*p],   ah, bh);
                mma16816(acc[2*p+1], ah, bh + 2);
            }
        }

        // ---- epilogue: +b2, per-row LN partials via quad shuffles ----
        #pragma unroll
        for (int nb = 0; nb < 8; nb++) {
            int col = nw * 64 + nb * 8 + tig * 2;
            float bx = b2s[col], by = b2s[col + 1];
            acc[nb][0] += bx; acc[nb][1] += by;
            acc[nb][2] += bx; acc[nb][3] += by;
        }
        {
            float s0 = 0.f, q0 = 0.f, s1 = 0.f, q1 = 0.f;
            #pragma unroll
            for (int nb = 0; nb < 8; nb++) {
                s0 += acc[nb][0] + acc[nb][1];
                q0 = fmaf(acc[nb][0], acc[nb][0], q0);
                q0 = fmaf(acc[nb][1], acc[nb][1], q0);
                s1 += acc[nb][2] + acc[nb][3];
                q1 = fmaf(acc[nb][2], acc[nb][2], q1);
                q1 = fmaf(acc[nb][3], acc[nb][3], q1);
            }
            #pragma unroll
            for (int o = 1; o <= 2; o <<= 1) {
                s0 += __shfl_xor_sync(0xffffffffu, s0, o);
                q0 += __shfl_xor_sync(0xffffffffu, q0, o);
                s1 += __shfl_xor_sync(0xffffffffu, s1, o);
                q1 += __shfl_xor_sync(0xffffffffu, q1, o);
            }
            if (tig == 0) {
                int r = mw * 16 + gid;
                partS[r*4 + nw] = s0; partQ[r*4 + nw] = q0;
                partS[(r+8)*4 + nw] = s1; partQ[(r+8)*4 + nw] = q1;
            }
        }
        BARG(barid);

        // ---- normalize + store ----
        #pragma unroll
        for (int half = 0; half < 2; half++) {
            int r = mw * 16 + gid + half * 8;
            float4 S4 = *(float4*)&partS[r*4];
            float4 Q4 = *(float4*)&partQ[r*4];
            float sum = (S4.x + S4.y) + (S4.z + S4.w);
            float sq  = (Q4.x + Q4.y) + (Q4.z + Q4.w);
            float mu = sum * (1.0f/256.0f);
            float var = sq * (1.0f/256.0f) - mu * mu;
            float rs = rsqrtf(var + 1e-5f);
            int grow = rowBase + r;
            if (grow < nRows) {
                float* op = out + (size_t)grow * 256;
                #pragma unroll
                for (int nb = 0; nb < 8; nb++) {
                    int col = nw * 64 + nb * 8 + tig * 2;
                    float va = acc[nb][half*2+0];
                    float vb = acc[nb][half*2+1];
                    float2 o2;
                    o2.x = fmaf((va - mu) * rs, gos[col],   bos[col]);
                    o2.y = fmaf((vb - mu) * rs, gos[col+1], bos[col+1]);
                    *(float2*)(op + col) = o2;
                }
            }
        }
        buf ^= 1;
    }
}

extern "C" void kernel_launch(void* const* d_in, const int* in_sizes, int n_in,
                              void* d_out, int out_size) {
    const float* x  = (const float*)d_in[0];
    const float* gm = (const float*)d_in[1];
    const float* bm = (const float*)d_in[2];
    const float* gs = (const float*)d_in[3];
    const float* bs = (const float*)d_in[4];
    const float* W1 = (const float*)d_in[5];
    const float* b1 = (const float*)d_in[6];
    const float* W2 = (const float*)d_in[7];
    const float* b2 = (const float*)d_in[8];
    const float* go = (const float*)d_in[9];
    const float* bo = (const float*)d_in[10];

    int B = in_sizes[0] / TLEN;
    int nRows = B * NP;

    cudaFuncSetAttribute(mlp_kernel, cudaFuncAttributeMaxDynamicSharedMemorySize,
                         SMEM_BYTES);

    feat_kernel<<<B, 256>>>(x, gm, bm, gs, bs);
    mlp_kernel<<<148, NTHREADS, SMEM_BYTES>>>(
        W1, b1, W2, b2, go, bo, (float*)d_out, nRows);
}

// round 16
// speedup vs baseline: 2.6279x; 1.0242x over previous
#include <cuda_runtime.h>
#include <cuda_fp16.h>
#include <cstdint>
#include <stdint.h>
#include <math.h>

#define TLEN    6000
#define NP      199
#define PLEN    60
#define PSTRIDE 30
#define NSP     30
#define NFREQ   16
#define NM      13
#define NS      9
#define NFEAT   22
#define GTM     32            // rows per group tile
#define NTHREADS 768
#define MAXROWS (1024*NP)

// fp16 feature rows, padded to 32 (22 real + 10 zeros)
__device__ __half g_F2[(size_t)MAXROWS * 32];

__device__ __forceinline__ float geluf(float v){
    return 0.5f * v * (1.0f + erff(v * 0.7071067811865476f));
}
__device__ __forceinline__ float freqf(int k){
    return (float)(((double)k * 200.0) / 30.0);
}
__device__ __forceinline__ uint32_t smem_u32(const void* p){
    uint32_t a;
    asm("{ .reg .u64 t; cvta.to.shared.u64 t, %1; cvt.u32.u64 %0, t; }"
        : "=r"(a) : "l"(p));
    return a;
}

// mma.sync m16n8k16 fp16 -> f32, accumulate in place
__device__ __forceinline__ void mma16816(float* d, const uint32_t* a,
                                         const uint32_t* b){
    asm volatile(
        "mma.sync.aligned.m16n8k16.row.col.f32.f16.f16.f32 "
        "{%0,%1,%2,%3}, {%4,%5,%6,%7}, {%8,%9}, {%0,%1,%2,%3};"
        : "+f"(d[0]), "+f"(d[1]), "+f"(d[2]), "+f"(d[3])
        : "r"(a[0]), "r"(a[1]), "r"(a[2]), "r"(a[3]), "r"(b[0]), "r"(b[1]));
}
#define LDSM4(R, addr) \
    asm volatile("ldmatrix.sync.aligned.m8n8.x4.shared.b16 {%0,%1,%2,%3}, [%4];" \
        : "=r"((R)[0]), "=r"((R)[1]), "=r"((R)[2]), "=r"((R)[3]) : "r"(addr))
#define BARG(id) \
    asm volatile("bar.sync %0, 256;" :: "r"(id) : "memory")

// ============================================================
// Kernel A: per-patch features + group layernorms -> g_F2 (fp16)
// (unchanged from R15)
// ============================================================
__global__ __launch_bounds__(256) void feat_kernel(
    const float* __restrict__ x,
    const float* __restrict__ gm, const float* __restrict__ bm,
    const float* __restrict__ gs, const float* __restrict__ bs)
{
    __shared__ float sx[TLEN];
    __shared__ float cosT[NFREQ * 16];
    __shared__ float sinT[NFREQ * 16];
    __shared__ float hannS[NSP];
    __shared__ float psdS[NFREQ * 200];

    const int tid = threadIdx.x;
    {
        const float4* xg = (const float4*)(x + (size_t)blockIdx.x * TLEN);
        float4* s4 = (float4*)sx;
        for (int i = tid; i < TLEN/4; i += 256) s4[i] = xg[i];
    }
    for (int i = tid; i < NFREQ*16; i += 256) {
        int k = i >> 4, t = i & 15;
        double sv, cv;
        sincospi(2.0 * (double)(k * t) / 30.0, &sv, &cv);
        cosT[i] = (float)cv;
        sinT[i] = (float)sv;
    }
    if (tid < NSP)
        hannS[tid] = (float)(0.5 * (1.0 - cospi(2.0 * (double)tid / 30.0)));
    __syncthreads();
    if (tid >= NP) return;

    const int off = tid * PSTRIDE;
    __half* frow = &g_F2[((size_t)blockIdx.x * NP + tid) * 32];

    float v0 = sx[off];
    float mx = v0, mn = v0, sum = v0;
    float sumsq = v0 * v0;
    float amax = fabsf(v0); int aidx = 0;
    float prev = v0;
    float tsg = v0 + 1e-10f;
    int   sprev = (tsg > 0.0f) - (tsg < 0.0f);
    float dmax = -INFINITY, dmin = INFINITY, dabs = 0.0f;
    int zc = 0;
    #pragma unroll
    for (int t = 1; t < PLEN; t++) {
        float v = sx[off + t];
        mx = fmaxf(mx, v); mn = fminf(mn, v);
        sum += v; sumsq = fmaf(v, v, sumsq);
        float a = fabsf(v);
        if (a > amax) { amax = a; aidx = t; }
        float d = v - prev;
        dmax = fmaxf(dmax, d); dmin = fminf(dmin, d); dabs += fabsf(d);
        float tg = v + 1e-10f;
        int sg = (tg > 0.0f) - (tg < 0.0f);
        zc += (sg != sprev);
        sprev = sg; prev = v;
    }
    float mean = sum * (1.0f/60.0f);

    float m2 = 0.f, m3 = 0.f, m4 = 0.f;
    #pragma unroll
    for (int t = 0; t < PLEN; t++) {
        float c = sx[off + t] - mean;
        float c2 = c * c;
        m2 += c2; m3 = fmaf(c2, c, m3); m4 = fmaf(c2, c2, m4);
    }
    m2 *= (1.0f/60.0f); m3 *= (1.0f/60.0f); m4 *= (1.0f/60.0f);
    float stdv = sqrtf(m2);

    {
        float morph[NM];
        morph[0] = mx; morph[1] = mn; morph[2] = mx - mn; morph[3] = mean;
        morph[4] = stdv;
        morph[5] = (float)aidx * (1.0f/60.0f);
        morph[6] = dmax; morph[7] = dmin;
        morph[8] = dabs * (1.0f/59.0f);
        morph[9] = (float)zc * (1.0f/60.0f);
        morph[10] = sumsq;
        morph[11] = m4 / (m2 * m2) - 3.0f;
        morph[12] = m3 / (m2 * stdv);
        #pragma unroll
        for (int i = 0; i < NM; i++) if (!isfinite(morph[i])) morph[i] = 0.0f;

        float mu = 0.f;
        #pragma unroll
        for (int i = 0; i < NM; i++) mu += morph[i];
        mu *= (1.0f/13.0f);
        float var = 0.f;
        #pragma unroll
        for (int i = 0; i < NM; i++) { float d = morph[i]-mu; var = fmaf(d,d,var); }
        var *= (1.0f/13.0f);
        float scl = rsqrtf(var + 1e-5f);
        #pragma unroll
        for (int i = 0; i < NM; i++)
            frow[i] = __float2half_rn(fmaf((morph[i]-mu)*scl, gm[i], bm[i]));
    }

    float ye0[16], yo0[15], ye1[16], yo1[15], ye2[16], yo2[15];

    #define FOLD_SEG(YE, YO, SB) { \
        float s = 0.f; \
        _Pragma("unroll") \
        for (int t = 0; t < NSP; t++) s += sx[(SB) + t]; \
        s *= (1.0f/30.0f); \
        float s2 = 2.0f * s; \
        _Pragma("unroll") \
        for (int t = 1; t < 15; t++) { \
            float a = sx[(SB) + t]; \
            float b = sx[(SB) + 30 - t]; \
            float w = hannS[t]; \
            YE[t] = (a + b - s2) * w; \
            YO[t] = (a - b) * w; \
        } \
        YE[15] = sx[(SB) + 15] - s; \
    }

    FOLD_SEG(ye0, yo0, off)
    FOLD_SEG(ye1, yo1, off + 15)
    FOLD_SEG(ye2, yo2, off + 30)
    #undef FOLD_SEG

    for (int k = 0; k < NFREQ; k++) {
        const float* ck = &cosT[k * 16];
        const float* sk = &sinT[k * 16];
        float re0 = 0.f, im0 = 0.f, re1 = 0.f, im1 = 0.f, re2 = 0.f, im2 = 0.f;
        #pragma unroll
        for (int t = 1; t < 15; t++) {
            float c = ck[t], si = sk[t];
            re0 = fmaf(ye0[t], c, re0); im0 = fmaf(yo0[t], si, im0);
            re1 = fmaf(ye1[t], c, re1); im1 = fmaf(yo1[t], si, im1);
            re2 = fmaf(ye2[t], c, re2); im2 = fmaf(yo2[t], si, im2);
        }
        float c15 = ck[15];
        re0 = fmaf(ye0[15], c15, re0);
        re1 = fmaf(ye1[15], c15, re1);
        re2 = fmaf(ye2[15], c15, re2);
        float p = fmaf(re0,re0,im0*im0) + fmaf(re1,re1,im1*im1) + fmaf(re2,re2,im2*im2);
        float sc = (k == 0 || k == NFREQ-1) ? (1.0f/6750.0f) : (2.0f/6750.0f);
        psdS[k*200 + tid] = p * sc;
    }

    float psd[NFREQ];
    #pragma unroll
    for (int k = 0; k < NFREQ; k++) psd[k] = psdS[k*200 + tid];

    float total = 0.f;
    #pragma unroll
    for (int k = 0; k < NFREQ; k++) total += psd[k];
    total += 1e-12f;
    float inv = 1.0f / total;

    float b1v = psd[1];
    float b3v = psd[2] + psd[3] + psd[4];
    float b4v = 0.f;
    #pragma unroll
    for (int k = 5; k <= 14; k++) b4v += psd[k];

    float pmax = psd[0]; int pkk = 0;
    #pragma unroll
    for (int k = 1; k < NFREQ; k++)
        if (psd[k] > pmax) { pmax = psd[k]; pkk = k; }

    float thr = 0.95f * total;
    float csum = 0.f; int ek = 0; bool fnd = false;
    #pragma unroll
    for (int k = 0; k < NFREQ; k++) {
        csum += psd[k];
        if (!fnd && csum >= thr) { ek = k; fnd = true; }
    }
    float ent = 0.f;
    #pragma unroll
    for (int k = 0; k < NFREQ; k++) {
        float pn = psd[k] * inv;
        ent -= pn * log2f(pn + 1e-12f);
    }

    float spec[NS];
    spec[0] = 0.0f;
    spec[1] = b1v * inv;
    spec[2] = 0.0f;
    spec[3] = b3v * inv;
    spec[4] = b4v * inv;
    spec[5] = freqf(pkk);
    spec[6] = freqf(ek);
    spec[7] = ent;
    spec[8] = total;
    #pragma unroll
    for (int i = 0; i < NS; i++) if (!isfinite(spec[i])) spec[i] = 0.0f;

    {
        float mu = 0.f;
        #pragma unroll
        for (int i = 0; i < NS; i++) mu += spec[i];
        mu *= (1.0f/9.0f);
        float var = 0.f;
        #pragma unroll
        for (int i = 0; i < NS; i++) { float d = spec[i]-mu; var = fmaf(d,d,var); }
        var *= (1.0f/9.0f);
        float scl = rsqrtf(var + 1e-5f);
        #pragma unroll
        for (int i = 0; i < NS; i++)
            frow[NM + i] = __float2half_rn(fmaf((spec[i]-mu)*scl, gs[i], bs[i]));
    }
    #pragma unroll
    for (int i = NFEAT; i < 32; i++) frow[i] = __ushort_as_half((unsigned short)0);
}

// ============================================================
// Kernel B: persistent MLP, both GEMMs on tensor cores (fp16)
// 3 staggered warp-groups x 32-row tiles; GEMM2 warp tile 32x32
// ============================================================
#define OFF_B      0          // W2 panel 65536
#define OFF_W1P    65536      // W1 fp16 panel 128x128B = 16384
#define OFF_AG     81920      // 3 groups x 2 bufs x 8192 = 49152
#define OFF_B1     131072     // 512
#define OFF_B2     131584     // 1024
#define OFF_GO     132608     // 1024
#define OFF_BO     133632     // 1024
#define OFF_PS     134656     // 3 x 32 x 8 floats = 3072
#define OFF_PQ     137728     // 3072
#define SMEM_BYTES 140800

// XOR swizzle at 16B granularity; 256B rows (A / W2 panels)
__device__ __forceinline__ uint32_t offA(uint32_t row, uint32_t kbyte){
    return row * 256u + (kbyte ^ ((row & 7u) << 4));
}
// 128B rows (W1 panel)
__device__ __forceinline__ uint32_t offW(uint32_t row, uint32_t kbyte){
    return row * 128u + (kbyte ^ ((row & 7u) << 4));
}

__global__ __launch_bounds__(NTHREADS, 1) void mlp_kernel(
    const float* __restrict__ W1, const float* __restrict__ b1,
    const float* __restrict__ W2, const float* __restrict__ b2,
    const float* __restrict__ go, const float* __restrict__ bo,
    float* __restrict__ out, int nRows)
{
    extern __shared__ char smc[];
    const uint32_t sm32 = smem_u32(smc);
    float* b1s = (float*)(smc + OFF_B1);
    float* b2s = (float*)(smc + OFF_B2);
    float* gos = (float*)(smc + OFF_GO);
    float* bos = (float*)(smc + OFF_BO);

    const int tid  = threadIdx.x;
    const int wid  = tid >> 5;
    const int lane = tid & 31;
    const int gid  = lane >> 2;   // 0..7
    const int tig  = lane & 3;    // 0..3

    const int g    = wid >> 3;    // warp group 0/1/2
    const int wg   = wid & 7;     // warp within group
    const int barid = 1 + g;

    // ---- one-time setup ----
    if (tid < 128) b1s[tid] = b1[tid];
    for (int i = tid; i < 256; i += NTHREADS) { b2s[i]=b2[i]; gos[i]=go[i]; bos[i]=bo[i]; }

    // W2 [k][n] -> B_T panel [n][kbyte] fp16, swizzled (256B rows)
    for (int i = tid; i < 128*256; i += NTHREADS) {
        int k = i >> 8, n = i & 255;
        uint32_t o = offA((uint32_t)n, (uint32_t)(2*k));
        *(__half*)(smc + OFF_B + o) = __float2half_rn(W2[i]);
    }
    // W1 [k][n] -> panel [n][kbyte] fp16, K padded to 32 (128B rows)
    for (int i = tid; i < 128*32; i += NTHREADS) {
        int n = i >> 5, k = i & 31;
        float v = (k < NFEAT) ? W1[k*128 + n] : 0.0f;
        uint32_t o = offW((uint32_t)n, (uint32_t)(2*k));
        *(__half*)(smc + OFF_W1P + o) = __float2half_rn(v);
    }
    __syncthreads();

    float* partS = (float*)(smc + OFF_PS) + g * 256;  // [32][8]
    float* partQ = (float*)(smc + OFF_PQ) + g * 256;

    const int mw  = wg & 1;               // GEMM1: 16-row half
    const int nw1 = wg >> 1;              // GEMM1: 32-col quarter of 128
    const int nw  = wg;                   // GEMM2: 32-col slice of 256
    const int nTiles = (nRows + GTM - 1) / GTM;   // 6368

    // group A panel base (2 buffers x 8192)
    const char* AGc = smc + OFF_AG + g * 16384;
    const uint32_t AG = sm32 + OFF_AG + (uint32_t)g * 16384u;

    // ---- ldmatrix / address invariants ----
    const uint32_t swz  = (uint32_t)(lane & 7) << 4;
    const uint32_t chA  = (uint32_t)((lane >> 4) & 1) * 16;
    const uint32_t rA   = (uint32_t)((lane & 7) + ((lane >> 3) & 1) * 8);
    const uint32_t aOff = rA * 256;
    const uint32_t chB  = (uint32_t)((lane >> 3) & 1) * 16;
    const uint32_t bCst = sm32 + OFF_B
                        + (uint32_t)(nw * 32 + (lane & 7)) * 256
                        + (uint32_t)((lane >> 4) & 1) * 2048;
    // W1 frags: col-major B pattern over 128B rows
    const uint32_t nW1  = (uint32_t)(nw1 * 32 + (lane & 7) + ((lane >> 4) & 1) * 8);
    const uint32_t w1Base = sm32 + OFF_W1P + nW1 * 128u;
    const uint32_t swW  = (nW1 & 7u) << 4;

    int buf = 0;
    for (int tile = blockIdx.x * 3 + g; tile < nTiles; tile += 444) {
        const int rowBase = tile * GTM;

        // ---- GEMM1 on MMA: warp = 16 rows x 32 cols, K=32 ----
        {
            float acc1[4][4];
            #pragma unroll
            for (int nb = 0; nb < 4; nb++)
                #pragma unroll
                for (int j = 0; j < 4; j++) acc1[nb][j] = 0.0f;

            const __half* f0 = g_F2 + (size_t)(rowBase + mw*16 + gid) * 32 + tig * 2;
            #pragma unroll
            for (int kb = 0; kb < 2; kb++) {
                uint32_t af[4];
                af[0] = *(const uint32_t*)(f0 + kb*16);
                af[1] = *(const uint32_t*)(f0 + kb*16 + 256);
                af[2] = *(const uint32_t*)(f0 + kb*16 + 8);
                af[3] = *(const uint32_t*)(f0 + kb*16 + 264);
                uint32_t kxW = ((uint32_t)(kb * 32) + chB) ^ swW;
                uint32_t wf0[4], wf1[4];
                LDSM4(wf0, w1Base + kxW);
                LDSM4(wf1, w1Base + 2048u + kxW);
                mma16816(acc1[0], af, wf0);
                mma16816(acc1[1], af, wf0 + 2);
                mma16816(acc1[2], af, wf1);
                mma16816(acc1[3], af, wf1 + 2);
            }
            // bias + GELU + pack fp16 -> A panel[buf]
            const char* Ab = AGc + buf * 8192;
            const uint32_t r0 = (uint32_t)(mw * 16 + gid);
            #pragma unroll
            for (int nb = 0; nb < 4; nb++) {
                int col = nw1 * 32 + nb * 8 + tig * 2;
                float bx = b1s[col], by = b1s[col + 1];
                float h0 = geluf(acc1[nb][0] + bx);
                float h1 = geluf(acc1[nb][1] + by);
                float h2 = geluf(acc1[nb][2] + bx);
                float h3 = geluf(acc1[nb][3] + by);
                uint32_t p01 = (uint32_t)__half_as_ushort(__float2half_rn(h0))
                             | ((uint32_t)__half_as_ushort(__float2half_rn(h1)) << 16);
                uint32_t p23 = (uint32_t)__half_as_ushort(__float2half_rn(h2))
                             | ((uint32_t)__half_as_ushort(__float2half_rn(h3)) << 16);
                uint32_t cb = (uint32_t)(nw1 * 64 + nb * 16);
                *(uint32_t*)(Ab + offA(r0,     cb) + tig * 4) = p01;
                *(uint32_t*)(Ab + offA(r0 + 8, cb) + tig * 4) = p23;
            }
        }
        BARG(barid);   // A[buf] visible to the whole group

        // ---- GEMM2: warp = 32 rows (2 m-blocks) x 32 cols (4 n-blocks) ----
        float acc[2][4][4];
        #pragma unroll
        for (int m = 0; m < 2; m++)
            #pragma unroll
            for (int nb = 0; nb < 4; nb++)
                #pragma unroll
                for (int j = 0; j < 4; j++) acc[m][nb][j] = 0.0f;

        const uint32_t aBase = AG + (uint32_t)(buf << 13) + aOff;
        #pragma unroll
        for (int kb = 0; kb < 8; kb++) {
            const uint32_t kxA = ((uint32_t)(kb * 32) + chA) ^ swz;
            const uint32_t kxB = ((uint32_t)(kb * 32) + chB) ^ swz;

            uint32_t ah0[4], ah1[4];
            LDSM4(ah0, aBase + kxA);            // rows 0-15
            LDSM4(ah1, aBase + 4096u + kxA);    // rows 16-31

            #pragma unroll
            for (int p = 0; p < 2; p++) {
                uint32_t bh[4];
                LDSM4(bh, bCst + (uint32_t)(p * 4096) + kxB);
                mma16816(acc[0][2*p],   ah0, bh);
                mma16816(acc[0][2*p+1], ah0, bh + 2);
                mma16816(acc[1][2*p],   ah1, bh);
                mma16816(acc[1][2*p+1], ah1, bh + 2);
            }
        }

        // ---- epilogue: +b2, per-row LN partials via quad shuffles ----
        #pragma unroll
        for (int nb = 0; nb < 4; nb++) {
            int col = nw * 32 + nb * 8 + tig * 2;
            float bx = b2s[col], by = b2s[col + 1];
            #pragma unroll
            for (int m = 0; m < 2; m++) {
                acc[m][nb][0] += bx; acc[m][nb][1] += by;
                acc[m][nb][2] += bx; acc[m][nb][3] += by;
            }
        }
        #pragma unroll
        for (int m = 0; m < 2; m++) {
            float s0 = 0.f, q0 = 0.f, s1 = 0.f, q1 = 0.f;
            #pragma unroll
            for (int nb = 0; nb < 4; nb++) {
                s0 += acc[m][nb][0] + acc[m][nb][1];
                q0 = fmaf(acc[m][nb][0], acc[m][nb][0], q0);
                q0 = fmaf(acc[m][nb][1], acc[m][nb][1], q0);
                s1 += acc[m][nb][2] + acc[m][nb][3];
                q1 = fmaf(acc[m][nb][2], acc[m][nb][2], q1);
                q1 = fmaf(acc[m][nb][3], acc[m][nb][3], q1);
            }
            #pragma unroll
            for (int o = 1; o <= 2; o <<= 1) {
                s0 += __shfl_xor_sync(0xffffffffu, s0, o);
                q0 += __shfl_xor_sync(0xffffffffu, q0, o);
                s1 += __shfl_xor_sync(0xffffffffu, s1, o);
                q1 += __shfl_xor_sync(0xffffffffu, q1, o);
            }
            if (tig == 0) {
                int r = m * 16 + gid;
                partS[r*8 + nw] = s0; partQ[r*8 + nw] = q0;
                partS[(r+8)*8 + nw] = s1; partQ[(r+8)*8 + nw] = q1;
            }
        }
        BARG(barid);

        // ---- normalize + store ----
        #pragma unroll
        for (int m = 0; m < 2; m++) {
            #pragma unroll
            for (int half = 0; half < 2; half++) {
                int r = m * 16 + gid + half * 8;
                float4 Sa = *(float4*)&partS[r*8];
                float4 Sb = *(float4*)&partS[r*8 + 4];
                float4 Qa = *(float4*)&partQ[r*8];
                float4 Qb = *(float4*)&partQ[r*8 + 4];
                float sum = ((Sa.x + Sa.y) + (Sa.z + Sa.w))
                          + ((Sb.x + Sb.y) + (Sb.z + Sb.w));
                float sq  = ((Qa.x + Qa.y) + (Qa.z + Qa.w))
                          + ((Qb.x + Qb.y) + (Qb.z + Qb.w));
                float mu = sum * (1.0f/256.0f);
                float var = sq * (1.0f/256.0f) - mu * mu;
                float rs = rsqrtf(var + 1e-5f);
                int grow = rowBase + r;
                if (grow < nRows) {
                    float* op = out + (size_t)grow * 256;
                    #pragma unroll
                    for (int nb = 0; nb < 4; nb++) {
                        int col = nw * 32 + nb * 8 + tig * 2;
                        float va = acc[m][nb][half*2+0];
                        float vb = acc[m][nb][half*2+1];
                        float2 o2;
                        o2.x = fmaf((va - mu) * rs, gos[col],   bos[col]);
                        o2.y = fmaf((vb - mu) * rs, gos[col+1], bos[col+1]);
                        *(float2*)(op + col) = o2;
                    }
                }
            }
        }
        buf ^= 1;
    }
}

extern "C" void kernel_launch(void* const* d_in, const int* in_sizes, int n_in,
                              void* d_out, int out_size) {
    const float* x  = (const float*)d_in[0];
    const float* gm = (const float*)d_in[1];
    const float* bm = (const float*)d_in[2];
    const float* gs = (const float*)d_in[3];
    const float* bs = (const float*)d_in[4];
    const float* W1 = (const float*)d_in[5];
    const float* b1 = (const float*)d_in[6];
    const float* W2 = (const float*)d_in[7];
    const float* b2 = (const float*)d_in[8];
    const float* go = (const float*)d_in[9];
    const float* bo = (const float*)d_in[10];

    int B = in_sizes[0] / TLEN;
    int nRows = B * NP;

    cudaFuncSetAttribute(mlp_kernel, cudaFuncAttributeMaxDynamicSharedMemorySize,
                         SMEM_BYTES);

    feat_kernel<<<B, 256>>>(x, gm, bm, gs, bs);
    mlp_kernel<<<148, NTHREADS, SMEM_BYTES>>>(
        W1, b1, W2, b2, go, bo, (float*)d_out, nRows);
}

// round 17
// speedup vs baseline: 2.9554x; 1.1246x over previous
#include <cuda_runtime.h>
#include <cuda_fp16.h>
#include <cstdint>
#include <stdint.h>
#include <math.h>

#define TLEN    6000
#define NP      199
#define PLEN    60
#define PSTRIDE 30
#define NSP     30
#define NFREQ   16
#define NM      13
#define NS      9
#define NFEAT   22
#define GTM     32            // rows per group tile
#define NTHREADS 768
#define MAXROWS (1024*NP)

// fp16 feature rows, padded to 32 (22 real + 10 zeros)
__device__ __half g_F2[(size_t)MAXROWS * 32];

__device__ __forceinline__ float geluf(float v){
    return 0.5f * v * (1.0f + erff(v * 0.7071067811865476f));
}
__device__ __forceinline__ float freqf(int k){
    return (float)(((double)k * 200.0) / 30.0);
}
__device__ __forceinline__ uint32_t smem_u32(const void* p){
    uint32_t a;
    asm("{ .reg .u64 t; cvta.to.shared.u64 t, %1; cvt.u32.u64 %0, t; }"
        : "=r"(a) : "l"(p));
    return a;
}

// mma.sync m16n8k16 fp16 -> f32, accumulate in place
__device__ __forceinline__ void mma16816(float* d, const uint32_t* a,
                                         const uint32_t* b){
    asm volatile(
        "mma.sync.aligned.m16n8k16.row.col.f32.f16.f16.f32 "
        "{%0,%1,%2,%3}, {%4,%5,%6,%7}, {%8,%9}, {%0,%1,%2,%3};"
        : "+f"(d[0]), "+f"(d[1]), "+f"(d[2]), "+f"(d[3])
        : "r"(a[0]), "r"(a[1]), "r"(a[2]), "r"(a[3]), "r"(b[0]), "r"(b[1]));
}
#define LDSM4(R, addr) \
    asm volatile("ldmatrix.sync.aligned.m8n8.x4.shared.b16 {%0,%1,%2,%3}, [%4];" \
        : "=r"((R)[0]), "=r"((R)[1]), "=r"((R)[2]), "=r"((R)[3]) : "r"(addr))
#define BARG(id) \
    asm volatile("bar.sync %0, 256;" :: "r"(id) : "memory")

// ============================================================
// Kernel A: per-patch features + group layernorms -> g_F2 (fp16)
//  - single-pass raw moments (no 2nd central-moment pass)
//  - packed 4x uint4 output stores
// ============================================================
__global__ __launch_bounds__(256) void feat_kernel(
    const float* __restrict__ x,
    const float* __restrict__ gm, const float* __restrict__ bm,
    const float* __restrict__ gs, const float* __restrict__ bs)
{
    __shared__ float sx[TLEN];
    __shared__ float cosT[NFREQ * 16];
    __shared__ float sinT[NFREQ * 16];
    __shared__ float hannS[NSP];
    __shared__ float psdS[NFREQ * 200];

    const int tid = threadIdx.x;
    {
        const float4* xg = (const float4*)(x + (size_t)blockIdx.x * TLEN);
        float4* s4 = (float4*)sx;
        for (int i = tid; i < TLEN/4; i += 256) s4[i] = xg[i];
    }
    for (int i = tid; i < NFREQ*16; i += 256) {
        int k = i >> 4, t = i & 15;
        double sv, cv;
        sincospi(2.0 * (double)(k * t) / 30.0, &sv, &cv);
        cosT[i] = (float)cv;
        sinT[i] = (float)sv;
    }
    if (tid < NSP)
        hannS[tid] = (float)(0.5 * (1.0 - cospi(2.0 * (double)tid / 30.0)));
    __syncthreads();
    if (tid >= NP) return;

    const int off = tid * PSTRIDE;

    float fb[NFEAT];

    // ---- single streaming pass: extrema, diffs, zc, raw moments s1..s4 ----
    float v0 = sx[off];
    float mx = v0, mn = v0;
    float s1 = v0, s2 = v0*v0, s3 = v0*v0*v0, s4 = (v0*v0)*(v0*v0);
    float amax = fabsf(v0); int aidx = 0;
    float prev = v0;
    float tsg = v0 + 1e-10f;
    int   sprev = (tsg > 0.0f) - (tsg < 0.0f);
    float dmax = -INFINITY, dmin = INFINITY, dabs = 0.0f;
    int zc = 0;
    #pragma unroll
    for (int t = 1; t < PLEN; t++) {
        float v = sx[off + t];
        float v2 = v * v;
        mx = fmaxf(mx, v); mn = fminf(mn, v);
        s1 += v; s2 = fmaf(v, v, s2);
        s3 = fmaf(v2, v, s3); s4 = fmaf(v2, v2, s4);
        float a = fabsf(v);
        if (a > amax) { amax = a; aidx = t; }
        float d = v - prev;
        dmax = fmaxf(dmax, d); dmin = fminf(dmin, d); dabs += fabsf(d);
        float tg = v + 1e-10f;
        int sg = (tg > 0.0f) - (tg < 0.0f);
        zc += (sg != sprev);
        sprev = sg; prev = v;
    }
    float mean = s1 * (1.0f/60.0f);
    float e2 = s2 * (1.0f/60.0f);
    float e3 = s3 * (1.0f/60.0f);
    float e4 = s4 * (1.0f/60.0f);
    float mu2 = mean * mean;
    float m2 = e2 - mu2;
    float m3 = e3 - 3.0f*mean*e2 + 2.0f*mean*mu2;
    float m4 = e4 - 4.0f*mean*e3 + 6.0f*mu2*e2 - 3.0f*mu2*mu2;
    float stdv = sqrtf(m2);

    {
        float morph[NM];
        morph[0] = mx; morph[1] = mn; morph[2] = mx - mn; morph[3] = mean;
        morph[4] = stdv;
        morph[5] = (float)aidx * (1.0f/60.0f);
        morph[6] = dmax; morph[7] = dmin;
        morph[8] = dabs * (1.0f/59.0f);
        morph[9] = (float)zc * (1.0f/60.0f);
        morph[10] = s2;
        morph[11] = m4 / (m2 * m2) - 3.0f;
        morph[12] = m3 / (m2 * stdv);
        #pragma unroll
        for (int i = 0; i < NM; i++) if (!isfinite(morph[i])) morph[i] = 0.0f;

        float mu = 0.f;
        #pragma unroll
        for (int i = 0; i < NM; i++) mu += morph[i];
        mu *= (1.0f/13.0f);
        float var = 0.f;
        #pragma unroll
        for (int i = 0; i < NM; i++) { float d = morph[i]-mu; var = fmaf(d,d,var); }
        var *= (1.0f/13.0f);
        float scl = rsqrtf(var + 1e-5f);
        #pragma unroll
        for (int i = 0; i < NM; i++)
            fb[i] = fmaf((morph[i]-mu)*scl, gm[i], bm[i]);
    }

    float ye0[16], yo0[15], ye1[16], yo1[15], ye2[16], yo2[15];

    #define FOLD_SEG(YE, YO, SB) { \
        float s = 0.f; \
        _Pragma("unroll") \
        for (int t = 0; t < NSP; t++) s += sx[(SB) + t]; \
        s *= (1.0f/30.0f); \
        float s2_ = 2.0f * s; \
        _Pragma("unroll") \
        for (int t = 1; t < 15; t++) { \
            float a = sx[(SB) + t]; \
            float b = sx[(SB) + 30 - t]; \
            float w = hannS[t]; \
            YE[t] = (a + b - s2_) * w; \
            YO[t] = (a - b) * w; \
        } \
        YE[15] = sx[(SB) + 15] - s; \
    }

    FOLD_SEG(ye0, yo0, off)
    FOLD_SEG(ye1, yo1, off + 15)
    FOLD_SEG(ye2, yo2, off + 30)
    #undef FOLD_SEG

    for (int k = 0; k < NFREQ; k++) {
        const float* ck = &cosT[k * 16];
        const float* sk = &sinT[k * 16];
        float re0 = 0.f, im0 = 0.f, re1 = 0.f, im1 = 0.f, re2 = 0.f, im2 = 0.f;
        #pragma unroll
        for (int t = 1; t < 15; t++) {
            float c = ck[t], si = sk[t];
            re0 = fmaf(ye0[t], c, re0); im0 = fmaf(yo0[t], si, im0);
            re1 = fmaf(ye1[t], c, re1); im1 = fmaf(yo1[t], si, im1);
            re2 = fmaf(ye2[t], c, re2); im2 = fmaf(yo2[t], si, im2);
        }
        float c15 = ck[15];
        re0 = fmaf(ye0[15], c15, re0);
        re1 = fmaf(ye1[15], c15, re1);
        re2 = fmaf(ye2[15], c15, re2);
        float p = fmaf(re0,re0,im0*im0) + fmaf(re1,re1,im1*im1) + fmaf(re2,re2,im2*im2);
        float sc = (k == 0 || k == NFREQ-1) ? (1.0f/6750.0f) : (2.0f/6750.0f);
        psdS[k*200 + tid] = p * sc;
    }

    float psd[NFREQ];
    #pragma unroll
    for (int k = 0; k < NFREQ; k++) psd[k] = psdS[k*200 + tid];

    float total = 0.f;
    #pragma unroll
    for (int k = 0; k < NFREQ; k++) total += psd[k];
    total += 1e-12f;
    float inv = 1.0f / total;

    float b1v = psd[1];
    float b3v = psd[2] + psd[3] + psd[4];
    float b4v = 0.f;
    #pragma unroll
    for (int k = 5; k <= 14; k++) b4v += psd[k];

    float pmax = psd[0]; int pkk = 0;
    #pragma unroll
    for (int k = 1; k < NFREQ; k++)
        if (psd[k] > pmax) { pmax = psd[k]; pkk = k; }

    float thr = 0.95f * total;
    float csum = 0.f; int ek = 0; bool fnd = false;
    #pragma unroll
    for (int k = 0; k < NFREQ; k++) {
        csum += psd[k];
        if (!fnd && csum >= thr) { ek = k; fnd = true; }
    }
    float ent = 0.f;
    #pragma unroll
    for (int k = 0; k < NFREQ; k++) {
        float pn = psd[k] * inv;
        ent -= pn * log2f(pn + 1e-12f);
    }

    {
        float spec[NS];
        spec[0] = 0.0f;
        spec[1] = b1v * inv;
        spec[2] = 0.0f;
        spec[3] = b3v * inv;
        spec[4] = b4v * inv;
        spec[5] = freqf(pkk);
        spec[6] = freqf(ek);
        spec[7] = ent;
        spec[8] = total;
        #pragma unroll
        for (int i = 0; i < NS; i++) if (!isfinite(spec[i])) spec[i] = 0.0f;

        float mu = 0.f;
        #pragma unroll
        for (int i = 0; i < NS; i++) mu += spec[i];
        mu *= (1.0f/9.0f);
        float var = 0.f;
        #pragma unroll
        for (int i = 0; i < NS; i++) { float d = spec[i]-mu; var = fmaf(d,d,var); }
        var *= (1.0f/9.0f);
        float scl = rsqrtf(var + 1e-5f);
        #pragma unroll
        for (int i = 0; i < NS; i++)
            fb[NM + i] = fmaf((spec[i]-mu)*scl, gs[i], bs[i]);
    }

    // ---- pack to fp16 and store as 4 x uint4 ----
    {
        uint32_t pk[16];
        #pragma unroll
        for (int i = 0; i < 11; i++) {
            uint32_t lo = (uint32_t)__half_as_ushort(__float2half_rn(fb[2*i]));
            uint32_t hi = (uint32_t)__half_as_ushort(__float2half_rn(fb[2*i+1]));
            pk[i] = lo | (hi << 16);
        }
        #pragma unroll
        for (int i = 11; i < 16; i++) pk[i] = 0u;

        uint4* dst = (uint4*)&g_F2[((size_t)blockIdx.x * NP + tid) * 32];
        dst[0] = make_uint4(pk[0],  pk[1],  pk[2],  pk[3]);
        dst[1] = make_uint4(pk[4],  pk[5],  pk[6],  pk[7]);
        dst[2] = make_uint4(pk[8],  pk[9],  pk[10], pk[11]);
        dst[3] = make_uint4(pk[12], pk[13], pk[14], pk[15]);
    }
}

// ============================================================
// Kernel B: persistent MLP (unchanged from R16)
// ============================================================
#define OFF_B      0          // W2 panel 65536
#define OFF_W1P    65536      // W1 fp16 panel 128x128B = 16384
#define OFF_AG     81920      // 3 groups x 2 bufs x 8192 = 49152
#define OFF_B1     131072     // 512
#define OFF_B2     131584     // 1024
#define OFF_GO     132608     // 1024
#define OFF_BO     133632     // 1024
#define OFF_PS     134656     // 3 x 32 x 8 floats = 3072
#define OFF_PQ     137728     // 3072
#define SMEM_BYTES 140800

// XOR swizzle at 16B granularity; 256B rows (A / W2 panels)
__device__ __forceinline__ uint32_t offA(uint32_t row, uint32_t kbyte){
    return row * 256u + (kbyte ^ ((row & 7u) << 4));
}
// 128B rows (W1 panel)
__device__ __forceinline__ uint32_t offW(uint32_t row, uint32_t kbyte){
    return row * 128u + (kbyte ^ ((row & 7u) << 4));
}

__global__ __launch_bounds__(NTHREADS, 1) void mlp_kernel(
    const float* __restrict__ W1, const float* __restrict__ b1,
    const float* __restrict__ W2, const float* __restrict__ b2,
    const float* __restrict__ go, const float* __restrict__ bo,
    float* __restrict__ out, int nRows)
{
    extern __shared__ char smc[];
    const uint32_t sm32 = smem_u32(smc);
    float* b1s = (float*)(smc + OFF_B1);
    float* b2s = (float*)(smc + OFF_B2);
    float* gos = (float*)(smc + OFF_GO);
    float* bos = (float*)(smc + OFF_BO);

    const int tid  = threadIdx.x;
    const int wid  = tid >> 5;
    const int lane = tid & 31;
    const int gid  = lane >> 2;   // 0..7
    const int tig  = lane & 3;    // 0..3

    const int g    = wid >> 3;    // warp group 0/1/2
    const int wg   = wid & 7;     // warp within group
    const int barid = 1 + g;

    // ---- one-time setup ----
    if (tid < 128) b1s[tid] = b1[tid];
    for (int i = tid; i < 256; i += NTHREADS) { b2s[i]=b2[i]; gos[i]=go[i]; bos[i]=bo[i]; }

    // W2 [k][n] -> B_T panel [n][kbyte] fp16, swizzled (256B rows)
    for (int i = tid; i < 128*256; i += NTHREADS) {
        int k = i >> 8, n = i & 255;
        uint32_t o = offA((uint32_t)n, (uint32_t)(2*k));
        *(__half*)(smc + OFF_B + o) = __float2half_rn(W2[i]);
    }
    // W1 [k][n] -> panel [n][kbyte] fp16, K padded to 32 (128B rows)
    for (int i = tid; i < 128*32; i += NTHREADS) {
        int n = i >> 5, k = i & 31;
        float v = (k < NFEAT) ? W1[k*128 + n] : 0.0f;
        uint32_t o = offW((uint32_t)n, (uint32_t)(2*k));
        *(__half*)(smc + OFF_W1P + o) = __float2half_rn(v);
    }
    __syncthreads();

    float* partS = (float*)(smc + OFF_PS) + g * 256;  // [32][8]
    float* partQ = (float*)(smc + OFF_PQ) + g * 256;

    const int mw  = wg & 1;               // GEMM1: 16-row half
    const int nw1 = wg >> 1;              // GEMM1: 32-col quarter of 128
    const int nw  = wg;                   // GEMM2: 32-col slice of 256
    const int nTiles = (nRows + GTM - 1) / GTM;   // 6368

    // group A panel base (2 buffers x 8192)
    const char* AGc = smc + OFF_AG + g * 16384;
    const uint32_t AG = sm32 + OFF_AG + (uint32_t)g * 16384u;

    // ---- ldmatrix / address invariants ----
    const uint32_t swz  = (uint32_t)(lane & 7) << 4;
    const uint32_t chA  = (uint32_t)((lane >> 4) & 1) * 16;
    const uint32_t rA   = (uint32_t)((lane & 7) + ((lane >> 3) & 1) * 8);
    const uint32_t aOff = rA * 256;
    const uint32_t chB  = (uint32_t)((lane >> 3) & 1) * 16;
    const uint32_t bCst = sm32 + OFF_B
                        + (uint32_t)(nw * 32 + (lane & 7)) * 256
                        + (uint32_t)((lane >> 4) & 1) * 2048;
    // W1 frags: col-major B pattern over 128B rows
    const uint32_t nW1  = (uint32_t)(nw1 * 32 + (lane & 7) + ((lane >> 4) & 1) * 8);
    const uint32_t w1Base = sm32 + OFF_W1P + nW1 * 128u;
    const uint32_t swW  = (nW1 & 7u) << 4;

    int buf = 0;
    for (int tile = blockIdx.x * 3 + g; tile < nTiles; tile += 444) {
        const int rowBase = tile * GTM;

        // ---- GEMM1 on MMA: warp = 16 rows x 32 cols, K=32 ----
        {
            float acc1[4][4];
            #pragma unroll
            for (int nb = 0; nb < 4; nb++)
                #pragma unroll
                for (int j = 0; j < 4; j++) acc1[nb][j] = 0.0f;

            const __half* f0 = g_F2 + (size_t)(rowBase + mw*16 + gid) * 32 + tig * 2;
            #pragma unroll
            for (int kb = 0; kb < 2; kb++) {
                uint32_t af[4];
                af[0] = *(const uint32_t*)(f0 + kb*16);
                af[1] = *(const uint32_t*)(f0 + kb*16 + 256);
                af[2] = *(const uint32_t*)(f0 + kb*16 + 8);
                af[3] = *(const uint32_t*)(f0 + kb*16 + 264);
                uint32_t kxW = ((uint32_t)(kb * 32) + chB) ^ swW;
                uint32_t wf0[4], wf1[4];
                LDSM4(wf0, w1Base + kxW);
                LDSM4(wf1, w1Base + 2048u + kxW);
                mma16816(acc1[0], af, wf0);
                mma16816(acc1[1], af, wf0 + 2);
                mma16816(acc1[2], af, wf1);
                mma16816(acc1[3], af, wf1 + 2);
            }
            // bias + GELU + pack fp16 -> A panel[buf]
            const char* Ab = AGc + buf * 8192;
            const uint32_t r0 = (uint32_t)(mw * 16 + gid);
            #pragma unroll
            for (int nb = 0; nb < 4; nb++) {
                int col = nw1 * 32 + nb * 8 + tig * 2;
                float bx = b1s[col], by = b1s[col + 1];
                float h0 = geluf(acc1[nb][0] + bx);
                float h1 = geluf(acc1[nb][1] + by);
                float h2 = geluf(acc1[nb][2] + bx);
                float h3 = geluf(acc1[nb][3] + by);
                uint32_t p01 = (uint32_t)__half_as_ushort(__float2half_rn(h0))
                             | ((uint32_t)__half_as_ushort(__float2half_rn(h1)) << 16);
                uint32_t p23 = (uint32_t)__half_as_ushort(__float2half_rn(h2))
                             | ((uint32_t)__half_as_ushort(__float2half_rn(h3)) << 16);
                uint32_t cb = (uint32_t)(nw1 * 64 + nb * 16);
                *(uint32_t*)(Ab + offA(r0,     cb) + tig * 4) = p01;
                *(uint32_t*)(Ab + offA(r0 + 8, cb) + tig * 4) = p23;
            }
        }
        BARG(barid);   // A[buf] visible to the whole group

        // ---- GEMM2: warp = 32 rows (2 m-blocks) x 32 cols (4 n-blocks) ----
        float acc[2][4][4];
        #pragma unroll
        for (int m = 0; m < 2; m++)
            #pragma unroll
            for (int nb = 0; nb < 4; nb++)
                #pragma unroll
                for (int j = 0; j < 4; j++) acc[m][nb][j] = 0.0f;

        const uint32_t aBase = AG + (uint32_t)(buf << 13) + aOff;
        #pragma unroll
        for (int kb = 0; kb < 8; kb++) {
            const uint32_t kxA = ((uint32_t)(kb * 32) + chA) ^ swz;
            const uint32_t kxB = ((uint32_t)(kb * 32) + chB) ^ swz;

            uint32_t ah0[4], ah1[4];
            LDSM4(ah0, aBase + kxA);            // rows 0-15
            LDSM4(ah1, aBase + 4096u + kxA);    // rows 16-31

            #pragma unroll
            for (int p = 0; p < 2; p++) {
                uint32_t bh[4];
                LDSM4(bh, bCst + (uint32_t)(p * 4096) + kxB);
                mma16816(acc[0][2*p],   ah0, bh);
                mma16816(acc[0][2*p+1], ah0, bh + 2);
                mma16816(acc[1][2*p],   ah1, bh);
                mma16816(acc[1][2*p+1], ah1, bh + 2);
            }
        }

        // ---- epilogue: +b2, per-row LN partials via quad shuffles ----
        #pragma unroll
        for (int nb = 0; nb < 4; nb++) {
            int col = nw * 32 + nb * 8 + tig * 2;
            float bx = b2s[col], by = b2s[col + 1];
            #pragma unroll
            for (int m = 0; m < 2; m++) {
                acc[m][nb][0] += bx; acc[m][nb][1] += by;
                acc[m][nb][2] += bx; acc[m][nb][3] += by;
            }
        }
        #pragma unroll
        for (int m = 0; m < 2; m++) {
            float s0 = 0.f, q0 = 0.f, s1 = 0.f, q1 = 0.f;
            #pragma unroll
            for (int nb = 0; nb < 4; nb++) {
                s0 += acc[m][nb][0] + acc[m][nb][1];
                q0 = fmaf(acc[m][nb][0], acc[m][nb][0], q0);
                q0 = fmaf(acc[m][nb][1], acc[m][nb][1], q0);
                s1 += acc[m][nb][2] + acc[m][nb][3];
                q1 = fmaf(acc[m][nb][2], acc[m][nb][2], q1);
                q1 = fmaf(acc[m][nb][3], acc[m][nb][3], q1);
            }
            #pragma unroll
            for (int o = 1; o <= 2; o <<= 1) {
                s0 += __shfl_xor_sync(0xffffffffu, s0, o);
                q0 += __shfl_xor_sync(0xffffffffu, q0, o);
                s1 += __shfl_xor_sync(0xffffffffu, s1, o);
                q1 += __shfl_xor_sync(0xffffffffu, q1, o);
            }
            if (tig == 0) {
                int r = m * 16 + gid;
                partS[r*8 + nw] = s0; partQ[r*8 + nw] = q0;
                partS[(r+8)*8 + nw] = s1; partQ[(r+8)*8 + nw] = q1;
            }
        }
        BARG(barid);

        // ---- normalize + store ----
        #pragma unroll
        for (int m = 0; m < 2; m++) {
            #pragma unroll
            for (int half = 0; half < 2; half++) {
                int r = m * 16 + gid + half * 8;
                float4 Sa = *(float4*)&partS[r*8];
                float4 Sb = *(float4*)&partS[r*8 + 4];
                float4 Qa = *(float4*)&partQ[r*8];
                float4 Qb = *(float4*)&partQ[r*8 + 4];
                float sum = ((Sa.x + Sa.y) + (Sa.z + Sa.w))
                          + ((Sb.x + Sb.y) + (Sb.z + Sb.w));
                float sq  = ((Qa.x + Qa.y) + (Qa.z + Qa.w))
                          + ((Qb.x + Qb.y) + (Qb.z + Qb.w));
                float mu = sum * (1.0f/256.0f);
                float var = sq * (1.0f/256.0f) - mu * mu;
                float rs = rsqrtf(var + 1e-5f);
                int grow = rowBase + r;
                if (grow < nRows) {
                    float* op = out + (size_t)grow * 256;
                    #pragma unroll
                    for (int nb = 0; nb < 4; nb++) {
                        int col = nw * 32 + nb * 8 + tig * 2;
                        float va = acc[m][nb][half*2+0];
                        float vb = acc[m][nb][half*2+1];
                        float2 o2;
                        o2.x = fmaf((va - mu) * rs, gos[col],   bos[col]);
                        o2.y = fmaf((vb - mu) * rs, gos[col+1], bos[col+1]);
                        *(float2*)(op + col) = o2;
                    }
                }
            }
        }
        buf ^= 1;
    }
}

extern "C" void kernel_launch(void* const* d_in, const int* in_sizes, int n_in,
                              void* d_out, int out_size) {
    const float* x  = (const float*)d_in[0];
    const float* gm = (const float*)d_in[1];
    const float* bm = (const float*)d_in[2];
    const float* gs = (const float*)d_in[3];
    const float* bs = (const float*)d_in[4];
    const float* W1 = (const float*)d_in[5];
    const float* b1 = (const float*)d_in[6];
    const float* W2 = (const float*)d_in[7];
    const float* b2 = (const float*)d_in[8];
    const float* go = (const float*)d_in[9];
    const float* bo = (const float*)d_in[10];

    int B = in_sizes[0] / TLEN;
    int nRows = B * NP;

    cudaFuncSetAttribute(mlp_kernel, cudaFuncAttributeMaxDynamicSharedMemorySize,
                         SMEM_BYTES);

    feat_kernel<<<B, 256>>>(x, gm, bm, gs, bs);
    mlp_kernel<<<148, NTHREADS, SMEM_BYTES>>>(
        W1, b1, W2, b2, go, bo, (float*)d_out, nRows);
}